// round 2
// baseline (speedup 1.0000x reference)
#include <cuda_runtime.h>

#define NN 100000
#define NE 800000
#define NG 512
#define D  128
#define EPSV 1e-5f

// ---------------- scratch (static device globals; no allocations) ----------------
__device__ float  g_bufA[NN * D];
__device__ float  g_bufB[NN * D];
__device__ float  g_dinv[NN];
__device__ float  g_selfw[NN];
__device__ int    g_cnt[NN];
__device__ int    g_fill[NN];
__device__ int    g_off[NN + 1];
__device__ int    g_src[NE];
__device__ float  g_w[NE];
__device__ double g_sum[D];
__device__ double g_sq[D];
__device__ float  g_scale[D];
__device__ float  g_shift[D];
__device__ float  g_Z[NG * D];
__device__ int    g_start[NG];
__device__ int    g_end[NG];

__device__ __forceinline__ int clampN(int v) {
    return v < 0 ? 0 : (v >= NN ? NN - 1 : v);
}

// ---------------- graph preprocessing ----------------
__global__ void k_zero_cnt() {
    int i = blockIdx.x * blockDim.x + threadIdx.x;
    if (i < NN) g_cnt[i] = 0;
}

__global__ void k_count(const int* __restrict__ ei) {
    int e = blockIdx.x * blockDim.x + threadIdx.x;
    if (e < NE) atomicAdd(&g_cnt[clampN(ei[NE + e])], 1);
}

__global__ void k_node() {
    int i = blockIdx.x * blockDim.x + threadIdx.x;
    if (i < NN) {
        float deg = (float)g_cnt[i] + 1.0f;
        g_dinv[i]  = rsqrtf(deg);
        g_selfw[i] = 1.0f / deg;
        g_fill[i]  = 0;
    }
    if (i < NG) { g_start[i] = 0; g_end[i] = 0; }
}

__global__ void k_scan() {
    __shared__ int ss[1024];
    int tid = threadIdx.x;
    const int CH = (NN + 1023) / 1024;   // 98
    int b = tid * CH;
    int e = b + CH; if (e > NN) e = NN;
    if (b > NN) b = NN;
    int s = 0;
    for (int i = b; i < e; i++) s += g_cnt[i];
    ss[tid] = s;
    __syncthreads();
    // Hillis-Steele inclusive scan
    for (int d = 1; d < 1024; d <<= 1) {
        int v = (tid >= d) ? ss[tid - d] : 0;
        __syncthreads();
        ss[tid] += v;
        __syncthreads();
    }
    int pre = ss[tid] - s;   // exclusive prefix
    for (int i = b; i < e; i++) { g_off[i] = pre; pre += g_cnt[i]; }
    if (tid == 1023) g_off[NN] = pre;
}

__global__ void k_fill(const int* __restrict__ ei) {
    int e = blockIdx.x * blockDim.x + threadIdx.x;
    if (e >= NE) return;
    int s = clampN(ei[e]);
    int d = clampN(ei[NE + e]);
    int p = g_off[d] + atomicAdd(&g_fill[d], 1);
    g_src[p] = s;
    g_w[p]   = g_dinv[s] * g_dinv[d];
}

__global__ void k_bounds(const int* __restrict__ batch) {
    int i = blockIdx.x * blockDim.x + threadIdx.x;
    if (i >= NN) return;
    int b = batch[i];
    if (b < 0) b = 0; if (b >= NG) b = NG - 1;
    int bp = (i == 0) ? -1 : batch[i - 1];
    int bn = (i == NN - 1) ? -1 : batch[i + 1];
    if (i == 0      || bp != b) g_start[b] = i;
    if (i == NN - 1 || bn != b) g_end[b]   = i + 1;
}

// ---------------- GEMM: out[N,128] = in[N,128] @ W[128,128] ----------------
// 64-row tile per block, W fully staged in smem, 4x8 register blocking.
#define GEMM_SMEM ((D * D + 64 * 132) * 4)

__global__ __launch_bounds__(256) void k_gemm(const float* __restrict__ in,
                                              const float* __restrict__ W,
                                              float* __restrict__ out) {
    extern __shared__ float sm[];
    float* Ws = sm;             // 128*128
    float* As = sm + D * D;     // 64 rows, stride 132 (pad to dodge bank conflicts)
    int tid = threadIdx.x;

    // stage W (16384 floats = 4096 float4)
    const float4* W4 = (const float4*)W;
    float4* Ws4 = (float4*)Ws;
#pragma unroll
    for (int i = 0; i < 16; i++) Ws4[tid + i * 256] = W4[tid + i * 256];

    // stage A tile (64 x 128), 8 float4 per thread
    int row0 = blockIdx.x * 64;
    int q = tid & 31, rr = tid >> 5;
#pragma unroll
    for (int i = 0; i < 8; i++) {
        int r = rr + i * 8;
        int grow = row0 + r;
        float4 v = make_float4(0.f, 0.f, 0.f, 0.f);
        if (grow < NN) v = ((const float4*)in)[grow * 32 + q];
        *((float4*)&As[r * 132 + q * 4]) = v;
    }
    __syncthreads();

    int tx = tid & 15, ty = tid >> 4;   // tx: col group, ty: row group
    float acc[4][8];
#pragma unroll
    for (int i = 0; i < 4; i++)
#pragma unroll
        for (int j = 0; j < 8; j++) acc[i][j] = 0.f;

    const float4* Wsv = (const float4*)Ws;
#pragma unroll 4
    for (int k = 0; k < D; k++) {
        float a0 = As[(ty * 4 + 0) * 132 + k];
        float a1 = As[(ty * 4 + 1) * 132 + k];
        float a2 = As[(ty * 4 + 2) * 132 + k];
        float a3 = As[(ty * 4 + 3) * 132 + k];
        float4 w0 = Wsv[k * 32 + tx];        // cols tx*4..tx*4+3
        float4 w1 = Wsv[k * 32 + 16 + tx];   // cols 64+tx*4..64+tx*4+3
        acc[0][0] = fmaf(a0, w0.x, acc[0][0]); acc[0][1] = fmaf(a0, w0.y, acc[0][1]);
        acc[0][2] = fmaf(a0, w0.z, acc[0][2]); acc[0][3] = fmaf(a0, w0.w, acc[0][3]);
        acc[0][4] = fmaf(a0, w1.x, acc[0][4]); acc[0][5] = fmaf(a0, w1.y, acc[0][5]);
        acc[0][6] = fmaf(a0, w1.z, acc[0][6]); acc[0][7] = fmaf(a0, w1.w, acc[0][7]);
        acc[1][0] = fmaf(a1, w0.x, acc[1][0]); acc[1][1] = fmaf(a1, w0.y, acc[1][1]);
        acc[1][2] = fmaf(a1, w0.z, acc[1][2]); acc[1][3] = fmaf(a1, w0.w, acc[1][3]);
        acc[1][4] = fmaf(a1, w1.x, acc[1][4]); acc[1][5] = fmaf(a1, w1.y, acc[1][5]);
        acc[1][6] = fmaf(a1, w1.z, acc[1][6]); acc[1][7] = fmaf(a1, w1.w, acc[1][7]);
        acc[2][0] = fmaf(a2, w0.x, acc[2][0]); acc[2][1] = fmaf(a2, w0.y, acc[2][1]);
        acc[2][2] = fmaf(a2, w0.z, acc[2][2]); acc[2][3] = fmaf(a2, w0.w, acc[2][3]);
        acc[2][4] = fmaf(a2, w1.x, acc[2][4]); acc[2][5] = fmaf(a2, w1.y, acc[2][5]);
        acc[2][6] = fmaf(a2, w1.z, acc[2][6]); acc[2][7] = fmaf(a2, w1.w, acc[2][7]);
        acc[3][0] = fmaf(a3, w0.x, acc[3][0]); acc[3][1] = fmaf(a3, w0.y, acc[3][1]);
        acc[3][2] = fmaf(a3, w0.z, acc[3][2]); acc[3][3] = fmaf(a3, w0.w, acc[3][3]);
        acc[3][4] = fmaf(a3, w1.x, acc[3][4]); acc[3][5] = fmaf(a3, w1.y, acc[3][5]);
        acc[3][6] = fmaf(a3, w1.z, acc[3][6]); acc[3][7] = fmaf(a3, w1.w, acc[3][7]);
    }

#pragma unroll
    for (int i = 0; i < 4; i++) {
        int grow = row0 + ty * 4 + i;
        if (grow < NN) {
            ((float4*)out)[grow * 32 + tx]      = make_float4(acc[i][0], acc[i][1], acc[i][2], acc[i][3]);
            ((float4*)out)[grow * 32 + 16 + tx] = make_float4(acc[i][4], acc[i][5], acc[i][6], acc[i][7]);
        }
    }
}

// ---------------- aggregation (gather, CSR) + bias + fused BN stats ----------------
__global__ __launch_bounds__(256) void k_agg(const float* __restrict__ tmp,
                                             float* __restrict__ outh,
                                             const float* __restrict__ bias) {
    __shared__ float bsum[D];
    __shared__ float bsq[D];
    int tid = threadIdx.x;
    if (tid < D) { bsum[tid] = 0.f; bsq[tid] = 0.f; }
    __syncthreads();

    int lane = tid & 31, wid = tid >> 5;
    const float4* t4 = (const float4*)tmp;
    float4 b4 = ((const float4*)bias)[lane];
    float ls0 = 0, ls1 = 0, ls2 = 0, ls3 = 0;
    float lq0 = 0, lq1 = 0, lq2 = 0, lq3 = 0;

    for (int row = blockIdx.x * 8 + wid; row < NN; row += gridDim.x * 8) {
        float4 acc = make_float4(0.f, 0.f, 0.f, 0.f);
        int e0 = g_off[row], e1 = g_off[row + 1];
        for (int e = e0; e < e1; e++) {
            int s  = __ldg(&g_src[e]);
            float w = __ldg(&g_w[e]);
            float4 v = t4[s * 32 + lane];
            acc.x = fmaf(w, v.x, acc.x);
            acc.y = fmaf(w, v.y, acc.y);
            acc.z = fmaf(w, v.z, acc.z);
            acc.w = fmaf(w, v.w, acc.w);
        }
        float sw = g_selfw[row];
        float4 v = t4[row * 32 + lane];
        acc.x = fmaf(sw, v.x, acc.x) + b4.x;
        acc.y = fmaf(sw, v.y, acc.y) + b4.y;
        acc.z = fmaf(sw, v.z, acc.z) + b4.z;
        acc.w = fmaf(sw, v.w, acc.w) + b4.w;
        ((float4*)outh)[row * 32 + lane] = acc;
        ls0 += acc.x; ls1 += acc.y; ls2 += acc.z; ls3 += acc.w;
        lq0 += acc.x * acc.x; lq1 += acc.y * acc.y;
        lq2 += acc.z * acc.z; lq3 += acc.w * acc.w;
    }

    atomicAdd(&bsum[lane * 4 + 0], ls0); atomicAdd(&bsum[lane * 4 + 1], ls1);
    atomicAdd(&bsum[lane * 4 + 2], ls2); atomicAdd(&bsum[lane * 4 + 3], ls3);
    atomicAdd(&bsq[lane * 4 + 0], lq0);  atomicAdd(&bsq[lane * 4 + 1], lq1);
    atomicAdd(&bsq[lane * 4 + 2], lq2);  atomicAdd(&bsq[lane * 4 + 3], lq3);
    __syncthreads();
    if (tid < D) {
        atomicAdd(&g_sum[tid], (double)bsum[tid]);
        atomicAdd(&g_sq[tid],  (double)bsq[tid]);
    }
}

__global__ void k_zstats() {
    int i = threadIdx.x;
    if (i < D) { g_sum[i] = 0.0; g_sq[i] = 0.0; }
}

__global__ void k_stats(const float* __restrict__ gamma, const float* __restrict__ beta) {
    int f = threadIdx.x;
    if (f >= D) return;
    float mu  = (float)(g_sum[f] / (double)NN);
    float var = (float)(g_sq[f] / (double)NN) - mu * mu;
    float rstd = rsqrtf(var + EPSV);
    float sc = rstd * gamma[f];
    g_scale[f] = sc;
    g_shift[f] = beta[f] - mu * sc;
}

__global__ void k_bn(float* __restrict__ h) {
    int i = blockIdx.x * blockDim.x + threadIdx.x;  // float4 index
    if (i >= NN * 32) return;
    int f4 = i & 31;
    float4 v  = ((float4*)h)[i];
    float4 s  = ((const float4*)g_scale)[f4];
    float4 sh = ((const float4*)g_shift)[f4];
    v.x = fmaxf(fmaf(v.x, s.x, sh.x), 0.f);
    v.y = fmaxf(fmaf(v.y, s.y, sh.y), 0.f);
    v.z = fmaxf(fmaf(v.z, s.z, sh.z), 0.f);
    v.w = fmaxf(fmaf(v.w, s.w, sh.w), 0.f);
    ((float4*)h)[i] = v;
}

// ---------------- pooling + MLP head ----------------
__global__ void k_pool(const float* __restrict__ h) {
    int g = blockIdx.x, f = threadIdx.x;
    int a = g_start[g], b = g_end[g];
    float s = 0.f;
    for (int i = a; i < b; i++) s += h[i * D + f];
    int c = b - a;
    g_Z[g * D + f] = s / (float)(c > 0 ? c : 1);
}

__global__ void k_head(const float* __restrict__ W1, const float* __restrict__ b1,
                       const float* __restrict__ W2, const float* __restrict__ b2,
                       float* __restrict__ out) {
    __shared__ float zs[D];
    __shared__ float red[4];
    int g = blockIdx.x, j = threadIdx.x;
    zs[j] = g_Z[g * D + j];
    __syncthreads();
    float acc = b1[j];
#pragma unroll 8
    for (int k = 0; k < D; k++) acc = fmaf(zs[k], W1[k * D + j], acc);
    float hz = fmaxf(acc, 0.f);
    float p = hz * W2[j];
#pragma unroll
    for (int o = 16; o; o >>= 1) p += __shfl_down_sync(0xffffffffu, p, o);
    if ((j & 31) == 0) red[j >> 5] = p;
    __syncthreads();
    if (j == 0) out[g] = red[0] + red[1] + red[2] + red[3] + b2[0];
}

// ---------------- launch ----------------
extern "C" void kernel_launch(void* const* d_in, const int* in_sizes, int n_in,
                              void* d_out, int out_size) {
    const float* x      = (const float*)d_in[0];
    const int*   ei     = (const int*)d_in[1];
    const int*   batch  = (const int*)d_in[2];
    const float* Ws     = (const float*)d_in[3];
    const float* bs     = (const float*)d_in[4];
    const float* gammas = (const float*)d_in[5];
    const float* betas  = (const float*)d_in[6];
    const float* W1     = (const float*)d_in[7];
    const float* b1     = (const float*)d_in[8];
    const float* W2     = (const float*)d_in[9];
    const float* b2     = (const float*)d_in[10];
    float* out = (float*)d_out;

    float *A, *B;
    cudaGetSymbolAddress((void**)&A, g_bufA);
    cudaGetSymbolAddress((void**)&B, g_bufB);
    cudaFuncSetAttribute(k_gemm, cudaFuncAttributeMaxDynamicSharedMemorySize, GEMM_SMEM);

    const int NB_N = (NN + 255) / 256;   // 391
    const int NB_E = (NE + 255) / 256;   // 3125

    k_zero_cnt<<<NB_N, 256>>>();
    k_count<<<NB_E, 256>>>(ei);
    k_node<<<NB_N, 256>>>();
    k_scan<<<1, 1024>>>();
    k_fill<<<NB_E, 256>>>(ei);
    k_bounds<<<NB_N, 256>>>(batch);

    const float* hin = x;
    for (int l = 0; l < 3; l++) {
        k_zstats<<<1, 128>>>();
        k_gemm<<<(NN + 63) / 64, 256, GEMM_SMEM>>>(hin, Ws + l * D * D, B);
        k_agg<<<1024, 256>>>(B, A, bs + l * D);
        k_stats<<<1, 128>>>(gammas + l * D, betas + l * D);
        k_bn<<<(NN * 32 + 255) / 256, 256>>>(A);
        hin = A;
    }

    k_pool<<<NG, 128>>>(A);
    k_head<<<NG, 128>>>(W1, b1, W2, b2, out);
}

// round 4
// speedup vs baseline: 1.2948x; 1.2948x over previous
#include <cuda_runtime.h>
#include <cuda_bf16.h>
#include <cstdint>

#define NN 100000
#define NE 800000
#define NG 512
#define D  128
#define EPSV 1e-5f
#define NTILE 782            // ceil(NN/128)
#define SCAN_B 391           // ceil(NN/256)

// ---------------- scratch (static device globals; no allocations) ----------------
__device__ float  g_bufA[NN * D];
__device__ float  g_bufB[NN * D];
__device__ float  g_dinv[NN];
__device__ float  g_selfw[NN];
__device__ int    g_cnt[NN];
__device__ int    g_fill[NN];
__device__ int    g_off[NN + 1];
__device__ int    g_src[NE];
__device__ float  g_w[NE];
__device__ int    g_part[SCAN_B];
__device__ int    g_pbase[SCAN_B];
__device__ double g_sum[D];
__device__ double g_sq[D];
__device__ float  g_scale[D];
__device__ float  g_shift[D];
__device__ float  g_Z[NG * D];
__device__ int    g_start[NG];
__device__ int    g_end[NG];
__device__ __nv_bfloat16 g_Whi[3 * D * D];   // W^T per layer, [n][k]
__device__ __nv_bfloat16 g_Wlo[3 * D * D];

__device__ __forceinline__ int clampN(int v) {
    return v < 0 ? 0 : (v >= NN ? NN - 1 : v);
}

__device__ __forceinline__ uint32_t smem_u32(const void* p) {
    uint32_t a;
    asm("{ .reg .u64 t; cvta.to.shared.u64 t, %1; cvt.u32.u64 %0, t; }" : "=r"(a) : "l"(p));
    return a;
}

// XOR swizzle for 256B rows: shift 16B-chunk index (bits[6:4]) by row&7 (bits[10:8])
__device__ __forceinline__ uint32_t sw(uint32_t off) {
    return off ^ ((off >> 4) & 0x70);
}

__device__ __forceinline__ void ldm_x4(uint32_t* r, uint32_t addr) {
    asm volatile("ldmatrix.sync.aligned.m8n8.x4.shared.b16 {%0,%1,%2,%3}, [%4];"
                 : "=r"(r[0]), "=r"(r[1]), "=r"(r[2]), "=r"(r[3]) : "r"(addr));
}

__device__ __forceinline__ void mma_bf16(float* c, const uint32_t* a, uint32_t b0, uint32_t b1) {
    asm volatile(
        "mma.sync.aligned.m16n8k16.row.col.f32.bf16.bf16.f32 "
        "{%0,%1,%2,%3}, {%4,%5,%6,%7}, {%8,%9}, {%0,%1,%2,%3};"
        : "+f"(c[0]), "+f"(c[1]), "+f"(c[2]), "+f"(c[3])
        : "r"(a[0]), "r"(a[1]), "r"(a[2]), "r"(a[3]), "r"(b0), "r"(b1));
}

// ---------------- graph preprocessing ----------------
__global__ void k_zero_cnt() {
    int i = blockIdx.x * blockDim.x + threadIdx.x;
    if (i < NN) g_cnt[i] = 0;
}

__global__ void k_count(const int* __restrict__ ei) {
    int e = blockIdx.x * blockDim.x + threadIdx.x;
    if (e < NE) atomicAdd(&g_cnt[clampN(ei[NE + e])], 1);
}

__global__ void k_node() {
    int i = blockIdx.x * blockDim.x + threadIdx.x;
    if (i < NN) {
        float deg = (float)g_cnt[i] + 1.0f;
        g_dinv[i]  = rsqrtf(deg);
        g_selfw[i] = 1.0f / deg;
        g_fill[i]  = 0;
    }
    if (i < NG) { g_start[i] = 0; g_end[i] = 0; }
}

__global__ void k_part() {
    __shared__ int s[256];
    int t = threadIdx.x;
    int i = blockIdx.x * 256 + t;
    int v = (i < NN) ? g_cnt[i] : 0;
    s[t] = v; __syncthreads();
    for (int o = 128; o; o >>= 1) { if (t < o) s[t] += s[t + o]; __syncthreads(); }
    if (t == 0) g_part[blockIdx.x] = s[0];
}

__global__ void k_scanpart() {
    __shared__ int s[512];
    int t = threadIdx.x;
    int v = (t < SCAN_B) ? g_part[t] : 0;
    s[t] = v; __syncthreads();
    for (int d = 1; d < 512; d <<= 1) {
        int x = (t >= d) ? s[t - d] : 0;
        __syncthreads();
        s[t] += x;
        __syncthreads();
    }
    if (t < SCAN_B) g_pbase[t] = s[t] - v;
    if (t == SCAN_B - 1) g_off[NN] = s[t];
}

__global__ void k_offsets() {
    __shared__ int s[256];
    int t = threadIdx.x;
    int i = blockIdx.x * 256 + t;
    int v = (i < NN) ? g_cnt[i] : 0;
    s[t] = v; __syncthreads();
    for (int d = 1; d < 256; d <<= 1) {
        int x = (t >= d) ? s[t - d] : 0;
        __syncthreads();
        s[t] += x;
        __syncthreads();
    }
    if (i < NN) g_off[i] = g_pbase[blockIdx.x] + s[t] - v;
}

__global__ void k_fill(const int* __restrict__ ei) {
    int e = blockIdx.x * blockDim.x + threadIdx.x;
    if (e >= NE) return;
    int s = clampN(ei[e]);
    int d = clampN(ei[NE + e]);
    int p = g_off[d] + atomicAdd(&g_fill[d], 1);
    g_src[p] = s;
    g_w[p]   = g_dinv[s] * g_dinv[d];
}

__global__ void k_bounds(const int* __restrict__ batch) {
    int i = blockIdx.x * blockDim.x + threadIdx.x;
    if (i >= NN) return;
    int b = batch[i];
    if (b < 0) b = 0; if (b >= NG) b = NG - 1;
    int bp = (i == 0) ? -1 : batch[i - 1];
    int bn = (i == NN - 1) ? -1 : batch[i + 1];
    if (i == 0      || bp != b) g_start[b] = i;
    if (i == NN - 1 || bn != b) g_end[b]   = i + 1;
}

// W^T + hi/lo bf16 decomposition: g_W*[l][n][k] = split(W[l][k][n])
__global__ void k_prepw(const float* __restrict__ Ws) {
    int idx = blockIdx.x * 128 + threadIdx.x;       // 3*128*128 total
    int l = idx >> 14, rem = idx & 16383;
    int n = rem >> 7, k = rem & 127;
    float w = Ws[l * 16384 + k * 128 + n];
    __nv_bfloat16 hi = __float2bfloat16_rn(w);
    __nv_bfloat16 lo = __float2bfloat16_rn(w - __bfloat162float(hi));
    g_Whi[idx] = hi;
    g_Wlo[idx] = lo;
}

// ---------------- HMMA GEMM: out[N,128] = bnrelu(in)[N,128] @ W ----------------
// smem: AH[128x128 bf16] AL WH WL, each 32KB, 256B rows, XOR swizzled
#define S_AH 0
#define S_AL 32768
#define S_WH 65536
#define S_WL 98304
#define MMASMEM 131072

__global__ __launch_bounds__(256) void k_gemm_mma(const float* __restrict__ in,
                                                  const __nv_bfloat16* __restrict__ Whi,
                                                  const __nv_bfloat16* __restrict__ Wlo,
                                                  float* __restrict__ out,
                                                  int apply) {
    extern __shared__ char smraw[];
    char* smc = smraw;
    uint32_t sb = smem_u32(smc);
    int tid = threadIdx.x, wid = tid >> 5, lane = tid & 31;
    int row0 = blockIdx.x * 128;

    // ---- stage W^T hi/lo: thread t -> row n=t/2, half=t&1, 8 x 16B chunks
    {
        int n = tid >> 1, half = tid & 1;
        const uint4* src_h = (const uint4*)(Whi) + n * 16 + half * 8;
        const uint4* src_l = (const uint4*)(Wlo) + n * 16 + half * 8;
        uint32_t base = n * 256 + half * 128;
#pragma unroll
        for (int c = 0; c < 8; c++) {
            uint32_t o = sw(base + c * 16);
            *(uint4*)(smc + S_WH + o) = __ldg(&src_h[c]);
            *(uint4*)(smc + S_WL + o) = __ldg(&src_l[c]);
        }
    }
    // ---- stage A hi/lo with fused BN+ReLU
    {
        int r = tid >> 1, half = tid & 1;
        int grow = row0 + r;
        bool ok = grow < NN;
        const float4* src = (const float4*)(in + (size_t)grow * D) + half * 16;
        uint32_t base = r * 256 + half * 128;
#pragma unroll
        for (int c = 0; c < 8; c++) {
            float4 v0 = make_float4(0.f, 0.f, 0.f, 0.f), v1 = v0;
            if (ok) {
                v0 = __ldg(&src[c * 2]);
                v1 = __ldg(&src[c * 2 + 1]);
                if (apply) {
                    int cb = half * 16 + c * 2;
                    float4 s0 = ((const float4*)g_scale)[cb],   sh0 = ((const float4*)g_shift)[cb];
                    float4 s1 = ((const float4*)g_scale)[cb+1], sh1 = ((const float4*)g_shift)[cb+1];
                    v0.x = fmaxf(fmaf(v0.x, s0.x, sh0.x), 0.f);
                    v0.y = fmaxf(fmaf(v0.y, s0.y, sh0.y), 0.f);
                    v0.z = fmaxf(fmaf(v0.z, s0.z, sh0.z), 0.f);
                    v0.w = fmaxf(fmaf(v0.w, s0.w, sh0.w), 0.f);
                    v1.x = fmaxf(fmaf(v1.x, s1.x, sh1.x), 0.f);
                    v1.y = fmaxf(fmaf(v1.y, s1.y, sh1.y), 0.f);
                    v1.z = fmaxf(fmaf(v1.z, s1.z, sh1.z), 0.f);
                    v1.w = fmaxf(fmaf(v1.w, s1.w, sh1.w), 0.f);
                }
            }
            __nv_bfloat162 h0 = __float22bfloat162_rn(make_float2(v0.x, v0.y));
            __nv_bfloat162 h1 = __float22bfloat162_rn(make_float2(v0.z, v0.w));
            __nv_bfloat162 h2 = __float22bfloat162_rn(make_float2(v1.x, v1.y));
            __nv_bfloat162 h3 = __float22bfloat162_rn(make_float2(v1.z, v1.w));
            __nv_bfloat162 l0 = __float22bfloat162_rn(make_float2(v0.x - __bfloat162float(h0.x), v0.y - __bfloat162float(h0.y)));
            __nv_bfloat162 l1 = __float22bfloat162_rn(make_float2(v0.z - __bfloat162float(h1.x), v0.w - __bfloat162float(h1.y)));
            __nv_bfloat162 l2 = __float22bfloat162_rn(make_float2(v1.x - __bfloat162float(h2.x), v1.y - __bfloat162float(h2.y)));
            __nv_bfloat162 l3 = __float22bfloat162_rn(make_float2(v1.z - __bfloat162float(h3.x), v1.w - __bfloat162float(h3.y)));
            uint4 ph, pl;
            ph.x = *(uint32_t*)&h0; ph.y = *(uint32_t*)&h1; ph.z = *(uint32_t*)&h2; ph.w = *(uint32_t*)&h3;
            pl.x = *(uint32_t*)&l0; pl.y = *(uint32_t*)&l1; pl.z = *(uint32_t*)&l2; pl.w = *(uint32_t*)&l3;
            uint32_t o = sw(base + c * 16);
            *(uint4*)(smc + S_AH + o) = ph;
            *(uint4*)(smc + S_AL + o) = pl;
        }
    }
    __syncthreads();

    // ---- load A fragments for this warp (rows wid*16..+15), all 8 k-chunks
    uint32_t afh[8][4], afl[8][4];
    uint32_t a_base = (wid * 16 + (lane & 15)) * 256 + ((lane >> 4) * 8) * 2;
#pragma unroll
    for (int k = 0; k < 8; k++) {
        uint32_t o = sw(a_base + k * 32);
        ldm_x4(afh[k], sb + S_AH + o);
        ldm_x4(afl[k], sb + S_AL + o);
    }

    // ---- main loop over 8 n-pairs (16 cols each)
    uint32_t b_base = ((lane & 7) + ((lane >> 4) << 3)) * 256 + (((lane >> 3) & 1) * 8) * 2;
    int row_t = lane >> 2, col_t = (lane & 3) * 2;
    int grow0 = row0 + wid * 16 + row_t;
    int grow1 = grow0 + 8;

#pragma unroll 2
    for (int np = 0; np < 8; np++) {
        float ce[4] = {0.f, 0.f, 0.f, 0.f};
        float co[4] = {0.f, 0.f, 0.f, 0.f};
#pragma unroll
        for (int k = 0; k < 8; k++) {
            uint32_t bh[4], bl[4];
            uint32_t o = sw(b_base + np * 4096 + k * 32);
            ldm_x4(bh, sb + S_WH + o);
            ldm_x4(bl, sb + S_WL + o);
            mma_bf16(ce, afh[k], bh[0], bh[1]);
            mma_bf16(co, afh[k], bh[2], bh[3]);
            mma_bf16(ce, afh[k], bl[0], bl[1]);
            mma_bf16(co, afh[k], bl[2], bl[3]);
            mma_bf16(ce, afl[k], bh[0], bh[1]);
            mma_bf16(co, afl[k], bh[2], bh[3]);
        }
        int nb = np * 16;
        if (grow0 < NN) {
            *(float2*)(out + (size_t)grow0 * D + nb + col_t)     = make_float2(ce[0], ce[1]);
            *(float2*)(out + (size_t)grow0 * D + nb + 8 + col_t) = make_float2(co[0], co[1]);
        }
        if (grow1 < NN) {
            *(float2*)(out + (size_t)grow1 * D + nb + col_t)     = make_float2(ce[2], ce[3]);
            *(float2*)(out + (size_t)grow1 * D + nb + 8 + col_t) = make_float2(co[2], co[3]);
        }
    }
}

// ---------------- aggregation (gather, CSR) + bias + fused BN stats ----------------
__global__ __launch_bounds__(256) void k_agg(const float* __restrict__ tmp,
                                             float* __restrict__ outh,
                                             const float* __restrict__ bias) {
    __shared__ float bsum[D];
    __shared__ float bsq[D];
    int tid = threadIdx.x;
    if (tid < D) { bsum[tid] = 0.f; bsq[tid] = 0.f; }
    __syncthreads();

    int lane = tid & 31, wid = tid >> 5;
    const float4* t4 = (const float4*)tmp;
    float4 b4 = ((const float4*)bias)[lane];
    float ls0 = 0, ls1 = 0, ls2 = 0, ls3 = 0;
    float lq0 = 0, lq1 = 0, lq2 = 0, lq3 = 0;

    for (int row = blockIdx.x * 8 + wid; row < NN; row += gridDim.x * 8) {
        float4 acc = make_float4(0.f, 0.f, 0.f, 0.f);
        int e0 = g_off[row], e1 = g_off[row + 1];
        int e = e0;
        for (; e + 4 <= e1; e += 4) {
            int s0 = __ldg(&g_src[e]);
            int s1 = __ldg(&g_src[e + 1]);
            int s2 = __ldg(&g_src[e + 2]);
            int s3 = __ldg(&g_src[e + 3]);
            float w0 = __ldg(&g_w[e]);
            float w1 = __ldg(&g_w[e + 1]);
            float w2 = __ldg(&g_w[e + 2]);
            float w3 = __ldg(&g_w[e + 3]);
            float4 v0 = t4[s0 * 32 + lane];
            float4 v1 = t4[s1 * 32 + lane];
            float4 v2 = t4[s2 * 32 + lane];
            float4 v3 = t4[s3 * 32 + lane];
            acc.x = fmaf(w0, v0.x, acc.x); acc.y = fmaf(w0, v0.y, acc.y);
            acc.z = fmaf(w0, v0.z, acc.z); acc.w = fmaf(w0, v0.w, acc.w);
            acc.x = fmaf(w1, v1.x, acc.x); acc.y = fmaf(w1, v1.y, acc.y);
            acc.z = fmaf(w1, v1.z, acc.z); acc.w = fmaf(w1, v1.w, acc.w);
            acc.x = fmaf(w2, v2.x, acc.x); acc.y = fmaf(w2, v2.y, acc.y);
            acc.z = fmaf(w2, v2.z, acc.z); acc.w = fmaf(w2, v2.w, acc.w);
            acc.x = fmaf(w3, v3.x, acc.x); acc.y = fmaf(w3, v3.y, acc.y);
            acc.z = fmaf(w3, v3.z, acc.z); acc.w = fmaf(w3, v3.w, acc.w);
        }
        for (; e < e1; e++) {
            int s  = __ldg(&g_src[e]);
            float w = __ldg(&g_w[e]);
            float4 v = t4[s * 32 + lane];
            acc.x = fmaf(w, v.x, acc.x);
            acc.y = fmaf(w, v.y, acc.y);
            acc.z = fmaf(w, v.z, acc.z);
            acc.w = fmaf(w, v.w, acc.w);
        }
        float sw_ = g_selfw[row];
        float4 v = t4[row * 32 + lane];
        acc.x = fmaf(sw_, v.x, acc.x) + b4.x;
        acc.y = fmaf(sw_, v.y, acc.y) + b4.y;
        acc.z = fmaf(sw_, v.z, acc.z) + b4.z;
        acc.w = fmaf(sw_, v.w, acc.w) + b4.w;
        ((float4*)outh)[row * 32 + lane] = acc;
        ls0 += acc.x; ls1 += acc.y; ls2 += acc.z; ls3 += acc.w;
        lq0 += acc.x * acc.x; lq1 += acc.y * acc.y;
        lq2 += acc.z * acc.z; lq3 += acc.w * acc.w;
    }

    atomicAdd(&bsum[lane * 4 + 0], ls0); atomicAdd(&bsum[lane * 4 + 1], ls1);
    atomicAdd(&bsum[lane * 4 + 2], ls2); atomicAdd(&bsum[lane * 4 + 3], ls3);
    atomicAdd(&bsq[lane * 4 + 0], lq0);  atomicAdd(&bsq[lane * 4 + 1], lq1);
    atomicAdd(&bsq[lane * 4 + 2], lq2);  atomicAdd(&bsq[lane * 4 + 3], lq3);
    __syncthreads();
    if (tid < D) {
        atomicAdd(&g_sum[tid], (double)bsum[tid]);
        atomicAdd(&g_sq[tid],  (double)bsq[tid]);
    }
}

__global__ void k_zstats() {
    int i = threadIdx.x;
    if (i < D) { g_sum[i] = 0.0; g_sq[i] = 0.0; }
}

__global__ void k_stats(const float* __restrict__ gamma, const float* __restrict__ beta) {
    int f = threadIdx.x;
    if (f >= D) return;
    float mu  = (float)(g_sum[f] / (double)NN);
    float var = (float)(g_sq[f] / (double)NN) - mu * mu;
    float rstd = rsqrtf(var + EPSV);
    float sc = rstd * gamma[f];
    g_scale[f] = sc;
    g_shift[f] = beta[f] - mu * sc;
}

// ---------------- pooling (fused BN+ReLU of last layer) + MLP head ----------------
__global__ void k_pool(const float* __restrict__ h) {
    int g = blockIdx.x, f = threadIdx.x;
    int a = g_start[g], b = g_end[g];
    float sc = g_scale[f], sh = g_shift[f];
    float s = 0.f;
    for (int i = a; i < b; i++) s += fmaxf(fmaf(h[i * D + f], sc, sh), 0.f);
    int c = b - a;
    g_Z[g * D + f] = s / (float)(c > 0 ? c : 1);
}

__global__ void k_head(const float* __restrict__ W1, const float* __restrict__ b1,
                       const float* __restrict__ W2, const float* __restrict__ b2,
                       float* __restrict__ out) {
    __shared__ float zs[D];
    __shared__ float red[4];
    int g = blockIdx.x, j = threadIdx.x;
    zs[j] = g_Z[g * D + j];
    __syncthreads();
    float acc = b1[j];
#pragma unroll 8
    for (int k = 0; k < D; k++) acc = fmaf(zs[k], W1[k * D + j], acc);
    float hz = fmaxf(acc, 0.f);
    float p = hz * W2[j];
#pragma unroll
    for (int o = 16; o; o >>= 1) p += __shfl_down_sync(0xffffffffu, p, o);
    if ((j & 31) == 0) red[j >> 5] = p;
    __syncthreads();
    if (j == 0) out[g] = red[0] + red[1] + red[2] + red[3] + b2[0];
}

// ---------------- launch ----------------
extern "C" void kernel_launch(void* const* d_in, const int* in_sizes, int n_in,
                              void* d_out, int out_size) {
    const float* x      = (const float*)d_in[0];
    const int*   ei     = (const int*)d_in[1];
    const int*   batch  = (const int*)d_in[2];
    const float* Ws     = (const float*)d_in[3];
    const float* bs     = (const float*)d_in[4];
    const float* gammas = (const float*)d_in[5];
    const float* betas  = (const float*)d_in[6];
    const float* W1     = (const float*)d_in[7];
    const float* b1     = (const float*)d_in[8];
    const float* W2     = (const float*)d_in[9];
    const float* b2     = (const float*)d_in[10];
    float* out = (float*)d_out;

    float *A, *B;
    __nv_bfloat16 *whi, *wlo;
    cudaGetSymbolAddress((void**)&A, g_bufA);
    cudaGetSymbolAddress((void**)&B, g_bufB);
    cudaGetSymbolAddress((void**)&whi, g_Whi);
    cudaGetSymbolAddress((void**)&wlo, g_Wlo);
    cudaFuncSetAttribute(k_gemm_mma, cudaFuncAttributeMaxDynamicSharedMemorySize, MMASMEM);

    const int NB_N = (NN + 255) / 256;   // 391
    const int NB_E = (NE + 255) / 256;   // 3125

    k_zero_cnt<<<NB_N, 256>>>();
    k_count<<<NB_E, 256>>>(ei);
    k_node<<<NB_N, 256>>>();
    k_part<<<SCAN_B, 256>>>();
    k_scanpart<<<1, 512>>>();
    k_offsets<<<SCAN_B, 256>>>();
    k_fill<<<NB_E, 256>>>(ei);
    k_bounds<<<NB_N, 256>>>(batch);
    k_prepw<<<3 * D * D / 128, 128>>>(Ws);

    const float* hin = x;
    for (int l = 0; l < 3; l++) {
        k_zstats<<<1, 128>>>();
        k_gemm_mma<<<NTILE, 256, MMASMEM>>>(hin, whi + l * D * D, wlo + l * D * D, B, l > 0);
        k_agg<<<1024, 256>>>(B, A, bs + l * D);
        k_stats<<<1, 128>>>(gammas + l * D, betas + l * D);
        hin = A;
    }

    k_pool<<<NG, 128>>>(A);
    k_head<<<NG, 128>>>(W1, b1, W2, b2, out);
}

// round 5
// speedup vs baseline: 1.3150x; 1.0156x over previous
#include <cuda_runtime.h>
#include <cuda_bf16.h>
#include <cstdint>

#define NN 100000
#define NE 800000
#define NG 512
#define D  128
#define EPSV 1e-5f
#define NTILE 782            // ceil(NN/128)
#define SCAN_B 391           // ceil(NN/256)

// ---------------- scratch (static device globals; no allocations) ----------------
__device__ float  g_bufA[NN * D];
__device__ float  g_bufB[NN * D];
__device__ float  g_dinv[NN];
__device__ float  g_selfw[NN];
__device__ int    g_cnt[NN];
__device__ int    g_fill[NN];
__device__ int    g_off[NN + 1];
__device__ int2   g_edge[NE];        // (src, __float_as_int(w))
__device__ int    g_part[SCAN_B];
__device__ int    g_pbase[SCAN_B];
__device__ double g_sum[D];
__device__ double g_sq[D];
__device__ float  g_scale[D];
__device__ float  g_shift[D];
__device__ float  g_Z[NG * D];
__device__ int    g_start[NG];
__device__ int    g_end[NG];
__device__ __nv_bfloat16 g_Whi[3 * D * D];   // W^T per layer, [n][k]
__device__ __nv_bfloat16 g_Wlo[3 * D * D];

__device__ __forceinline__ int clampN(int v) {
    return v < 0 ? 0 : (v >= NN ? NN - 1 : v);
}

__device__ __forceinline__ uint32_t smem_u32(const void* p) {
    uint32_t a;
    asm("{ .reg .u64 t; cvta.to.shared.u64 t, %1; cvt.u32.u64 %0, t; }" : "=r"(a) : "l"(p));
    return a;
}

// XOR swizzle for 256B rows
__device__ __forceinline__ uint32_t sw(uint32_t off) {
    return off ^ ((off >> 4) & 0x70);
}

__device__ __forceinline__ void ldm_x4(uint32_t* r, uint32_t addr) {
    asm volatile("ldmatrix.sync.aligned.m8n8.x4.shared.b16 {%0,%1,%2,%3}, [%4];"
                 : "=r"(r[0]), "=r"(r[1]), "=r"(r[2]), "=r"(r[3]) : "r"(addr));
}

__device__ __forceinline__ void mma_bf16(float* c, const uint32_t* a, uint32_t b0, uint32_t b1) {
    asm volatile(
        "mma.sync.aligned.m16n8k16.row.col.f32.bf16.bf16.f32 "
        "{%0,%1,%2,%3}, {%4,%5,%6,%7}, {%8,%9}, {%0,%1,%2,%3};"
        : "+f"(c[0]), "+f"(c[1]), "+f"(c[2]), "+f"(c[3])
        : "r"(a[0]), "r"(a[1]), "r"(a[2]), "r"(a[3]), "r"(b0), "r"(b1));
}

// ---------------- graph preprocessing ----------------
__global__ void k_zero_cnt() {
    int i = blockIdx.x * blockDim.x + threadIdx.x;
    if (i < NN) g_cnt[i] = 0;
}

__global__ void k_count(const int* __restrict__ ei) {
    int e = blockIdx.x * blockDim.x + threadIdx.x;
    if (e < NE) atomicAdd(&g_cnt[clampN(ei[NE + e])], 1);
}

__global__ void k_node() {
    int i = blockIdx.x * blockDim.x + threadIdx.x;
    if (i < NN) {
        float deg = (float)g_cnt[i] + 1.0f;
        g_dinv[i]  = rsqrtf(deg);
        g_selfw[i] = 1.0f / deg;
        g_fill[i]  = 0;
    }
    if (i < NG) { g_start[i] = 0; g_end[i] = 0; }
    if (i < D)  { g_sum[i] = 0.0; g_sq[i] = 0.0; }
}

__global__ void k_part() {
    __shared__ int s[256];
    int t = threadIdx.x;
    int i = blockIdx.x * 256 + t;
    int v = (i < NN) ? g_cnt[i] : 0;
    s[t] = v; __syncthreads();
    for (int o = 128; o; o >>= 1) { if (t < o) s[t] += s[t + o]; __syncthreads(); }
    if (t == 0) g_part[blockIdx.x] = s[0];
}

__global__ void k_scanpart() {
    __shared__ int s[512];
    int t = threadIdx.x;
    int v = (t < SCAN_B) ? g_part[t] : 0;
    s[t] = v; __syncthreads();
    for (int d = 1; d < 512; d <<= 1) {
        int x = (t >= d) ? s[t - d] : 0;
        __syncthreads();
        s[t] += x;
        __syncthreads();
    }
    if (t < SCAN_B) g_pbase[t] = s[t] - v;
    if (t == SCAN_B - 1) g_off[NN] = s[t];
}

__global__ void k_offsets() {
    __shared__ int s[256];
    int t = threadIdx.x;
    int i = blockIdx.x * 256 + t;
    int v = (i < NN) ? g_cnt[i] : 0;
    s[t] = v; __syncthreads();
    for (int d = 1; d < 256; d <<= 1) {
        int x = (t >= d) ? s[t - d] : 0;
        __syncthreads();
        s[t] += x;
        __syncthreads();
    }
    if (i < NN) g_off[i] = g_pbase[blockIdx.x] + s[t] - v;
}

__global__ void k_fill(const int* __restrict__ ei) {
    int e = blockIdx.x * blockDim.x + threadIdx.x;
    if (e >= NE) return;
    int s = clampN(ei[e]);
    int d = clampN(ei[NE + e]);
    int p = g_off[d] + atomicAdd(&g_fill[d], 1);
    g_edge[p] = make_int2(s, __float_as_int(g_dinv[s] * g_dinv[d]));
}

__global__ void k_bounds(const int* __restrict__ batch) {
    int i = blockIdx.x * blockDim.x + threadIdx.x;
    if (i >= NN) return;
    int b = batch[i];
    if (b < 0) b = 0; if (b >= NG) b = NG - 1;
    int bp = (i == 0) ? -1 : batch[i - 1];
    int bn = (i == NN - 1) ? -1 : batch[i + 1];
    if (i == 0      || bp != b) g_start[b] = i;
    if (i == NN - 1 || bn != b) g_end[b]   = i + 1;
}

// W^T + hi/lo bf16 decomposition: g_W*[l][n][k] = split(W[l][k][n])
__global__ void k_prepw(const float* __restrict__ Ws) {
    int idx = blockIdx.x * 128 + threadIdx.x;       // 3*128*128 total
    int l = idx >> 14, rem = idx & 16383;
    int n = rem >> 7, k = rem & 127;
    float w = Ws[l * 16384 + k * 128 + n];
    __nv_bfloat16 hi = __float2bfloat16_rn(w);
    __nv_bfloat16 lo = __float2bfloat16_rn(w - __bfloat162float(hi));
    g_Whi[idx] = hi;
    g_Wlo[idx] = lo;
}

// ---------------- HMMA GEMM: out[N,128] = bnrelu(in)[N,128] @ W ----------------
#define S_AH 0
#define S_AL 32768
#define S_WH 65536
#define S_WL 98304
#define MMASMEM 131072

__global__ __launch_bounds__(256) void k_gemm_mma(const float* __restrict__ in,
                                                  const __nv_bfloat16* __restrict__ Whi,
                                                  const __nv_bfloat16* __restrict__ Wlo,
                                                  float* __restrict__ out,
                                                  int apply) {
    extern __shared__ char smraw[];
    char* smc = smraw;
    uint32_t sb = smem_u32(smc);
    int tid = threadIdx.x, wid = tid >> 5, lane = tid & 31;
    int row0 = blockIdx.x * 128;

    // ---- stage W^T hi/lo
    {
        int n = tid >> 1, half = tid & 1;
        const uint4* src_h = (const uint4*)(Whi) + n * 16 + half * 8;
        const uint4* src_l = (const uint4*)(Wlo) + n * 16 + half * 8;
        uint32_t base = n * 256 + half * 128;
#pragma unroll
        for (int c = 0; c < 8; c++) {
            uint32_t o = sw(base + c * 16);
            *(uint4*)(smc + S_WH + o) = __ldg(&src_h[c]);
            *(uint4*)(smc + S_WL + o) = __ldg(&src_l[c]);
        }
    }
    // ---- stage A hi/lo with fused BN+ReLU
    {
        int r = tid >> 1, half = tid & 1;
        int grow = row0 + r;
        bool ok = grow < NN;
        const float4* src = (const float4*)(in + (size_t)grow * D) + half * 16;
        uint32_t base = r * 256 + half * 128;
#pragma unroll
        for (int c = 0; c < 8; c++) {
            float4 v0 = make_float4(0.f, 0.f, 0.f, 0.f), v1 = v0;
            if (ok) {
                v0 = __ldg(&src[c * 2]);
                v1 = __ldg(&src[c * 2 + 1]);
                if (apply) {
                    int cb = half * 16 + c * 2;
                    float4 s0 = ((const float4*)g_scale)[cb],   sh0 = ((const float4*)g_shift)[cb];
                    float4 s1 = ((const float4*)g_scale)[cb+1], sh1 = ((const float4*)g_shift)[cb+1];
                    v0.x = fmaxf(fmaf(v0.x, s0.x, sh0.x), 0.f);
                    v0.y = fmaxf(fmaf(v0.y, s0.y, sh0.y), 0.f);
                    v0.z = fmaxf(fmaf(v0.z, s0.z, sh0.z), 0.f);
                    v0.w = fmaxf(fmaf(v0.w, s0.w, sh0.w), 0.f);
                    v1.x = fmaxf(fmaf(v1.x, s1.x, sh1.x), 0.f);
                    v1.y = fmaxf(fmaf(v1.y, s1.y, sh1.y), 0.f);
                    v1.z = fmaxf(fmaf(v1.z, s1.z, sh1.z), 0.f);
                    v1.w = fmaxf(fmaf(v1.w, s1.w, sh1.w), 0.f);
                }
            }
            __nv_bfloat162 h0 = __float22bfloat162_rn(make_float2(v0.x, v0.y));
            __nv_bfloat162 h1 = __float22bfloat162_rn(make_float2(v0.z, v0.w));
            __nv_bfloat162 h2 = __float22bfloat162_rn(make_float2(v1.x, v1.y));
            __nv_bfloat162 h3 = __float22bfloat162_rn(make_float2(v1.z, v1.w));
            __nv_bfloat162 l0 = __float22bfloat162_rn(make_float2(v0.x - __bfloat162float(h0.x), v0.y - __bfloat162float(h0.y)));
            __nv_bfloat162 l1 = __float22bfloat162_rn(make_float2(v0.z - __bfloat162float(h1.x), v0.w - __bfloat162float(h1.y)));
            __nv_bfloat162 l2 = __float22bfloat162_rn(make_float2(v1.x - __bfloat162float(h2.x), v1.y - __bfloat162float(h2.y)));
            __nv_bfloat162 l3 = __float22bfloat162_rn(make_float2(v1.z - __bfloat162float(h3.x), v1.w - __bfloat162float(h3.y)));
            uint4 ph, pl;
            ph.x = *(uint32_t*)&h0; ph.y = *(uint32_t*)&h1; ph.z = *(uint32_t*)&h2; ph.w = *(uint32_t*)&h3;
            pl.x = *(uint32_t*)&l0; pl.y = *(uint32_t*)&l1; pl.z = *(uint32_t*)&l2; pl.w = *(uint32_t*)&l3;
            uint32_t o = sw(base + c * 16);
            *(uint4*)(smc + S_AH + o) = ph;
            *(uint4*)(smc + S_AL + o) = pl;
        }
    }
    __syncthreads();

    // ---- A fragments for this warp
    uint32_t afh[8][4], afl[8][4];
    uint32_t a_base = (wid * 16 + (lane & 15)) * 256 + ((lane >> 4) * 8) * 2;
#pragma unroll
    for (int k = 0; k < 8; k++) {
        uint32_t o = sw(a_base + k * 32);
        ldm_x4(afh[k], sb + S_AH + o);
        ldm_x4(afl[k], sb + S_AL + o);
    }

    uint32_t b_base = ((lane & 7) + ((lane >> 4) << 3)) * 256 + (((lane >> 3) & 1) * 8) * 2;
    int row_t = lane >> 2, col_t = (lane & 3) * 2;
    int grow0 = row0 + wid * 16 + row_t;
    int grow1 = grow0 + 8;

#pragma unroll 2
    for (int np = 0; np < 8; np++) {
        float ce[4] = {0.f, 0.f, 0.f, 0.f};
        float co[4] = {0.f, 0.f, 0.f, 0.f};
#pragma unroll
        for (int k = 0; k < 8; k++) {
            uint32_t bh[4], bl[4];
            uint32_t o = sw(b_base + np * 4096 + k * 32);
            ldm_x4(bh, sb + S_WH + o);
            ldm_x4(bl, sb + S_WL + o);
            mma_bf16(ce, afh[k], bh[0], bh[1]);
            mma_bf16(co, afh[k], bh[2], bh[3]);
            mma_bf16(ce, afh[k], bl[0], bl[1]);
            mma_bf16(co, afh[k], bl[2], bl[3]);
            mma_bf16(ce, afl[k], bh[0], bh[1]);
            mma_bf16(co, afl[k], bh[2], bh[3]);
        }
        int nb = np * 16;
        if (grow0 < NN) {
            *(float2*)(out + (size_t)grow0 * D + nb + col_t)     = make_float2(ce[0], ce[1]);
            *(float2*)(out + (size_t)grow0 * D + nb + 8 + col_t) = make_float2(co[0], co[1]);
        }
        if (grow1 < NN) {
            *(float2*)(out + (size_t)grow1 * D + nb + col_t)     = make_float2(ce[2], ce[3]);
            *(float2*)(out + (size_t)grow1 * D + nb + 8 + col_t) = make_float2(co[2], co[3]);
        }
    }
}

// ---------------- aggregation (gather, CSR) + bias + fused BN stats ----------------
__global__ __launch_bounds__(256) void k_agg(const float* __restrict__ tmp,
                                             float* __restrict__ outh,
                                             const float* __restrict__ bias) {
    __shared__ float bsum[D];
    __shared__ float bsq[D];
    int tid = threadIdx.x;
    if (tid < D) { bsum[tid] = 0.f; bsq[tid] = 0.f; }
    __syncthreads();

    int lane = tid & 31, wid = tid >> 5;
    const float4* t4 = (const float4*)tmp;
    float4 b4 = ((const float4*)bias)[lane];
    float ls0 = 0, ls1 = 0, ls2 = 0, ls3 = 0;
    float lq0 = 0, lq1 = 0, lq2 = 0, lq3 = 0;

    for (int row = blockIdx.x * 8 + wid; row < NN; row += gridDim.x * 8) {
        float4 acc = make_float4(0.f, 0.f, 0.f, 0.f);
        int e0 = g_off[row], e1 = g_off[row + 1];
        int e = e0;
        for (; e + 4 <= e1; e += 4) {
            int2 p0 = __ldg(&g_edge[e]);
            int2 p1 = __ldg(&g_edge[e + 1]);
            int2 p2 = __ldg(&g_edge[e + 2]);
            int2 p3 = __ldg(&g_edge[e + 3]);
            float4 v0 = t4[p0.x * 32 + lane];
            float4 v1 = t4[p1.x * 32 + lane];
            float4 v2 = t4[p2.x * 32 + lane];
            float4 v3 = t4[p3.x * 32 + lane];
            float w0 = __int_as_float(p0.y), w1 = __int_as_float(p1.y);
            float w2 = __int_as_float(p2.y), w3 = __int_as_float(p3.y);
            acc.x = fmaf(w0, v0.x, acc.x); acc.y = fmaf(w0, v0.y, acc.y);
            acc.z = fmaf(w0, v0.z, acc.z); acc.w = fmaf(w0, v0.w, acc.w);
            acc.x = fmaf(w1, v1.x, acc.x); acc.y = fmaf(w1, v1.y, acc.y);
            acc.z = fmaf(w1, v1.z, acc.z); acc.w = fmaf(w1, v1.w, acc.w);
            acc.x = fmaf(w2, v2.x, acc.x); acc.y = fmaf(w2, v2.y, acc.y);
            acc.z = fmaf(w2, v2.z, acc.z); acc.w = fmaf(w2, v2.w, acc.w);
            acc.x = fmaf(w3, v3.x, acc.x); acc.y = fmaf(w3, v3.y, acc.y);
            acc.z = fmaf(w3, v3.z, acc.z); acc.w = fmaf(w3, v3.w, acc.w);
        }
        for (; e < e1; e++) {
            int2 pp = __ldg(&g_edge[e]);
            float w = __int_as_float(pp.y);
            float4 v = t4[pp.x * 32 + lane];
            acc.x = fmaf(w, v.x, acc.x);
            acc.y = fmaf(w, v.y, acc.y);
            acc.z = fmaf(w, v.z, acc.z);
            acc.w = fmaf(w, v.w, acc.w);
        }
        float sw_ = g_selfw[row];
        float4 v = t4[row * 32 + lane];
        acc.x = fmaf(sw_, v.x, acc.x) + b4.x;
        acc.y = fmaf(sw_, v.y, acc.y) + b4.y;
        acc.z = fmaf(sw_, v.z, acc.z) + b4.z;
        acc.w = fmaf(sw_, v.w, acc.w) + b4.w;
        ((float4*)outh)[row * 32 + lane] = acc;
        ls0 += acc.x; ls1 += acc.y; ls2 += acc.z; ls3 += acc.w;
        lq0 += acc.x * acc.x; lq1 += acc.y * acc.y;
        lq2 += acc.z * acc.z; lq3 += acc.w * acc.w;
    }

    atomicAdd(&bsum[lane * 4 + 0], ls0); atomicAdd(&bsum[lane * 4 + 1], ls1);
    atomicAdd(&bsum[lane * 4 + 2], ls2); atomicAdd(&bsum[lane * 4 + 3], ls3);
    atomicAdd(&bsq[lane * 4 + 0], lq0);  atomicAdd(&bsq[lane * 4 + 1], lq1);
    atomicAdd(&bsq[lane * 4 + 2], lq2);  atomicAdd(&bsq[lane * 4 + 3], lq3);
    __syncthreads();
    if (tid < D) {
        atomicAdd(&g_sum[tid], (double)bsum[tid]);
        atomicAdd(&g_sq[tid],  (double)bsq[tid]);
    }
}

// computes affine from accumulated stats, then self-zeros for the next layer
__global__ void k_stats(const float* __restrict__ gamma, const float* __restrict__ beta) {
    int f = threadIdx.x;
    if (f >= D) return;
    float mu  = (float)(g_sum[f] / (double)NN);
    float var = (float)(g_sq[f] / (double)NN) - mu * mu;
    float rstd = rsqrtf(var + EPSV);
    float sc = rstd * gamma[f];
    g_scale[f] = sc;
    g_shift[f] = beta[f] - mu * sc;
    g_sum[f] = 0.0;
    g_sq[f]  = 0.0;
}

// ---------------- pooling (fused BN+ReLU of last layer) + MLP head ----------------
__global__ void k_pool(const float* __restrict__ h) {
    int g = blockIdx.x, f = threadIdx.x;
    int a = g_start[g], b = g_end[g];
    float sc = g_scale[f], sh = g_shift[f];
    float s0 = 0.f, s1 = 0.f, s2 = 0.f, s3 = 0.f;
    int i = a;
    for (; i + 4 <= b; i += 4) {
        s0 += fmaxf(fmaf(h[(i + 0) * D + f], sc, sh), 0.f);
        s1 += fmaxf(fmaf(h[(i + 1) * D + f], sc, sh), 0.f);
        s2 += fmaxf(fmaf(h[(i + 2) * D + f], sc, sh), 0.f);
        s3 += fmaxf(fmaf(h[(i + 3) * D + f], sc, sh), 0.f);
    }
    for (; i < b; i++) s0 += fmaxf(fmaf(h[i * D + f], sc, sh), 0.f);
    int c = b - a;
    g_Z[g * D + f] = ((s0 + s1) + (s2 + s3)) / (float)(c > 0 ? c : 1);
}

__global__ void k_head(const float* __restrict__ W1, const float* __restrict__ b1,
                       const float* __restrict__ W2, const float* __restrict__ b2,
                       float* __restrict__ out) {
    __shared__ float zs[D];
    __shared__ float red[4];
    int g = blockIdx.x, j = threadIdx.x;
    zs[j] = g_Z[g * D + j];
    __syncthreads();
    float acc = b1[j];
#pragma unroll 8
    for (int k = 0; k < D; k++) acc = fmaf(zs[k], W1[k * D + j], acc);
    float hz = fmaxf(acc, 0.f);
    float p = hz * W2[j];
#pragma unroll
    for (int o = 16; o; o >>= 1) p += __shfl_down_sync(0xffffffffu, p, o);
    if ((j & 31) == 0) red[j >> 5] = p;
    __syncthreads();
    if (j == 0) out[g] = red[0] + red[1] + red[2] + red[3] + b2[0];
}

// ---------------- launch ----------------
extern "C" void kernel_launch(void* const* d_in, const int* in_sizes, int n_in,
                              void* d_out, int out_size) {
    const float* x      = (const float*)d_in[0];
    const int*   ei     = (const int*)d_in[1];
    const int*   batch  = (const int*)d_in[2];
    const float* Ws     = (const float*)d_in[3];
    const float* bs     = (const float*)d_in[4];
    const float* gammas = (const float*)d_in[5];
    const float* betas  = (const float*)d_in[6];
    const float* W1     = (const float*)d_in[7];
    const float* b1     = (const float*)d_in[8];
    const float* W2     = (const float*)d_in[9];
    const float* b2     = (const float*)d_in[10];
    float* out = (float*)d_out;

    float *A, *B;
    __nv_bfloat16 *whi, *wlo;
    cudaGetSymbolAddress((void**)&A, g_bufA);
    cudaGetSymbolAddress((void**)&B, g_bufB);
    cudaGetSymbolAddress((void**)&whi, g_Whi);
    cudaGetSymbolAddress((void**)&wlo, g_Wlo);
    cudaFuncSetAttribute(k_gemm_mma, cudaFuncAttributeMaxDynamicSharedMemorySize, MMASMEM);

    const int NB_N = (NN + 255) / 256;   // 391
    const int NB_E = (NE + 255) / 256;   // 3125

    // Launch order arranged so launch index 5 (0-based, ncu -s 5 -c 1) is the
    // layer-0 GEMM — its only deps are x and k_prepw.
    k_zero_cnt<<<NB_N, 256>>>();                                        // 0
    k_count<<<NB_E, 256>>>(ei);                                         // 1
    k_node<<<NB_N, 256>>>();                                            // 2
    k_part<<<SCAN_B, 256>>>();                                          // 3
    k_prepw<<<3 * D * D / 128, 128>>>(Ws);                              // 4
    k_gemm_mma<<<NTILE, 256, MMASMEM>>>(x, whi, wlo, B, 0);             // 5 <- profiled
    k_scanpart<<<1, 512>>>();                                           // 6
    k_offsets<<<SCAN_B, 256>>>();                                       // 7
    k_fill<<<NB_E, 256>>>(ei);                                          // 8
    k_bounds<<<NB_N, 256>>>(batch);                                     // 9

    for (int l = 0; l < 3; l++) {
        if (l > 0)
            k_gemm_mma<<<NTILE, 256, MMASMEM>>>(A, whi + l * D * D, wlo + l * D * D, B, 1);
        k_agg<<<2048, 256>>>(B, A, bs + l * D);
        k_stats<<<1, 128>>>(gammas + l * D, betas + l * D);
    }

    k_pool<<<NG, 128>>>(A);
    k_head<<<NG, 128>>>(W1, b1, W2, b2, out);
}

// round 6
// speedup vs baseline: 1.3808x; 1.0501x over previous
#include <cuda_runtime.h>
#include <cuda_bf16.h>
#include <cstdint>

#define NN 100000
#define NE 800000
#define NG 512
#define D  128
#define EPSV 1e-5f
#define NTILE 782            // ceil(NN/128)
#define SCAN_B 391           // ceil(NN/256)
#define NSLOT 32

// ---------------- scratch (static device globals; no allocations) ----------------
__device__ float  g_bufA[NN * D];
__device__ float  g_bufB[NN * D];
__device__ float  g_dinv[NN];
__device__ float  g_selfw[NN];
__device__ int    g_cnt[NN];
__device__ int    g_fill[NN];
__device__ int    g_off[NN + 1];
__device__ int2   g_edge[NE];        // (src, __float_as_int(w))
__device__ int    g_part[SCAN_B];
__device__ int    g_pbase[SCAN_B];
__device__ float  g_psum[NSLOT * D];
__device__ float  g_psq[NSLOT * D];
__device__ float  g_scale[D];
__device__ float  g_shift[D];
__device__ float  g_Z[NG * D];
__device__ int    g_start[NG];
__device__ int    g_end[NG];
__device__ __nv_bfloat16 g_Whi[3 * D * D];   // W^T per layer, [n][k]
__device__ __nv_bfloat16 g_Wlo[3 * D * D];

__device__ __forceinline__ int clampN(int v) {
    return v < 0 ? 0 : (v >= NN ? NN - 1 : v);
}

__device__ __forceinline__ uint32_t smem_u32(const void* p) {
    uint32_t a;
    asm("{ .reg .u64 t; cvta.to.shared.u64 t, %1; cvt.u32.u64 %0, t; }" : "=r"(a) : "l"(p));
    return a;
}

// XOR swizzle for 256B rows
__device__ __forceinline__ uint32_t sw(uint32_t off) {
    return off ^ ((off >> 4) & 0x70);
}

__device__ __forceinline__ void ldm_x4(uint32_t* r, uint32_t addr) {
    asm volatile("ldmatrix.sync.aligned.m8n8.x4.shared.b16 {%0,%1,%2,%3}, [%4];"
                 : "=r"(r[0]), "=r"(r[1]), "=r"(r[2]), "=r"(r[3]) : "r"(addr));
}

__device__ __forceinline__ void mma_bf16(float* c, const uint32_t* a, uint32_t b0, uint32_t b1) {
    asm volatile(
        "mma.sync.aligned.m16n8k16.row.col.f32.bf16.bf16.f32 "
        "{%0,%1,%2,%3}, {%4,%5,%6,%7}, {%8,%9}, {%0,%1,%2,%3};"
        : "+f"(c[0]), "+f"(c[1]), "+f"(c[2]), "+f"(c[3])
        : "r"(a[0]), "r"(a[1]), "r"(a[2]), "r"(a[3]), "r"(b0), "r"(b1));
}

// ---------------- graph preprocessing ----------------
__global__ void k_zero_cnt() {
    int i = blockIdx.x * blockDim.x + threadIdx.x;
    if (i < NN) g_cnt[i] = 0;
}

__global__ void k_count(const int* __restrict__ ei) {
    int e = blockIdx.x * blockDim.x + threadIdx.x;
    if (e < NE) atomicAdd(&g_cnt[clampN(ei[NE + e])], 1);
}

__global__ void k_node() {
    int i = blockIdx.x * blockDim.x + threadIdx.x;
    if (i < NN) {
        float deg = (float)g_cnt[i] + 1.0f;
        g_dinv[i]  = rsqrtf(deg);
        g_selfw[i] = 1.0f / deg;
        g_fill[i]  = 0;
    }
    if (i < NG) { g_start[i] = 0; g_end[i] = 0; }
    if (i < NSLOT * D) { g_psum[i] = 0.f; g_psq[i] = 0.f; }
}

__global__ void k_part() {
    __shared__ int s[256];
    int t = threadIdx.x;
    int i = blockIdx.x * 256 + t;
    int v = (i < NN) ? g_cnt[i] : 0;
    s[t] = v; __syncthreads();
    for (int o = 128; o; o >>= 1) { if (t < o) s[t] += s[t + o]; __syncthreads(); }
    if (t == 0) g_part[blockIdx.x] = s[0];
}

__global__ void k_scanpart() {
    __shared__ int s[512];
    int t = threadIdx.x;
    int v = (t < SCAN_B) ? g_part[t] : 0;
    s[t] = v; __syncthreads();
    for (int d = 1; d < 512; d <<= 1) {
        int x = (t >= d) ? s[t - d] : 0;
        __syncthreads();
        s[t] += x;
        __syncthreads();
    }
    if (t < SCAN_B) g_pbase[t] = s[t] - v;
    if (t == SCAN_B - 1) g_off[NN] = s[t];
}

__global__ void k_offsets() {
    __shared__ int s[256];
    int t = threadIdx.x;
    int i = blockIdx.x * 256 + t;
    int v = (i < NN) ? g_cnt[i] : 0;
    s[t] = v; __syncthreads();
    for (int d = 1; d < 256; d <<= 1) {
        int x = (t >= d) ? s[t - d] : 0;
        __syncthreads();
        s[t] += x;
        __syncthreads();
    }
    if (i < NN) g_off[i] = g_pbase[blockIdx.x] + s[t] - v;
}

__global__ void k_fill(const int* __restrict__ ei) {
    int e = blockIdx.x * blockDim.x + threadIdx.x;
    if (e >= NE) return;
    int s = clampN(ei[e]);
    int d = clampN(ei[NE + e]);
    int p = g_off[d] + atomicAdd(&g_fill[d], 1);
    g_edge[p] = make_int2(s, __float_as_int(g_dinv[s] * g_dinv[d]));
}

__global__ void k_bounds(const int* __restrict__ batch) {
    int i = blockIdx.x * blockDim.x + threadIdx.x;
    if (i >= NN) return;
    int b = batch[i];
    if (b < 0) b = 0; if (b >= NG) b = NG - 1;
    int bp = (i == 0) ? -1 : batch[i - 1];
    int bn = (i == NN - 1) ? -1 : batch[i + 1];
    if (i == 0      || bp != b) g_start[b] = i;
    if (i == NN - 1 || bn != b) g_end[b]   = i + 1;
}

// W^T + hi/lo bf16 decomposition: g_W*[l][n][k] = split(W[l][k][n])
__global__ void k_prepw(const float* __restrict__ Ws) {
    int idx = blockIdx.x * 128 + threadIdx.x;       // 3*128*128 total
    int l = idx >> 14, rem = idx & 16383;
    int n = rem >> 7, k = rem & 127;
    float w = Ws[l * 16384 + k * 128 + n];
    __nv_bfloat16 hi = __float2bfloat16_rn(w);
    __nv_bfloat16 lo = __float2bfloat16_rn(w - __bfloat162float(hi));
    g_Whi[idx] = hi;
    g_Wlo[idx] = lo;
}

// ---------------- HMMA GEMM: out[N,128] = bnrelu(in)[N,128] @ W ----------------
#define S_AH 0
#define S_AL 32768
#define S_WH 65536
#define S_WL 98304
#define MMASMEM 131072

__global__ __launch_bounds__(256) void k_gemm_mma(const float* __restrict__ in,
                                                  const __nv_bfloat16* __restrict__ Whi,
                                                  const __nv_bfloat16* __restrict__ Wlo,
                                                  float* __restrict__ out,
                                                  int apply) {
    extern __shared__ char smraw[];
    char* smc = smraw;
    uint32_t sb = smem_u32(smc);
    int tid = threadIdx.x, wid = tid >> 5, lane = tid & 31;
    int row0 = blockIdx.x * 128;

    // ---- stage W^T hi/lo
    {
        int n = tid >> 1, half = tid & 1;
        const uint4* src_h = (const uint4*)(Whi) + n * 16 + half * 8;
        const uint4* src_l = (const uint4*)(Wlo) + n * 16 + half * 8;
        uint32_t base = n * 256 + half * 128;
#pragma unroll
        for (int c = 0; c < 8; c++) {
            uint32_t o = sw(base + c * 16);
            *(uint4*)(smc + S_WH + o) = __ldg(&src_h[c]);
            *(uint4*)(smc + S_WL + o) = __ldg(&src_l[c]);
        }
    }
    // ---- stage A hi/lo with fused BN+ReLU
    {
        int r = tid >> 1, half = tid & 1;
        int grow = row0 + r;
        bool ok = grow < NN;
        const float4* src = (const float4*)(in + (size_t)grow * D) + half * 16;
        uint32_t base = r * 256 + half * 128;
#pragma unroll
        for (int c = 0; c < 8; c++) {
            float4 v0 = make_float4(0.f, 0.f, 0.f, 0.f), v1 = v0;
            if (ok) {
                v0 = __ldg(&src[c * 2]);
                v1 = __ldg(&src[c * 2 + 1]);
                if (apply) {
                    int cb = half * 16 + c * 2;
                    float4 s0 = ((const float4*)g_scale)[cb],   sh0 = ((const float4*)g_shift)[cb];
                    float4 s1 = ((const float4*)g_scale)[cb+1], sh1 = ((const float4*)g_shift)[cb+1];
                    v0.x = fmaxf(fmaf(v0.x, s0.x, sh0.x), 0.f);
                    v0.y = fmaxf(fmaf(v0.y, s0.y, sh0.y), 0.f);
                    v0.z = fmaxf(fmaf(v0.z, s0.z, sh0.z), 0.f);
                    v0.w = fmaxf(fmaf(v0.w, s0.w, sh0.w), 0.f);
                    v1.x = fmaxf(fmaf(v1.x, s1.x, sh1.x), 0.f);
                    v1.y = fmaxf(fmaf(v1.y, s1.y, sh1.y), 0.f);
                    v1.z = fmaxf(fmaf(v1.z, s1.z, sh1.z), 0.f);
                    v1.w = fmaxf(fmaf(v1.w, s1.w, sh1.w), 0.f);
                }
            }
            __nv_bfloat162 h0 = __float22bfloat162_rn(make_float2(v0.x, v0.y));
            __nv_bfloat162 h1 = __float22bfloat162_rn(make_float2(v0.z, v0.w));
            __nv_bfloat162 h2 = __float22bfloat162_rn(make_float2(v1.x, v1.y));
            __nv_bfloat162 h3 = __float22bfloat162_rn(make_float2(v1.z, v1.w));
            __nv_bfloat162 l0 = __float22bfloat162_rn(make_float2(v0.x - __bfloat162float(h0.x), v0.y - __bfloat162float(h0.y)));
            __nv_bfloat162 l1 = __float22bfloat162_rn(make_float2(v0.z - __bfloat162float(h1.x), v0.w - __bfloat162float(h1.y)));
            __nv_bfloat162 l2 = __float22bfloat162_rn(make_float2(v1.x - __bfloat162float(h2.x), v1.y - __bfloat162float(h2.y)));
            __nv_bfloat162 l3 = __float22bfloat162_rn(make_float2(v1.z - __bfloat162float(h3.x), v1.w - __bfloat162float(h3.y)));
            uint4 ph, pl;
            ph.x = *(uint32_t*)&h0; ph.y = *(uint32_t*)&h1; ph.z = *(uint32_t*)&h2; ph.w = *(uint32_t*)&h3;
            pl.x = *(uint32_t*)&l0; pl.y = *(uint32_t*)&l1; pl.z = *(uint32_t*)&l2; pl.w = *(uint32_t*)&l3;
            uint32_t o = sw(base + c * 16);
            *(uint4*)(smc + S_AH + o) = ph;
            *(uint4*)(smc + S_AL + o) = pl;
        }
    }
    __syncthreads();

    // ---- A fragments for this warp
    uint32_t afh[8][4], afl[8][4];
    uint32_t a_base = (wid * 16 + (lane & 15)) * 256 + ((lane >> 4) * 8) * 2;
#pragma unroll
    for (int k = 0; k < 8; k++) {
        uint32_t o = sw(a_base + k * 32);
        ldm_x4(afh[k], sb + S_AH + o);
        ldm_x4(afl[k], sb + S_AL + o);
    }

    uint32_t b_base = ((lane & 7) + ((lane >> 4) << 3)) * 256 + (((lane >> 3) & 1) * 8) * 2;
    int row_t = lane >> 2, col_t = (lane & 3) * 2;
    int grow0 = row0 + wid * 16 + row_t;
    int grow1 = grow0 + 8;

#pragma unroll 2
    for (int np = 0; np < 8; np++) {
        float ce[4] = {0.f, 0.f, 0.f, 0.f};
        float co[4] = {0.f, 0.f, 0.f, 0.f};
#pragma unroll
        for (int k = 0; k < 8; k++) {
            uint32_t bh[4], bl[4];
            uint32_t o = sw(b_base + np * 4096 + k * 32);
            ldm_x4(bh, sb + S_WH + o);
            ldm_x4(bl, sb + S_WL + o);
            mma_bf16(ce, afh[k], bh[0], bh[1]);
            mma_bf16(co, afh[k], bh[2], bh[3]);
            mma_bf16(ce, afh[k], bl[0], bl[1]);
            mma_bf16(co, afh[k], bl[2], bl[3]);
            mma_bf16(ce, afl[k], bh[0], bh[1]);
            mma_bf16(co, afl[k], bh[2], bh[3]);
        }
        int nb = np * 16;
        if (grow0 < NN) {
            *(float2*)(out + (size_t)grow0 * D + nb + col_t)     = make_float2(ce[0], ce[1]);
            *(float2*)(out + (size_t)grow0 * D + nb + 8 + col_t) = make_float2(co[0], co[1]);
        }
        if (grow1 < NN) {
            *(float2*)(out + (size_t)grow1 * D + nb + col_t)     = make_float2(ce[2], ce[3]);
            *(float2*)(out + (size_t)grow1 * D + nb + 8 + col_t) = make_float2(co[2], co[3]);
        }
    }
}

// ---------------- aggregation (gather, CSR) + bias + fused BN stats ----------------
__global__ __launch_bounds__(256) void k_agg(const float* __restrict__ tmp,
                                             float* __restrict__ outh,
                                             const float* __restrict__ bias) {
    __shared__ float bsum[D];
    __shared__ float bsq[D];
    int tid = threadIdx.x;
    if (tid < D) { bsum[tid] = 0.f; bsq[tid] = 0.f; }
    __syncthreads();

    int lane = tid & 31, wid = tid >> 5;
    const float4* t4 = (const float4*)tmp;
    float4 b4 = ((const float4*)bias)[lane];
    float ls0 = 0, ls1 = 0, ls2 = 0, ls3 = 0;
    float lq0 = 0, lq1 = 0, lq2 = 0, lq3 = 0;

    for (int row = blockIdx.x * 8 + wid; row < NN; row += gridDim.x * 8) {
        float4 acc = make_float4(0.f, 0.f, 0.f, 0.f);
        int e0 = g_off[row], e1 = g_off[row + 1];
        int e = e0;
        for (; e + 4 <= e1; e += 4) {
            int2 p0 = __ldg(&g_edge[e]);
            int2 p1 = __ldg(&g_edge[e + 1]);
            int2 p2 = __ldg(&g_edge[e + 2]);
            int2 p3 = __ldg(&g_edge[e + 3]);
            float4 v0 = t4[p0.x * 32 + lane];
            float4 v1 = t4[p1.x * 32 + lane];
            float4 v2 = t4[p2.x * 32 + lane];
            float4 v3 = t4[p3.x * 32 + lane];
            float w0 = __int_as_float(p0.y), w1 = __int_as_float(p1.y);
            float w2 = __int_as_float(p2.y), w3 = __int_as_float(p3.y);
            acc.x = fmaf(w0, v0.x, acc.x); acc.y = fmaf(w0, v0.y, acc.y);
            acc.z = fmaf(w0, v0.z, acc.z); acc.w = fmaf(w0, v0.w, acc.w);
            acc.x = fmaf(w1, v1.x, acc.x); acc.y = fmaf(w1, v1.y, acc.y);
            acc.z = fmaf(w1, v1.z, acc.z); acc.w = fmaf(w1, v1.w, acc.w);
            acc.x = fmaf(w2, v2.x, acc.x); acc.y = fmaf(w2, v2.y, acc.y);
            acc.z = fmaf(w2, v2.z, acc.z); acc.w = fmaf(w2, v2.w, acc.w);
            acc.x = fmaf(w3, v3.x, acc.x); acc.y = fmaf(w3, v3.y, acc.y);
            acc.z = fmaf(w3, v3.z, acc.z); acc.w = fmaf(w3, v3.w, acc.w);
        }
        for (; e < e1; e++) {
            int2 pp = __ldg(&g_edge[e]);
            float w = __int_as_float(pp.y);
            float4 v = t4[pp.x * 32 + lane];
            acc.x = fmaf(w, v.x, acc.x);
            acc.y = fmaf(w, v.y, acc.y);
            acc.z = fmaf(w, v.z, acc.z);
            acc.w = fmaf(w, v.w, acc.w);
        }
        float sw_ = g_selfw[row];
        float4 v = t4[row * 32 + lane];
        acc.x = fmaf(sw_, v.x, acc.x) + b4.x;
        acc.y = fmaf(sw_, v.y, acc.y) + b4.y;
        acc.z = fmaf(sw_, v.z, acc.z) + b4.z;
        acc.w = fmaf(sw_, v.w, acc.w) + b4.w;
        ((float4*)outh)[row * 32 + lane] = acc;
        ls0 += acc.x; ls1 += acc.y; ls2 += acc.z; ls3 += acc.w;
        lq0 += acc.x * acc.x; lq1 += acc.y * acc.y;
        lq2 += acc.z * acc.z; lq3 += acc.w * acc.w;
    }

    atomicAdd(&bsum[lane * 4 + 0], ls0); atomicAdd(&bsum[lane * 4 + 1], ls1);
    atomicAdd(&bsum[lane * 4 + 2], ls2); atomicAdd(&bsum[lane * 4 + 3], ls3);
    atomicAdd(&bsq[lane * 4 + 0], lq0);  atomicAdd(&bsq[lane * 4 + 1], lq1);
    atomicAdd(&bsq[lane * 4 + 2], lq2);  atomicAdd(&bsq[lane * 4 + 3], lq3);
    __syncthreads();
    // 32-way slotted fp32 partials: 64 (not 2048) serialized ops per address,
    // fp32 RED instead of fp64 RMW.
    if (tid < D) {
        int slot = (blockIdx.x & (NSLOT - 1)) * D + tid;
        atomicAdd(&g_psum[slot], bsum[tid]);
        atomicAdd(&g_psq[slot],  bsq[tid]);
    }
}

// reduce slots -> affine coeffs, then self-zero slots for the next layer
__global__ void k_stats(const float* __restrict__ gamma, const float* __restrict__ beta) {
    int f = threadIdx.x;
    if (f >= D) return;
    float s = 0.f, q = 0.f;
#pragma unroll
    for (int k = 0; k < NSLOT; k++) {
        s += g_psum[k * D + f];
        q += g_psq[k * D + f];
        g_psum[k * D + f] = 0.f;
        g_psq[k * D + f]  = 0.f;
    }
    float mu  = s / (float)NN;
    float var = q / (float)NN - mu * mu;
    float rstd = rsqrtf(var + EPSV);
    float sc = rstd * gamma[f];
    g_scale[f] = sc;
    g_shift[f] = beta[f] - mu * sc;
}

// ---------------- pooling (fused BN+ReLU of last layer) + MLP head ----------------
__global__ void k_pool(const float* __restrict__ h) {
    int g = blockIdx.x, f = threadIdx.x;
    int a = g_start[g], b = g_end[g];
    float sc = g_scale[f], sh = g_shift[f];
    float s0 = 0.f, s1 = 0.f, s2 = 0.f, s3 = 0.f;
    int i = a;
    for (; i + 4 <= b; i += 4) {
        s0 += fmaxf(fmaf(h[(i + 0) * D + f], sc, sh), 0.f);
        s1 += fmaxf(fmaf(h[(i + 1) * D + f], sc, sh), 0.f);
        s2 += fmaxf(fmaf(h[(i + 2) * D + f], sc, sh), 0.f);
        s3 += fmaxf(fmaf(h[(i + 3) * D + f], sc, sh), 0.f);
    }
    for (; i < b; i++) s0 += fmaxf(fmaf(h[i * D + f], sc, sh), 0.f);
    int c = b - a;
    g_Z[g * D + f] = ((s0 + s1) + (s2 + s3)) / (float)(c > 0 ? c : 1);
}

__global__ void k_head(const float* __restrict__ W1, const float* __restrict__ b1,
                       const float* __restrict__ W2, const float* __restrict__ b2,
                       float* __restrict__ out) {
    __shared__ float zs[D];
    __shared__ float red[4];
    int g = blockIdx.x, j = threadIdx.x;
    zs[j] = g_Z[g * D + j];
    __syncthreads();
    float acc = b1[j];
#pragma unroll 8
    for (int k = 0; k < D; k++) acc = fmaf(zs[k], W1[k * D + j], acc);
    float hz = fmaxf(acc, 0.f);
    float p = hz * W2[j];
#pragma unroll
    for (int o = 16; o; o >>= 1) p += __shfl_down_sync(0xffffffffu, p, o);
    if ((j & 31) == 0) red[j >> 5] = p;
    __syncthreads();
    if (j == 0) out[g] = red[0] + red[1] + red[2] + red[3] + b2[0];
}

// ---------------- launch ----------------
extern "C" void kernel_launch(void* const* d_in, const int* in_sizes, int n_in,
                              void* d_out, int out_size) {
    const float* x      = (const float*)d_in[0];
    const int*   ei     = (const int*)d_in[1];
    const int*   batch  = (const int*)d_in[2];
    const float* Ws     = (const float*)d_in[3];
    const float* bs     = (const float*)d_in[4];
    const float* gammas = (const float*)d_in[5];
    const float* betas  = (const float*)d_in[6];
    const float* W1     = (const float*)d_in[7];
    const float* b1     = (const float*)d_in[8];
    const float* W2     = (const float*)d_in[9];
    const float* b2     = (const float*)d_in[10];
    float* out = (float*)d_out;

    float *A, *B;
    __nv_bfloat16 *whi, *wlo;
    cudaGetSymbolAddress((void**)&A, g_bufA);
    cudaGetSymbolAddress((void**)&B, g_bufB);
    cudaGetSymbolAddress((void**)&whi, g_Whi);
    cudaGetSymbolAddress((void**)&wlo, g_Wlo);
    cudaFuncSetAttribute(k_gemm_mma, cudaFuncAttributeMaxDynamicSharedMemorySize, MMASMEM);

    const int NB_N = (NN + 255) / 256;   // 391
    const int NB_E = (NE + 255) / 256;   // 3125

    // Profiler calibration: both prior rounds captured launch index 3 (0-based).
    // Place the layer-0 GEMM at index 3 (deps: x, k_prepw only).
    k_prepw<<<3 * D * D / 128, 128>>>(Ws);                              // 0
    k_zero_cnt<<<NB_N, 256>>>();                                        // 1
    k_count<<<NB_E, 256>>>(ei);                                         // 2
    k_gemm_mma<<<NTILE, 256, MMASMEM>>>(x, whi, wlo, B, 0);             // 3 <- profiled
    k_node<<<NB_N, 256>>>();                                            // 4
    k_part<<<SCAN_B, 256>>>();                                          // 5
    k_scanpart<<<1, 512>>>();                                           // 6
    k_offsets<<<SCAN_B, 256>>>();                                       // 7
    k_fill<<<NB_E, 256>>>(ei);                                          // 8
    k_bounds<<<NB_N, 256>>>(batch);                                     // 9

    for (int l = 0; l < 3; l++) {
        if (l > 0)
            k_gemm_mma<<<NTILE, 256, MMASMEM>>>(A, whi + l * D * D, wlo + l * D * D, B, 1);
        k_agg<<<2048, 256>>>(B, A, bs + l * D);
        k_stats<<<1, 128>>>(gammas + l * D, betas + l * D);
    }

    k_pool<<<NG, 128>>>(A);
    k_head<<<NG, 128>>>(W1, b1, W2, b2, out);
}

// round 7
// speedup vs baseline: 1.5400x; 1.1153x over previous
#include <cuda_runtime.h>
#include <cuda_bf16.h>
#include <cstdint>

#define NN 100000
#define NE 800000
#define NG 512
#define D  128
#define EPSV 1e-5f
#define NTILE 782            // ceil(NN/128)
#define SCAN_B 391           // ceil(NN/256)
#define NSLOT 32

// ---------------- scratch (static device globals; no allocations) ----------------
__device__ float  g_bufA[NN * D];
__device__ float  g_bufB[NN * D];
__device__ float  g_dinv[NN];
__device__ float  g_selfw[NN];
__device__ int    g_cnt[NN];
__device__ int    g_fill[NN];
__device__ int    g_off[NN + 1];
__device__ int2   g_edge[NE];        // (src, __float_as_int(w))
__device__ int    g_part[SCAN_B];
__device__ int    g_pbase[SCAN_B];
__device__ float  g_psum[NSLOT * D];
__device__ float  g_psq[NSLOT * D];
__device__ float  g_scale[D];
__device__ float  g_shift[D];
__device__ float  g_Z[NG * D];
__device__ int    g_start[NG];
__device__ int    g_end[NG];
__device__ __nv_bfloat16 g_Whi[3 * D * D];   // W^T per layer, [n][k]
__device__ __nv_bfloat16 g_Wlo[3 * D * D];

__device__ __forceinline__ int clampN(int v) {
    return v < 0 ? 0 : (v >= NN ? NN - 1 : v);
}

__device__ __forceinline__ uint32_t smem_u32(const void* p) {
    uint32_t a;
    asm("{ .reg .u64 t; cvta.to.shared.u64 t, %1; cvt.u32.u64 %0, t; }" : "=r"(a) : "l"(p));
    return a;
}

// XOR swizzle for 256B rows
__device__ __forceinline__ uint32_t sw(uint32_t off) {
    return off ^ ((off >> 4) & 0x70);
}

__device__ __forceinline__ void ldm_x4(uint32_t* r, uint32_t addr) {
    asm volatile("ldmatrix.sync.aligned.m8n8.x4.shared.b16 {%0,%1,%2,%3}, [%4];"
                 : "=r"(r[0]), "=r"(r[1]), "=r"(r[2]), "=r"(r[3]) : "r"(addr));
}

__device__ __forceinline__ void mma_bf16(float* c, const uint32_t* a, uint32_t b0, uint32_t b1) {
    asm volatile(
        "mma.sync.aligned.m16n8k16.row.col.f32.bf16.bf16.f32 "
        "{%0,%1,%2,%3}, {%4,%5,%6,%7}, {%8,%9}, {%0,%1,%2,%3};"
        : "+f"(c[0]), "+f"(c[1]), "+f"(c[2]), "+f"(c[3])
        : "r"(a[0]), "r"(a[1]), "r"(a[2]), "r"(a[3]), "r"(b0), "r"(b1));
}

// split fp32 pair into bf16x2 hi + lo packed regs
__device__ __forceinline__ void split2(float2 v, uint32_t& hi, uint32_t& lo) {
    __nv_bfloat162 h = __float22bfloat162_rn(v);
    __nv_bfloat162 l = __float22bfloat162_rn(make_float2(
        v.x - __bfloat162float(h.x), v.y - __bfloat162float(h.y)));
    hi = *(uint32_t*)&h;
    lo = *(uint32_t*)&l;
}

// ---------------- graph preprocessing ----------------
__global__ void k_zero_cnt() {
    int i = blockIdx.x * blockDim.x + threadIdx.x;
    if (i < NN) g_cnt[i] = 0;
}

__global__ void k_count(const int* __restrict__ ei) {
    int e = blockIdx.x * blockDim.x + threadIdx.x;
    if (e < NE) atomicAdd(&g_cnt[clampN(ei[NE + e])], 1);
}

__global__ void k_node() {
    int i = blockIdx.x * blockDim.x + threadIdx.x;
    if (i < NN) {
        float deg = (float)g_cnt[i] + 1.0f;
        g_dinv[i]  = rsqrtf(deg);
        g_selfw[i] = 1.0f / deg;
        g_fill[i]  = 0;
    }
    if (i < NG) { g_start[i] = 0; g_end[i] = 0; }
    if (i < NSLOT * D) { g_psum[i] = 0.f; g_psq[i] = 0.f; }
}

__global__ void k_part() {
    __shared__ int s[256];
    int t = threadIdx.x;
    int i = blockIdx.x * 256 + t;
    int v = (i < NN) ? g_cnt[i] : 0;
    s[t] = v; __syncthreads();
    for (int o = 128; o; o >>= 1) { if (t < o) s[t] += s[t + o]; __syncthreads(); }
    if (t == 0) g_part[blockIdx.x] = s[0];
}

__global__ void k_scanpart() {
    __shared__ int s[512];
    int t = threadIdx.x;
    int v = (t < SCAN_B) ? g_part[t] : 0;
    s[t] = v; __syncthreads();
    for (int d = 1; d < 512; d <<= 1) {
        int x = (t >= d) ? s[t - d] : 0;
        __syncthreads();
        s[t] += x;
        __syncthreads();
    }
    if (t < SCAN_B) g_pbase[t] = s[t] - v;
    if (t == SCAN_B - 1) g_off[NN] = s[t];
}

__global__ void k_offsets() {
    __shared__ int s[256];
    int t = threadIdx.x;
    int i = blockIdx.x * 256 + t;
    int v = (i < NN) ? g_cnt[i] : 0;
    s[t] = v; __syncthreads();
    for (int d = 1; d < 256; d <<= 1) {
        int x = (t >= d) ? s[t - d] : 0;
        __syncthreads();
        s[t] += x;
        __syncthreads();
    }
    if (i < NN) g_off[i] = g_pbase[blockIdx.x] + s[t] - v;
}

__global__ void k_fill(const int* __restrict__ ei) {
    int e = blockIdx.x * blockDim.x + threadIdx.x;
    if (e >= NE) return;
    int s = clampN(ei[e]);
    int d = clampN(ei[NE + e]);
    int p = g_off[d] + atomicAdd(&g_fill[d], 1);
    g_edge[p] = make_int2(s, __float_as_int(g_dinv[s] * g_dinv[d]));
}

__global__ void k_bounds(const int* __restrict__ batch) {
    int i = blockIdx.x * blockDim.x + threadIdx.x;
    if (i >= NN) return;
    int b = batch[i];
    if (b < 0) b = 0; if (b >= NG) b = NG - 1;
    int bp = (i == 0) ? -1 : batch[i - 1];
    int bn = (i == NN - 1) ? -1 : batch[i + 1];
    if (i == 0      || bp != b) g_start[b] = i;
    if (i == NN - 1 || bn != b) g_end[b]   = i + 1;
}

// W^T + hi/lo bf16 decomposition: g_W*[l][n][k] = split(W[l][k][n])
__global__ void k_prepw(const float* __restrict__ Ws) {
    int idx = blockIdx.x * 128 + threadIdx.x;       // 3*128*128 total
    int l = idx >> 14, rem = idx & 16383;
    int n = rem >> 7, k = rem & 127;
    float w = Ws[l * 16384 + k * 128 + n];
    __nv_bfloat16 hi = __float2bfloat16_rn(w);
    __nv_bfloat16 lo = __float2bfloat16_rn(w - __bfloat162float(hi));
    g_Whi[idx] = hi;
    g_Wlo[idx] = lo;
}

// ---------------- HMMA GEMM: out[N,128] = bnrelu(in)[N,128] @ W ----------------
// smem: only W^T hi/lo (2 x 32KB). A fragments loaded per-lane from global.
#define S_WH 0
#define S_WL 32768
#define MMASMEM 65536

__global__ __launch_bounds__(256) void k_gemm_mma(const float* __restrict__ in,
                                                  const __nv_bfloat16* __restrict__ Whi,
                                                  const __nv_bfloat16* __restrict__ Wlo,
                                                  float* __restrict__ out,
                                                  int apply) {
    extern __shared__ char smc[];
    uint32_t sb = smem_u32(smc);
    int tid = threadIdx.x, wid = tid >> 5, lane = tid & 31;
    int row0 = blockIdx.x * 128;

    // ---- stage W^T hi/lo (row n = tid/2, half = tid&1 -> 128B each)
    {
        int n = tid >> 1, half = tid & 1;
        const uint4* src_h = (const uint4*)(Whi) + n * 16 + half * 8;
        const uint4* src_l = (const uint4*)(Wlo) + n * 16 + half * 8;
        uint32_t base = n * 256 + half * 128;
#pragma unroll
        for (int c = 0; c < 8; c++) {
            uint32_t o = sw(base + c * 16);
            *(uint4*)(smc + S_WH + o) = __ldg(&src_h[c]);
            *(uint4*)(smc + S_WL + o) = __ldg(&src_l[c]);
        }
    }

    // ---- A fragments: direct per-lane global loads + BN/ReLU + hi/lo split
    int groupID = lane >> 2, tig = lane & 3;
    int r0 = row0 + wid * 16 + groupID;
    int r1 = r0 + 8;
    bool ok0 = r0 < NN, ok1 = r1 < NN;
    const float2* p0 = (const float2*)(in + (size_t)r0 * D) + tig;
    const float2* p1 = (const float2*)(in + (size_t)r1 * D) + tig;

    uint32_t afh[8][4], afl[8][4];
#pragma unroll
    for (int k = 0; k < 8; k++) {
        float2 a0 = ok0 ? __ldg(&p0[k * 8])     : make_float2(0.f, 0.f);
        float2 a1 = ok1 ? __ldg(&p1[k * 8])     : make_float2(0.f, 0.f);
        float2 a2 = ok0 ? __ldg(&p0[k * 8 + 4]) : make_float2(0.f, 0.f);
        float2 a3 = ok1 ? __ldg(&p1[k * 8 + 4]) : make_float2(0.f, 0.f);
        if (apply) {
            float2 s0 = ((const float2*)g_scale)[tig + k * 8];
            float2 h0 = ((const float2*)g_shift)[tig + k * 8];
            float2 s1 = ((const float2*)g_scale)[tig + k * 8 + 4];
            float2 h1 = ((const float2*)g_shift)[tig + k * 8 + 4];
            a0.x = fmaxf(fmaf(a0.x, s0.x, h0.x), 0.f);
            a0.y = fmaxf(fmaf(a0.y, s0.y, h0.y), 0.f);
            a1.x = fmaxf(fmaf(a1.x, s0.x, h0.x), 0.f);
            a1.y = fmaxf(fmaf(a1.y, s0.y, h0.y), 0.f);
            a2.x = fmaxf(fmaf(a2.x, s1.x, h1.x), 0.f);
            a2.y = fmaxf(fmaf(a2.y, s1.y, h1.y), 0.f);
            a3.x = fmaxf(fmaf(a3.x, s1.x, h1.x), 0.f);
            a3.y = fmaxf(fmaf(a3.y, s1.y, h1.y), 0.f);
        }
        split2(a0, afh[k][0], afl[k][0]);
        split2(a1, afh[k][1], afl[k][1]);
        split2(a2, afh[k][2], afl[k][2]);
        split2(a3, afh[k][3], afl[k][3]);
    }
    __syncthreads();   // W staged

    uint32_t b_base = ((lane & 7) + ((lane >> 4) << 3)) * 256 + (((lane >> 3) & 1) * 8) * 2;
    int col_t = tig * 2;
    // output rows are r0 (ce[0..1]), r1 (ce[2..3]) per mma layout

#pragma unroll 2
    for (int np = 0; np < 8; np++) {
        float ce[4] = {0.f, 0.f, 0.f, 0.f};
        float co[4] = {0.f, 0.f, 0.f, 0.f};
#pragma unroll
        for (int k = 0; k < 8; k++) {
            uint32_t bh[4], bl[4];
            uint32_t o = sw(b_base + np * 4096 + k * 32);
            ldm_x4(bh, sb + S_WH + o);
            ldm_x4(bl, sb + S_WL + o);
            mma_bf16(ce, afh[k], bh[0], bh[1]);
            mma_bf16(co, afh[k], bh[2], bh[3]);
            mma_bf16(ce, afh[k], bl[0], bl[1]);
            mma_bf16(co, afh[k], bl[2], bl[3]);
            mma_bf16(ce, afl[k], bh[0], bh[1]);
            mma_bf16(co, afl[k], bh[2], bh[3]);
        }
        int nb = np * 16;
        if (ok0) {
            *(float2*)(out + (size_t)r0 * D + nb + col_t)     = make_float2(ce[0], ce[1]);
            *(float2*)(out + (size_t)r0 * D + nb + 8 + col_t) = make_float2(co[0], co[1]);
        }
        if (ok1) {
            *(float2*)(out + (size_t)r1 * D + nb + col_t)     = make_float2(ce[2], ce[3]);
            *(float2*)(out + (size_t)r1 * D + nb + 8 + col_t) = make_float2(co[2], co[3]);
        }
    }
}

// ---------------- aggregation (gather, CSR) + bias + fused BN stats ----------------
__global__ __launch_bounds__(256) void k_agg(const float* __restrict__ tmp,
                                             float* __restrict__ outh,
                                             const float* __restrict__ bias) {
    __shared__ float bsum[D];
    __shared__ float bsq[D];
    int tid = threadIdx.x;
    if (tid < D) { bsum[tid] = 0.f; bsq[tid] = 0.f; }
    __syncthreads();

    int lane = tid & 31, wid = tid >> 5;
    const float4* t4 = (const float4*)tmp;
    float4 b4 = ((const float4*)bias)[lane];
    float ls0 = 0, ls1 = 0, ls2 = 0, ls3 = 0;
    float lq0 = 0, lq1 = 0, lq2 = 0, lq3 = 0;

    for (int row = blockIdx.x * 8 + wid; row < NN; row += gridDim.x * 8) {
        float4 acc = make_float4(0.f, 0.f, 0.f, 0.f);
        int e0 = g_off[row], e1 = g_off[row + 1];
        int e = e0;
        for (; e + 4 <= e1; e += 4) {
            int2 p0 = __ldg(&g_edge[e]);
            int2 p1 = __ldg(&g_edge[e + 1]);
            int2 p2 = __ldg(&g_edge[e + 2]);
            int2 p3 = __ldg(&g_edge[e + 3]);
            float4 v0 = t4[p0.x * 32 + lane];
            float4 v1 = t4[p1.x * 32 + lane];
            float4 v2 = t4[p2.x * 32 + lane];
            float4 v3 = t4[p3.x * 32 + lane];
            float w0 = __int_as_float(p0.y), w1 = __int_as_float(p1.y);
            float w2 = __int_as_float(p2.y), w3 = __int_as_float(p3.y);
            acc.x = fmaf(w0, v0.x, acc.x); acc.y = fmaf(w0, v0.y, acc.y);
            acc.z = fmaf(w0, v0.z, acc.z); acc.w = fmaf(w0, v0.w, acc.w);
            acc.x = fmaf(w1, v1.x, acc.x); acc.y = fmaf(w1, v1.y, acc.y);
            acc.z = fmaf(w1, v1.z, acc.z); acc.w = fmaf(w1, v1.w, acc.w);
            acc.x = fmaf(w2, v2.x, acc.x); acc.y = fmaf(w2, v2.y, acc.y);
            acc.z = fmaf(w2, v2.z, acc.z); acc.w = fmaf(w2, v2.w, acc.w);
            acc.x = fmaf(w3, v3.x, acc.x); acc.y = fmaf(w3, v3.y, acc.y);
            acc.z = fmaf(w3, v3.z, acc.z); acc.w = fmaf(w3, v3.w, acc.w);
        }
        for (; e < e1; e++) {
            int2 pp = __ldg(&g_edge[e]);
            float w = __int_as_float(pp.y);
            float4 v = t4[pp.x * 32 + lane];
            acc.x = fmaf(w, v.x, acc.x);
            acc.y = fmaf(w, v.y, acc.y);
            acc.z = fmaf(w, v.z, acc.z);
            acc.w = fmaf(w, v.w, acc.w);
        }
        float sw_ = g_selfw[row];
        float4 v = t4[row * 32 + lane];
        acc.x = fmaf(sw_, v.x, acc.x) + b4.x;
        acc.y = fmaf(sw_, v.y, acc.y) + b4.y;
        acc.z = fmaf(sw_, v.z, acc.z) + b4.z;
        acc.w = fmaf(sw_, v.w, acc.w) + b4.w;
        ((float4*)outh)[row * 32 + lane] = acc;
        ls0 += acc.x; ls1 += acc.y; ls2 += acc.z; ls3 += acc.w;
        lq0 += acc.x * acc.x; lq1 += acc.y * acc.y;
        lq2 += acc.z * acc.z; lq3 += acc.w * acc.w;
    }

    atomicAdd(&bsum[lane * 4 + 0], ls0); atomicAdd(&bsum[lane * 4 + 1], ls1);
    atomicAdd(&bsum[lane * 4 + 2], ls2); atomicAdd(&bsum[lane * 4 + 3], ls3);
    atomicAdd(&bsq[lane * 4 + 0], lq0);  atomicAdd(&bsq[lane * 4 + 1], lq1);
    atomicAdd(&bsq[lane * 4 + 2], lq2);  atomicAdd(&bsq[lane * 4 + 3], lq3);
    __syncthreads();
    if (tid < D) {
        int slot = (blockIdx.x & (NSLOT - 1)) * D + tid;
        atomicAdd(&g_psum[slot], bsum[tid]);
        atomicAdd(&g_psq[slot],  bsq[tid]);
    }
}

// reduce slots -> affine coeffs, then self-zero slots for the next layer
__global__ void k_stats(const float* __restrict__ gamma, const float* __restrict__ beta) {
    int f = threadIdx.x;
    if (f >= D) return;
    float s = 0.f, q = 0.f;
#pragma unroll
    for (int k = 0; k < NSLOT; k++) {
        s += g_psum[k * D + f];
        q += g_psq[k * D + f];
        g_psum[k * D + f] = 0.f;
        g_psq[k * D + f]  = 0.f;
    }
    float mu  = s / (float)NN;
    float var = q / (float)NN - mu * mu;
    float rstd = rsqrtf(var + EPSV);
    float sc = rstd * gamma[f];
    g_scale[f] = sc;
    g_shift[f] = beta[f] - mu * sc;
}

// ---------------- pooling (fused BN+ReLU of last layer) + MLP head ----------------
__global__ void k_pool(const float* __restrict__ h) {
    int g = blockIdx.x, f = threadIdx.x;
    int a = g_start[g], b = g_end[g];
    float sc = g_scale[f], sh = g_shift[f];
    float s0 = 0.f, s1 = 0.f, s2 = 0.f, s3 = 0.f;
    int i = a;
    for (; i + 4 <= b; i += 4) {
        s0 += fmaxf(fmaf(h[(i + 0) * D + f], sc, sh), 0.f);
        s1 += fmaxf(fmaf(h[(i + 1) * D + f], sc, sh), 0.f);
        s2 += fmaxf(fmaf(h[(i + 2) * D + f], sc, sh), 0.f);
        s3 += fmaxf(fmaf(h[(i + 3) * D + f], sc, sh), 0.f);
    }
    for (; i < b; i++) s0 += fmaxf(fmaf(h[i * D + f], sc, sh), 0.f);
    int c = b - a;
    g_Z[g * D + f] = ((s0 + s1) + (s2 + s3)) / (float)(c > 0 ? c : 1);
}

__global__ void k_head(const float* __restrict__ W1, const float* __restrict__ b1,
                       const float* __restrict__ W2, const float* __restrict__ b2,
                       float* __restrict__ out) {
    __shared__ float zs[D];
    __shared__ float red[4];
    int g = blockIdx.x, j = threadIdx.x;
    zs[j] = g_Z[g * D + j];
    __syncthreads();
    float acc = b1[j];
#pragma unroll 8
    for (int k = 0; k < D; k++) acc = fmaf(zs[k], W1[k * D + j], acc);
    float hz = fmaxf(acc, 0.f);
    float p = hz * W2[j];
#pragma unroll
    for (int o = 16; o; o >>= 1) p += __shfl_down_sync(0xffffffffu, p, o);
    if ((j & 31) == 0) red[j >> 5] = p;
    __syncthreads();
    if (j == 0) out[g] = red[0] + red[1] + red[2] + red[3] + b2[0];
}

// ---------------- launch ----------------
extern "C" void kernel_launch(void* const* d_in, const int* in_sizes, int n_in,
                              void* d_out, int out_size) {
    const float* x      = (const float*)d_in[0];
    const int*   ei     = (const int*)d_in[1];
    const int*   batch  = (const int*)d_in[2];
    const float* Ws     = (const float*)d_in[3];
    const float* bs     = (const float*)d_in[4];
    const float* gammas = (const float*)d_in[5];
    const float* betas  = (const float*)d_in[6];
    const float* W1     = (const float*)d_in[7];
    const float* b1     = (const float*)d_in[8];
    const float* W2     = (const float*)d_in[9];
    const float* b2     = (const float*)d_in[10];
    float* out = (float*)d_out;

    float *A, *B;
    __nv_bfloat16 *whi, *wlo;
    cudaGetSymbolAddress((void**)&A, g_bufA);
    cudaGetSymbolAddress((void**)&B, g_bufB);
    cudaGetSymbolAddress((void**)&whi, g_Whi);
    cudaGetSymbolAddress((void**)&wlo, g_Wlo);
    cudaFuncSetAttribute(k_gemm_mma, cudaFuncAttributeMaxDynamicSharedMemorySize, MMASMEM);

    const int NB_N = (NN + 255) / 256;   // 391
    const int NB_E = (NE + 255) / 256;   // 3125

    // ncu captures launch index 3: keep layer-0 GEMM there to verify this change.
    k_prepw<<<3 * D * D / 128, 128>>>(Ws);                              // 0
    k_zero_cnt<<<NB_N, 256>>>();                                        // 1
    k_count<<<NB_E, 256>>>(ei);                                         // 2
    k_gemm_mma<<<NTILE, 256, MMASMEM>>>(x, whi, wlo, B, 0);             // 3 <- profiled
    k_node<<<NB_N, 256>>>();                                            // 4
    k_part<<<SCAN_B, 256>>>();                                          // 5
    k_scanpart<<<1, 512>>>();                                           // 6
    k_offsets<<<SCAN_B, 256>>>();                                       // 7
    k_fill<<<NB_E, 256>>>(ei);                                          // 8
    k_bounds<<<NB_N, 256>>>(batch);                                     // 9

    for (int l = 0; l < 3; l++) {
        if (l > 0)
            k_gemm_mma<<<NTILE, 256, MMASMEM>>>(A, whi + l * D * D, wlo + l * D * D, B, 1);
        k_agg<<<2048, 256>>>(B, A, bs + l * D);
        k_stats<<<1, 128>>>(gammas + l * D, betas + l * D);
    }

    k_pool<<<NG, 128>>>(A);
    k_head<<<NG, 128>>>(W1, b1, W2, b2, out);
}

// round 8
// speedup vs baseline: 1.8198x; 1.1817x over previous
#include <cuda_runtime.h>
#include <cuda_bf16.h>
#include <cuda_fp16.h>
#include <cstdint>

#define NN 100000
#define NE 800000
#define NG 512
#define D  128
#define EPSV 1e-5f
#define NTILE 782            // ceil(NN/128)
#define SCAN_B 391           // ceil(NN/256)
#define NSLOT 32

// ---------------- scratch (static device globals; no allocations) ----------------
__device__ __half g_bufA[NN * D];
__device__ __half g_bufB[NN * D];
__device__ float  g_dinv[NN];
__device__ float  g_selfw[NN];
__device__ int    g_cnt[NN];
__device__ int    g_fill[NN];
__device__ int    g_off[NN + 1];
__device__ int2   g_edge[NE];        // (src, __float_as_int(w))
__device__ int    g_part[SCAN_B];
__device__ int    g_pbase[SCAN_B];
__device__ float  g_psum[NSLOT * D];
__device__ float  g_psq[NSLOT * D];
__device__ float  g_scale[D];
__device__ float  g_shift[D];
__device__ float  g_Z[NG * D];
__device__ int    g_start[NG];
__device__ int    g_end[NG];
__device__ __nv_bfloat16 g_Whi[3 * D * D];   // W^T per layer, [n][k]
__device__ __nv_bfloat16 g_Wlo[3 * D * D];

__device__ __forceinline__ int clampN(int v) {
    return v < 0 ? 0 : (v >= NN ? NN - 1 : v);
}

__device__ __forceinline__ uint32_t smem_u32(const void* p) {
    uint32_t a;
    asm("{ .reg .u64 t; cvta.to.shared.u64 t, %1; cvt.u32.u64 %0, t; }" : "=r"(a) : "l"(p));
    return a;
}

// XOR swizzle for 256B rows
__device__ __forceinline__ uint32_t sw(uint32_t off) {
    return off ^ ((off >> 4) & 0x70);
}

__device__ __forceinline__ void ldm_x4(uint32_t* r, uint32_t addr) {
    asm volatile("ldmatrix.sync.aligned.m8n8.x4.shared.b16 {%0,%1,%2,%3}, [%4];"
                 : "=r"(r[0]), "=r"(r[1]), "=r"(r[2]), "=r"(r[3]) : "r"(addr));
}

__device__ __forceinline__ void mma_bf16(float* c, const uint32_t* a, uint32_t b0, uint32_t b1) {
    asm volatile(
        "mma.sync.aligned.m16n8k16.row.col.f32.bf16.bf16.f32 "
        "{%0,%1,%2,%3}, {%4,%5,%6,%7}, {%8,%9}, {%0,%1,%2,%3};"
        : "+f"(c[0]), "+f"(c[1]), "+f"(c[2]), "+f"(c[3])
        : "r"(a[0]), "r"(a[1]), "r"(a[2]), "r"(a[3]), "r"(b0), "r"(b1));
}

// split fp32 pair into bf16x2 hi + lo packed regs
__device__ __forceinline__ void split2(float2 v, uint32_t& hi, uint32_t& lo) {
    __nv_bfloat162 h = __float22bfloat162_rn(v);
    __nv_bfloat162 l = __float22bfloat162_rn(make_float2(
        v.x - __bfloat162float(h.x), v.y - __bfloat162float(h.y)));
    hi = *(uint32_t*)&h;
    lo = *(uint32_t*)&l;
}

// typed pair loader (index in units of 2 elements from row base)
__device__ __forceinline__ float2 load_pair(const float* base, int idx) {
    return __ldg((const float2*)base + idx);
}
__device__ __forceinline__ float2 load_pair(const __half* base, int idx) {
    return __half22float2(__ldg((const __half2*)base + idx));
}

// ---------------- graph preprocessing ----------------
__global__ void k_zero_cnt() {
    int i = blockIdx.x * blockDim.x + threadIdx.x;
    if (i < NN) g_cnt[i] = 0;
}

__global__ void k_count(const int* __restrict__ ei) {
    int e = blockIdx.x * blockDim.x + threadIdx.x;
    if (e < NE) atomicAdd(&g_cnt[clampN(ei[NE + e])], 1);
}

__global__ void k_node() {
    int i = blockIdx.x * blockDim.x + threadIdx.x;
    if (i < NN) {
        float deg = (float)g_cnt[i] + 1.0f;
        g_dinv[i]  = rsqrtf(deg);
        g_selfw[i] = 1.0f / deg;
        g_fill[i]  = 0;
    }
    if (i < NG) { g_start[i] = 0; g_end[i] = 0; }
    if (i < NSLOT * D) { g_psum[i] = 0.f; g_psq[i] = 0.f; }
}

__global__ void k_part() {
    __shared__ int s[256];
    int t = threadIdx.x;
    int i = blockIdx.x * 256 + t;
    int v = (i < NN) ? g_cnt[i] : 0;
    s[t] = v; __syncthreads();
    for (int o = 128; o; o >>= 1) { if (t < o) s[t] += s[t + o]; __syncthreads(); }
    if (t == 0) g_part[blockIdx.x] = s[0];
}

__global__ void k_scanpart() {
    __shared__ int s[512];
    int t = threadIdx.x;
    int v = (t < SCAN_B) ? g_part[t] : 0;
    s[t] = v; __syncthreads();
    for (int d = 1; d < 512; d <<= 1) {
        int x = (t >= d) ? s[t - d] : 0;
        __syncthreads();
        s[t] += x;
        __syncthreads();
    }
    if (t < SCAN_B) g_pbase[t] = s[t] - v;
    if (t == SCAN_B - 1) g_off[NN] = s[t];
}

__global__ void k_offsets() {
    __shared__ int s[256];
    int t = threadIdx.x;
    int i = blockIdx.x * 256 + t;
    int v = (i < NN) ? g_cnt[i] : 0;
    s[t] = v; __syncthreads();
    for (int d = 1; d < 256; d <<= 1) {
        int x = (t >= d) ? s[t - d] : 0;
        __syncthreads();
        s[t] += x;
        __syncthreads();
    }
    if (i < NN) g_off[i] = g_pbase[blockIdx.x] + s[t] - v;
}

__global__ void k_fill(const int* __restrict__ ei) {
    int e = blockIdx.x * blockDim.x + threadIdx.x;
    if (e >= NE) return;
    int s = clampN(ei[e]);
    int d = clampN(ei[NE + e]);
    int p = g_off[d] + atomicAdd(&g_fill[d], 1);
    g_edge[p] = make_int2(s, __float_as_int(g_dinv[s] * g_dinv[d]));
}

__global__ void k_bounds(const int* __restrict__ batch) {
    int i = blockIdx.x * blockDim.x + threadIdx.x;
    if (i >= NN) return;
    int b = batch[i];
    if (b < 0) b = 0; if (b >= NG) b = NG - 1;
    int bp = (i == 0) ? -1 : batch[i - 1];
    int bn = (i == NN - 1) ? -1 : batch[i + 1];
    if (i == 0      || bp != b) g_start[b] = i;
    if (i == NN - 1 || bn != b) g_end[b]   = i + 1;
}

// W^T + hi/lo bf16 decomposition: g_W*[l][n][k] = split(W[l][k][n])
__global__ void k_prepw(const float* __restrict__ Ws) {
    int idx = blockIdx.x * 128 + threadIdx.x;       // 3*128*128 total
    int l = idx >> 14, rem = idx & 16383;
    int n = rem >> 7, k = rem & 127;
    float w = Ws[l * 16384 + k * 128 + n];
    __nv_bfloat16 hi = __float2bfloat16_rn(w);
    __nv_bfloat16 lo = __float2bfloat16_rn(w - __bfloat162float(hi));
    g_Whi[idx] = hi;
    g_Wlo[idx] = lo;
}

// ---------------- HMMA GEMM: out[N,128] = bnrelu(in)[N,128] @ W ----------------
// smem: only W^T hi/lo (2 x 32KB). A fragments loaded per-lane from global.
#define S_WH 0
#define S_WL 32768
#define MMASMEM 65536

template <typename T>
__global__ __launch_bounds__(256) void k_gemm_mma(const T* __restrict__ in,
                                                  const __nv_bfloat16* __restrict__ Whi,
                                                  const __nv_bfloat16* __restrict__ Wlo,
                                                  __half* __restrict__ out,
                                                  int apply) {
    extern __shared__ char smc[];
    uint32_t sb = smem_u32(smc);
    int tid = threadIdx.x, wid = tid >> 5, lane = tid & 31;
    int row0 = blockIdx.x * 128;

    // ---- stage W^T hi/lo
    {
        int n = tid >> 1, half = tid & 1;
        const uint4* src_h = (const uint4*)(Whi) + n * 16 + half * 8;
        const uint4* src_l = (const uint4*)(Wlo) + n * 16 + half * 8;
        uint32_t base = n * 256 + half * 128;
#pragma unroll
        for (int c = 0; c < 8; c++) {
            uint32_t o = sw(base + c * 16);
            *(uint4*)(smc + S_WH + o) = __ldg(&src_h[c]);
            *(uint4*)(smc + S_WL + o) = __ldg(&src_l[c]);
        }
    }

    // ---- A fragments: direct per-lane global loads + BN/ReLU + hi/lo split
    int groupID = lane >> 2, tig = lane & 3;
    int r0 = row0 + wid * 16 + groupID;
    int r1 = r0 + 8;
    bool ok0 = r0 < NN, ok1 = r1 < NN;
    const T* b0p = in + (size_t)r0 * D;
    const T* b1p = in + (size_t)r1 * D;

    uint32_t afh[8][4], afl[8][4];
#pragma unroll
    for (int k = 0; k < 8; k++) {
        float2 a0 = ok0 ? load_pair(b0p, tig + k * 8)     : make_float2(0.f, 0.f);
        float2 a1 = ok1 ? load_pair(b1p, tig + k * 8)     : make_float2(0.f, 0.f);
        float2 a2 = ok0 ? load_pair(b0p, tig + k * 8 + 4) : make_float2(0.f, 0.f);
        float2 a3 = ok1 ? load_pair(b1p, tig + k * 8 + 4) : make_float2(0.f, 0.f);
        if (apply) {
            float2 s0 = ((const float2*)g_scale)[tig + k * 8];
            float2 h0 = ((const float2*)g_shift)[tig + k * 8];
            float2 s1 = ((const float2*)g_scale)[tig + k * 8 + 4];
            float2 h1 = ((const float2*)g_shift)[tig + k * 8 + 4];
            a0.x = fmaxf(fmaf(a0.x, s0.x, h0.x), 0.f);
            a0.y = fmaxf(fmaf(a0.y, s0.y, h0.y), 0.f);
            a1.x = fmaxf(fmaf(a1.x, s0.x, h0.x), 0.f);
            a1.y = fmaxf(fmaf(a1.y, s0.y, h0.y), 0.f);
            a2.x = fmaxf(fmaf(a2.x, s1.x, h1.x), 0.f);
            a2.y = fmaxf(fmaf(a2.y, s1.y, h1.y), 0.f);
            a3.x = fmaxf(fmaf(a3.x, s1.x, h1.x), 0.f);
            a3.y = fmaxf(fmaf(a3.y, s1.y, h1.y), 0.f);
        }
        split2(a0, afh[k][0], afl[k][0]);
        split2(a1, afh[k][1], afl[k][1]);
        split2(a2, afh[k][2], afl[k][2]);
        split2(a3, afh[k][3], afl[k][3]);
    }
    __syncthreads();   // W staged

    uint32_t b_base = ((lane & 7) + ((lane >> 4) << 3)) * 256 + (((lane >> 3) & 1) * 8) * 2;
    int col_t = tig * 2;

#pragma unroll 2
    for (int np = 0; np < 8; np++) {
        float ce[4] = {0.f, 0.f, 0.f, 0.f};
        float co[4] = {0.f, 0.f, 0.f, 0.f};
#pragma unroll
        for (int k = 0; k < 8; k++) {
            uint32_t bh[4], bl[4];
            uint32_t o = sw(b_base + np * 4096 + k * 32);
            ldm_x4(bh, sb + S_WH + o);
            ldm_x4(bl, sb + S_WL + o);
            mma_bf16(ce, afh[k], bh[0], bh[1]);
            mma_bf16(co, afh[k], bh[2], bh[3]);
            mma_bf16(ce, afh[k], bl[0], bl[1]);
            mma_bf16(co, afh[k], bl[2], bl[3]);
            mma_bf16(ce, afl[k], bh[0], bh[1]);
            mma_bf16(co, afl[k], bh[2], bh[3]);
        }
        int nb = np * 16;
        if (ok0) {
            *(__half2*)(out + (size_t)r0 * D + nb + col_t)     = __floats2half2_rn(ce[0], ce[1]);
            *(__half2*)(out + (size_t)r0 * D + nb + 8 + col_t) = __floats2half2_rn(co[0], co[1]);
        }
        if (ok1) {
            *(__half2*)(out + (size_t)r1 * D + nb + col_t)     = __floats2half2_rn(ce[2], ce[3]);
            *(__half2*)(out + (size_t)r1 * D + nb + 8 + col_t) = __floats2half2_rn(co[2], co[3]);
        }
    }
}

// ---------------- aggregation (gather, CSR) + bias + fused BN stats ----------------
__device__ __forceinline__ float4 h4_to_f4(uint2 raw) {
    __half2 a = *(__half2*)&raw.x;
    __half2 b = *(__half2*)&raw.y;
    float2 fa = __half22float2(a), fb = __half22float2(b);
    return make_float4(fa.x, fa.y, fb.x, fb.y);
}

__global__ __launch_bounds__(256) void k_agg(const __half* __restrict__ tmp,
                                             __half* __restrict__ outh,
                                             const float* __restrict__ bias) {
    __shared__ float bsum[D];
    __shared__ float bsq[D];
    int tid = threadIdx.x;
    if (tid < D) { bsum[tid] = 0.f; bsq[tid] = 0.f; }
    __syncthreads();

    int lane = tid & 31, wid = tid >> 5;
    const uint2* t2 = (const uint2*)tmp;       // 4 halfs per uint2, 32 per row
    float4 b4 = ((const float4*)bias)[lane];
    float ls0 = 0, ls1 = 0, ls2 = 0, ls3 = 0;
    float lq0 = 0, lq1 = 0, lq2 = 0, lq3 = 0;

    for (int row = blockIdx.x * 8 + wid; row < NN; row += gridDim.x * 8) {
        float4 acc = make_float4(0.f, 0.f, 0.f, 0.f);
        int e0 = g_off[row], e1 = g_off[row + 1];
        int e = e0;
        for (; e + 4 <= e1; e += 4) {
            int2 p0 = __ldg(&g_edge[e]);
            int2 p1 = __ldg(&g_edge[e + 1]);
            int2 p2 = __ldg(&g_edge[e + 2]);
            int2 p3 = __ldg(&g_edge[e + 3]);
            float4 v0 = h4_to_f4(__ldg(&t2[p0.x * 32 + lane]));
            float4 v1 = h4_to_f4(__ldg(&t2[p1.x * 32 + lane]));
            float4 v2 = h4_to_f4(__ldg(&t2[p2.x * 32 + lane]));
            float4 v3 = h4_to_f4(__ldg(&t2[p3.x * 32 + lane]));
            float w0 = __int_as_float(p0.y), w1 = __int_as_float(p1.y);
            float w2 = __int_as_float(p2.y), w3 = __int_as_float(p3.y);
            acc.x = fmaf(w0, v0.x, acc.x); acc.y = fmaf(w0, v0.y, acc.y);
            acc.z = fmaf(w0, v0.z, acc.z); acc.w = fmaf(w0, v0.w, acc.w);
            acc.x = fmaf(w1, v1.x, acc.x); acc.y = fmaf(w1, v1.y, acc.y);
            acc.z = fmaf(w1, v1.z, acc.z); acc.w = fmaf(w1, v1.w, acc.w);
            acc.x = fmaf(w2, v2.x, acc.x); acc.y = fmaf(w2, v2.y, acc.y);
            acc.z = fmaf(w2, v2.z, acc.z); acc.w = fmaf(w2, v2.w, acc.w);
            acc.x = fmaf(w3, v3.x, acc.x); acc.y = fmaf(w3, v3.y, acc.y);
            acc.z = fmaf(w3, v3.z, acc.z); acc.w = fmaf(w3, v3.w, acc.w);
        }
        for (; e < e1; e++) {
            int2 pp = __ldg(&g_edge[e]);
            float w = __int_as_float(pp.y);
            float4 v = h4_to_f4(__ldg(&t2[pp.x * 32 + lane]));
            acc.x = fmaf(w, v.x, acc.x);
            acc.y = fmaf(w, v.y, acc.y);
            acc.z = fmaf(w, v.z, acc.z);
            acc.w = fmaf(w, v.w, acc.w);
        }
        float sw_ = g_selfw[row];
        float4 v = h4_to_f4(__ldg(&t2[row * 32 + lane]));
        acc.x = fmaf(sw_, v.x, acc.x) + b4.x;
        acc.y = fmaf(sw_, v.y, acc.y) + b4.y;
        acc.z = fmaf(sw_, v.z, acc.z) + b4.z;
        acc.w = fmaf(sw_, v.w, acc.w) + b4.w;
        uint2 packed;
        *(__half2*)&packed.x = __floats2half2_rn(acc.x, acc.y);
        *(__half2*)&packed.y = __floats2half2_rn(acc.z, acc.w);
        ((uint2*)outh)[row * 32 + lane] = packed;
        ls0 += acc.x; ls1 += acc.y; ls2 += acc.z; ls3 += acc.w;
        lq0 += acc.x * acc.x; lq1 += acc.y * acc.y;
        lq2 += acc.z * acc.z; lq3 += acc.w * acc.w;
    }

    atomicAdd(&bsum[lane * 4 + 0], ls0); atomicAdd(&bsum[lane * 4 + 1], ls1);
    atomicAdd(&bsum[lane * 4 + 2], ls2); atomicAdd(&bsum[lane * 4 + 3], ls3);
    atomicAdd(&bsq[lane * 4 + 0], lq0);  atomicAdd(&bsq[lane * 4 + 1], lq1);
    atomicAdd(&bsq[lane * 4 + 2], lq2);  atomicAdd(&bsq[lane * 4 + 3], lq3);
    __syncthreads();
    if (tid < D) {
        int slot = (blockIdx.x & (NSLOT - 1)) * D + tid;
        atomicAdd(&g_psum[slot], bsum[tid]);
        atomicAdd(&g_psq[slot],  bsq[tid]);
    }
}

// reduce slots -> affine coeffs, then self-zero slots for the next layer
__global__ void k_stats(const float* __restrict__ gamma, const float* __restrict__ beta) {
    int f = threadIdx.x;
    if (f >= D) return;
    float s = 0.f, q = 0.f;
#pragma unroll
    for (int k = 0; k < NSLOT; k++) {
        s += g_psum[k * D + f];
        q += g_psq[k * D + f];
        g_psum[k * D + f] = 0.f;
        g_psq[k * D + f]  = 0.f;
    }
    float mu  = s / (float)NN;
    float var = q / (float)NN - mu * mu;
    float rstd = rsqrtf(var + EPSV);
    float sc = rstd * gamma[f];
    g_scale[f] = sc;
    g_shift[f] = beta[f] - mu * sc;
}

// ---------------- pooling (fused BN+ReLU of last layer) + MLP head ----------------
__global__ void k_pool(const __half* __restrict__ h) {
    int g = blockIdx.x, f = threadIdx.x;
    int a = g_start[g], b = g_end[g];
    float sc = g_scale[f], sh = g_shift[f];
    float s0 = 0.f, s1 = 0.f, s2 = 0.f, s3 = 0.f;
    int i = a;
    for (; i + 4 <= b; i += 4) {
        s0 += fmaxf(fmaf(__half2float(h[(i + 0) * D + f]), sc, sh), 0.f);
        s1 += fmaxf(fmaf(__half2float(h[(i + 1) * D + f]), sc, sh), 0.f);
        s2 += fmaxf(fmaf(__half2float(h[(i + 2) * D + f]), sc, sh), 0.f);
        s3 += fmaxf(fmaf(__half2float(h[(i + 3) * D + f]), sc, sh), 0.f);
    }
    for (; i < b; i++) s0 += fmaxf(fmaf(__half2float(h[i * D + f]), sc, sh), 0.f);
    int c = b - a;
    g_Z[g * D + f] = ((s0 + s1) + (s2 + s3)) / (float)(c > 0 ? c : 1);
}

__global__ void k_head(const float* __restrict__ W1, const float* __restrict__ b1,
                       const float* __restrict__ W2, const float* __restrict__ b2,
                       float* __restrict__ out) {
    __shared__ float zs[D];
    __shared__ float red[4];
    int g = blockIdx.x, j = threadIdx.x;
    zs[j] = g_Z[g * D + j];
    __syncthreads();
    float acc = b1[j];
#pragma unroll 8
    for (int k = 0; k < D; k++) acc = fmaf(zs[k], W1[k * D + j], acc);
    float hz = fmaxf(acc, 0.f);
    float p = hz * W2[j];
#pragma unroll
    for (int o = 16; o; o >>= 1) p += __shfl_down_sync(0xffffffffu, p, o);
    if ((j & 31) == 0) red[j >> 5] = p;
    __syncthreads();
    if (j == 0) out[g] = red[0] + red[1] + red[2] + red[3] + b2[0];
}

// ---------------- launch ----------------
extern "C" void kernel_launch(void* const* d_in, const int* in_sizes, int n_in,
                              void* d_out, int out_size) {
    const float* x      = (const float*)d_in[0];
    const int*   ei     = (const int*)d_in[1];
    const int*   batch  = (const int*)d_in[2];
    const float* Ws     = (const float*)d_in[3];
    const float* bs     = (const float*)d_in[4];
    const float* gammas = (const float*)d_in[5];
    const float* betas  = (const float*)d_in[6];
    const float* W1     = (const float*)d_in[7];
    const float* b1     = (const float*)d_in[8];
    const float* W2     = (const float*)d_in[9];
    const float* b2     = (const float*)d_in[10];
    float* out = (float*)d_out;

    __half *A, *B;
    __nv_bfloat16 *whi, *wlo;
    cudaGetSymbolAddress((void**)&A, g_bufA);
    cudaGetSymbolAddress((void**)&B, g_bufB);
    cudaGetSymbolAddress((void**)&whi, g_Whi);
    cudaGetSymbolAddress((void**)&wlo, g_Wlo);
    cudaFuncSetAttribute(k_gemm_mma<float>,  cudaFuncAttributeMaxDynamicSharedMemorySize, MMASMEM);
    cudaFuncSetAttribute(k_gemm_mma<__half>, cudaFuncAttributeMaxDynamicSharedMemorySize, MMASMEM);

    const int NB_N = (NN + 255) / 256;   // 391
    const int NB_E = (NE + 255) / 256;   // 3125

    // ncu captures launch index 3: keep layer-0 GEMM there.
    k_prepw<<<3 * D * D / 128, 128>>>(Ws);                                 // 0
    k_zero_cnt<<<NB_N, 256>>>();                                           // 1
    k_count<<<NB_E, 256>>>(ei);                                            // 2
    k_gemm_mma<float><<<NTILE, 256, MMASMEM>>>(x, whi, wlo, B, 0);         // 3 <- profiled
    k_node<<<NB_N, 256>>>();                                               // 4
    k_part<<<SCAN_B, 256>>>();                                             // 5
    k_scanpart<<<1, 512>>>();                                              // 6
    k_offsets<<<SCAN_B, 256>>>();                                          // 7
    k_fill<<<NB_E, 256>>>(ei);                                             // 8
    k_bounds<<<NB_N, 256>>>(batch);                                        // 9

    for (int l = 0; l < 3; l++) {
        if (l > 0)
            k_gemm_mma<__half><<<NTILE, 256, MMASMEM>>>(A, whi + l * D * D, wlo + l * D * D, B, 1);
        k_agg<<<2048, 256>>>(B, A, bs + l * D);
        k_stats<<<1, 128>>>(gammas + l * D, betas + l * D);
    }

    k_pool<<<NG, 128>>>(A);
    k_head<<<NG, 128>>>(W1, b1, W2, b2, out);
}

// round 9
// speedup vs baseline: 2.0393x; 1.1206x over previous
#include <cuda_runtime.h>
#include <cuda_fp16.h>
#include <cstdint>

#define NN 100000
#define NE 800000
#define NG 512
#define D  128
#define EPSV 1e-5f
#define NT2 391              // ceil(NN/256)
#define SCAN_B 391           // ceil(NN/256)
#define NSLOT 32
#define LO_SCALE 512.0f
#define LO_INV (1.0f / 512.0f)

// ---------------- scratch (static device globals; no allocations) ----------------
__device__ __half g_bufA[NN * D];
__device__ __half g_bufB[NN * D];
__device__ float  g_dinv[NN];
__device__ float  g_selfw[NN];
__device__ int    g_cnt[NN];
__device__ int    g_fill[NN];
__device__ int    g_off[NN + 1];
__device__ int2   g_edge[NE];        // (src, __float_as_int(w))
__device__ int    g_part[SCAN_B];
__device__ int    g_pbase[SCAN_B];
__device__ float  g_psum[NSLOT * D];
__device__ float  g_psq[NSLOT * D];
__device__ float  g_scale[D];
__device__ float  g_shift[D];
__device__ float  g_Z[NG * D];
__device__ int    g_start[NG];
__device__ int    g_end[NG];
__device__ __half g_Wh16[3 * D * D];   // W^T per layer, [n][k], fp16 hi
__device__ __half g_Wl16[3 * D * D];   // (W - hi) * 512 in fp16

__device__ __forceinline__ int clampN(int v) {
    return v < 0 ? 0 : (v >= NN ? NN - 1 : v);
}

__device__ __forceinline__ uint32_t smem_u32(const void* p) {
    uint32_t a;
    asm("{ .reg .u64 t; cvta.to.shared.u64 t, %1; cvt.u32.u64 %0, t; }" : "=r"(a) : "l"(p));
    return a;
}

// XOR swizzle for 256B rows
__device__ __forceinline__ uint32_t sw(uint32_t off) {
    return off ^ ((off >> 4) & 0x70);
}

__device__ __forceinline__ void ldm_x4(uint32_t* r, uint32_t addr) {
    asm volatile("ldmatrix.sync.aligned.m8n8.x4.shared.b16 {%0,%1,%2,%3}, [%4];"
                 : "=r"(r[0]), "=r"(r[1]), "=r"(r[2]), "=r"(r[3]) : "r"(addr));
}

__device__ __forceinline__ void mma_f16(float* c, const uint32_t* a, uint32_t b0, uint32_t b1) {
    asm volatile(
        "mma.sync.aligned.m16n8k16.row.col.f32.f16.f16.f32 "
        "{%0,%1,%2,%3}, {%4,%5,%6,%7}, {%8,%9}, {%0,%1,%2,%3};"
        : "+f"(c[0]), "+f"(c[1]), "+f"(c[2]), "+f"(c[3])
        : "r"(a[0]), "r"(a[1]), "r"(a[2]), "r"(a[3]), "r"(b0), "r"(b1));
}

// ---------------- graph preprocessing ----------------
__global__ void k_zero_cnt() {
    int i = blockIdx.x * blockDim.x + threadIdx.x;
    if (i < NN) g_cnt[i] = 0;
}

__global__ void k_count(const int* __restrict__ ei) {
    int e = blockIdx.x * blockDim.x + threadIdx.x;
    if (e < NE) atomicAdd(&g_cnt[clampN(ei[NE + e])], 1);
}

__global__ void k_node() {
    int i = blockIdx.x * blockDim.x + threadIdx.x;
    if (i < NN) {
        float deg = (float)g_cnt[i] + 1.0f;
        g_dinv[i]  = rsqrtf(deg);
        g_selfw[i] = 1.0f / deg;
        g_fill[i]  = 0;
    }
    if (i < NG) { g_start[i] = 0; g_end[i] = 0; }
    if (i < NSLOT * D) { g_psum[i] = 0.f; g_psq[i] = 0.f; }
}

__global__ void k_part() {
    __shared__ int s[256];
    int t = threadIdx.x;
    int i = blockIdx.x * 256 + t;
    int v = (i < NN) ? g_cnt[i] : 0;
    s[t] = v; __syncthreads();
    for (int o = 128; o; o >>= 1) { if (t < o) s[t] += s[t + o]; __syncthreads(); }
    if (t == 0) g_part[blockIdx.x] = s[0];
}

__global__ void k_scanpart() {
    __shared__ int s[512];
    int t = threadIdx.x;
    int v = (t < SCAN_B) ? g_part[t] : 0;
    s[t] = v; __syncthreads();
    for (int d = 1; d < 512; d <<= 1) {
        int x = (t >= d) ? s[t - d] : 0;
        __syncthreads();
        s[t] += x;
        __syncthreads();
    }
    if (t < SCAN_B) g_pbase[t] = s[t] - v;
    if (t == SCAN_B - 1) g_off[NN] = s[t];
}

__global__ void k_offsets() {
    __shared__ int s[256];
    int t = threadIdx.x;
    int i = blockIdx.x * 256 + t;
    int v = (i < NN) ? g_cnt[i] : 0;
    s[t] = v; __syncthreads();
    for (int d = 1; d < 256; d <<= 1) {
        int x = (t >= d) ? s[t - d] : 0;
        __syncthreads();
        s[t] += x;
        __syncthreads();
    }
    if (i < NN) g_off[i] = g_pbase[blockIdx.x] + s[t] - v;
}

__global__ void k_fill(const int* __restrict__ ei) {
    int e = blockIdx.x * blockDim.x + threadIdx.x;
    if (e >= NE) return;
    int s = clampN(ei[e]);
    int d = clampN(ei[NE + e]);
    int p = g_off[d] + atomicAdd(&g_fill[d], 1);
    g_edge[p] = make_int2(s, __float_as_int(g_dinv[s] * g_dinv[d]));
}

__global__ void k_bounds(const int* __restrict__ batch) {
    int i = blockIdx.x * blockDim.x + threadIdx.x;
    if (i >= NN) return;
    int b = batch[i];
    if (b < 0) b = 0; if (b >= NG) b = NG - 1;
    int bp = (i == 0) ? -1 : batch[i - 1];
    int bn = (i == NN - 1) ? -1 : batch[i + 1];
    if (i == 0      || bp != b) g_start[b] = i;
    if (i == NN - 1 || bn != b) g_end[b]   = i + 1;
}

// W^T + fp16 hi/lo decomposition: g_W*[l][n][k] = split(W[l][k][n])
__global__ void k_prepw(const float* __restrict__ Ws) {
    int idx = blockIdx.x * 128 + threadIdx.x;       // 3*128*128 total
    int l = idx >> 14, rem = idx & 16383;
    int n = rem >> 7, k = rem & 127;
    float w = Ws[l * 16384 + k * 128 + n];
    __half hi = __float2half_rn(w);
    float lo = (w - __half2float(hi)) * LO_SCALE;
    g_Wh16[idx] = hi;
    g_Wl16[idx] = __float2half_rn(lo);
}

// x (fp32) -> fp16 buffer
__global__ void k_convx(const float* __restrict__ x, __half* __restrict__ o) {
    int i = blockIdx.x * blockDim.x + threadIdx.x;   // float4 index
    if (i >= NN * 32) return;
    float4 v = __ldg((const float4*)x + i);
    uint2 p;
    *(__half2*)&p.x = __floats2half2_rn(v.x, v.y);
    *(__half2*)&p.y = __floats2half2_rn(v.z, v.w);
    ((uint2*)o)[i] = p;
}

// ---------------- fp16 HMMA GEMM: out[N,128] = bnrelu(in)[N,128] @ W ----------------
// Tile M=256 (8 warps x 32 rows). smem: W^T hi/lo (2 x 32KB). 2-term W split.
#define S_WH 0
#define S_WL 32768
#define MMASMEM 65536

__global__ __launch_bounds__(256) void k_gemm16(const __half* __restrict__ in,
                                                const __half* __restrict__ Wh,
                                                const __half* __restrict__ Wl,
                                                __half* __restrict__ out,
                                                int apply) {
    extern __shared__ char smc[];
    uint32_t sb = smem_u32(smc);
    int tid = threadIdx.x, wid = tid >> 5, lane = tid & 31;
    int row0 = blockIdx.x * 256;

    // ---- stage W^T hi/lo
    {
        int n = tid >> 1, hf = tid & 1;
        const uint4* src_h = (const uint4*)(Wh) + n * 16 + hf * 8;
        const uint4* src_l = (const uint4*)(Wl) + n * 16 + hf * 8;
        uint32_t base = n * 256 + hf * 128;
#pragma unroll
        for (int c = 0; c < 8; c++) {
            uint32_t o = sw(base + c * 16);
            *(uint4*)(smc + S_WH + o) = __ldg(&src_h[c]);
            *(uint4*)(smc + S_WL + o) = __ldg(&src_l[c]);
        }
    }

    // ---- A fragments: 2 sets of 16 rows, direct fp16 global loads (+BN/ReLU)
    int groupID = lane >> 2, tig = lane & 3;
    int rb = row0 + wid * 32;
    uint32_t af[2][8][4];
    bool okr[2][2];
#pragma unroll
    for (int s = 0; s < 2; s++) {
        int r0 = rb + s * 16 + groupID;
        int r1 = r0 + 8;
        okr[s][0] = r0 < NN; okr[s][1] = r1 < NN;
        const __half2* hp0 = (const __half2*)(in + (size_t)r0 * D);
        const __half2* hp1 = (const __half2*)(in + (size_t)r1 * D);
#pragma unroll
        for (int k = 0; k < 8; k++) {
            __half2 z = __floats2half2_rn(0.f, 0.f);
            __half2 a0 = okr[s][0] ? __ldg(&hp0[tig + k * 8])     : z;
            __half2 a1 = okr[s][1] ? __ldg(&hp1[tig + k * 8])     : z;
            __half2 a2 = okr[s][0] ? __ldg(&hp0[tig + k * 8 + 4]) : z;
            __half2 a3 = okr[s][1] ? __ldg(&hp1[tig + k * 8 + 4]) : z;
            if (apply) {
                float2 s0 = ((const float2*)g_scale)[tig + k * 8];
                float2 h0 = ((const float2*)g_shift)[tig + k * 8];
                float2 s1 = ((const float2*)g_scale)[tig + k * 8 + 4];
                float2 h1 = ((const float2*)g_shift)[tig + k * 8 + 4];
                float2 f0 = __half22float2(a0), f1 = __half22float2(a1);
                float2 f2 = __half22float2(a2), f3 = __half22float2(a3);
                a0 = __floats2half2_rn(fmaxf(fmaf(f0.x, s0.x, h0.x), 0.f),
                                       fmaxf(fmaf(f0.y, s0.y, h0.y), 0.f));
                a1 = __floats2half2_rn(fmaxf(fmaf(f1.x, s0.x, h0.x), 0.f),
                                       fmaxf(fmaf(f1.y, s0.y, h0.y), 0.f));
                a2 = __floats2half2_rn(fmaxf(fmaf(f2.x, s1.x, h1.x), 0.f),
                                       fmaxf(fmaf(f2.y, s1.y, h1.y), 0.f));
                a3 = __floats2half2_rn(fmaxf(fmaf(f3.x, s1.x, h1.x), 0.f),
                                       fmaxf(fmaf(f3.y, s1.y, h1.y), 0.f));
            }
            af[s][k][0] = *(uint32_t*)&a0;
            af[s][k][1] = *(uint32_t*)&a1;
            af[s][k][2] = *(uint32_t*)&a2;
            af[s][k][3] = *(uint32_t*)&a3;
        }
    }
    __syncthreads();   // W staged

    uint32_t b_base = ((lane & 7) + ((lane >> 4) << 3)) * 256 + (((lane >> 3) & 1) * 8) * 2;
    int col_t = tig * 2;

#pragma unroll 1
    for (int np = 0; np < 8; np++) {
        float eh0[4] = {0,0,0,0}, oh0[4] = {0,0,0,0};
        float el0[4] = {0,0,0,0}, ol0[4] = {0,0,0,0};
        float eh1[4] = {0,0,0,0}, oh1[4] = {0,0,0,0};
        float el1[4] = {0,0,0,0}, ol1[4] = {0,0,0,0};
#pragma unroll
        for (int k = 0; k < 8; k++) {
            uint32_t bh[4], bl[4];
            uint32_t o = sw(b_base + np * 4096 + k * 32);
            ldm_x4(bh, sb + S_WH + o);
            ldm_x4(bl, sb + S_WL + o);
            mma_f16(eh0, af[0][k], bh[0], bh[1]);
            mma_f16(oh0, af[0][k], bh[2], bh[3]);
            mma_f16(el0, af[0][k], bl[0], bl[1]);
            mma_f16(ol0, af[0][k], bl[2], bl[3]);
            mma_f16(eh1, af[1][k], bh[0], bh[1]);
            mma_f16(oh1, af[1][k], bh[2], bh[3]);
            mma_f16(el1, af[1][k], bl[0], bl[1]);
            mma_f16(ol1, af[1][k], bl[2], bl[3]);
        }
        int nb = np * 16;
#pragma unroll
        for (int s = 0; s < 2; s++) {
            float* eh = s ? eh1 : eh0; float* oh = s ? oh1 : oh0;
            float* el = s ? el1 : el0; float* ol = s ? ol1 : ol0;
            int r0 = rb + s * 16 + groupID;
            int r1 = r0 + 8;
            if (okr[s][0]) {
                *(__half2*)(out + (size_t)r0 * D + nb + col_t) =
                    __floats2half2_rn(fmaf(el[0], LO_INV, eh[0]), fmaf(el[1], LO_INV, eh[1]));
                *(__half2*)(out + (size_t)r0 * D + nb + 8 + col_t) =
                    __floats2half2_rn(fmaf(ol[0], LO_INV, oh[0]), fmaf(ol[1], LO_INV, oh[1]));
            }
            if (okr[s][1]) {
                *(__half2*)(out + (size_t)r1 * D + nb + col_t) =
                    __floats2half2_rn(fmaf(el[2], LO_INV, eh[2]), fmaf(el[3], LO_INV, eh[3]));
                *(__half2*)(out + (size_t)r1 * D + nb + 8 + col_t) =
                    __floats2half2_rn(fmaf(ol[2], LO_INV, oh[2]), fmaf(ol[3], LO_INV, oh[3]));
            }
        }
    }
}

// ---------------- aggregation (gather, CSR) + bias + fused BN stats ----------------
__device__ __forceinline__ float4 h4_to_f4(uint2 raw) {
    __half2 a = *(__half2*)&raw.x;
    __half2 b = *(__half2*)&raw.y;
    float2 fa = __half22float2(a), fb = __half22float2(b);
    return make_float4(fa.x, fa.y, fb.x, fb.y);
}

__global__ __launch_bounds__(256) void k_agg(const __half* __restrict__ tmp,
                                             __half* __restrict__ outh,
                                             const float* __restrict__ bias) {
    __shared__ float bsum[D];
    __shared__ float bsq[D];
    int tid = threadIdx.x;
    if (tid < D) { bsum[tid] = 0.f; bsq[tid] = 0.f; }
    __syncthreads();

    int lane = tid & 31, wid = tid >> 5;
    const uint2* t2 = (const uint2*)tmp;
    float4 b4 = ((const float4*)bias)[lane];
    float ls0 = 0, ls1 = 0, ls2 = 0, ls3 = 0;
    float lq0 = 0, lq1 = 0, lq2 = 0, lq3 = 0;

    for (int row = blockIdx.x * 8 + wid; row < NN; row += gridDim.x * 8) {
        float4 acc = make_float4(0.f, 0.f, 0.f, 0.f);
        int e0 = g_off[row], e1 = g_off[row + 1];
        int e = e0;
        for (; e + 4 <= e1; e += 4) {
            int2 p0 = __ldg(&g_edge[e]);
            int2 p1 = __ldg(&g_edge[e + 1]);
            int2 p2 = __ldg(&g_edge[e + 2]);
            int2 p3 = __ldg(&g_edge[e + 3]);
            float4 v0 = h4_to_f4(__ldg(&t2[p0.x * 32 + lane]));
            float4 v1 = h4_to_f4(__ldg(&t2[p1.x * 32 + lane]));
            float4 v2 = h4_to_f4(__ldg(&t2[p2.x * 32 + lane]));
            float4 v3 = h4_to_f4(__ldg(&t2[p3.x * 32 + lane]));
            float w0 = __int_as_float(p0.y), w1 = __int_as_float(p1.y);
            float w2 = __int_as_float(p2.y), w3 = __int_as_float(p3.y);
            acc.x = fmaf(w0, v0.x, acc.x); acc.y = fmaf(w0, v0.y, acc.y);
            acc.z = fmaf(w0, v0.z, acc.z); acc.w = fmaf(w0, v0.w, acc.w);
            acc.x = fmaf(w1, v1.x, acc.x); acc.y = fmaf(w1, v1.y, acc.y);
            acc.z = fmaf(w1, v1.z, acc.z); acc.w = fmaf(w1, v1.w, acc.w);
            acc.x = fmaf(w2, v2.x, acc.x); acc.y = fmaf(w2, v2.y, acc.y);
            acc.z = fmaf(w2, v2.z, acc.z); acc.w = fmaf(w2, v2.w, acc.w);
            acc.x = fmaf(w3, v3.x, acc.x); acc.y = fmaf(w3, v3.y, acc.y);
            acc.z = fmaf(w3, v3.z, acc.z); acc.w = fmaf(w3, v3.w, acc.w);
        }
        for (; e < e1; e++) {
            int2 pp = __ldg(&g_edge[e]);
            float w = __int_as_float(pp.y);
            float4 v = h4_to_f4(__ldg(&t2[pp.x * 32 + lane]));
            acc.x = fmaf(w, v.x, acc.x);
            acc.y = fmaf(w, v.y, acc.y);
            acc.z = fmaf(w, v.z, acc.z);
            acc.w = fmaf(w, v.w, acc.w);
        }
        float sw_ = g_selfw[row];
        float4 v = h4_to_f4(__ldg(&t2[row * 32 + lane]));
        acc.x = fmaf(sw_, v.x, acc.x) + b4.x;
        acc.y = fmaf(sw_, v.y, acc.y) + b4.y;
        acc.z = fmaf(sw_, v.z, acc.z) + b4.z;
        acc.w = fmaf(sw_, v.w, acc.w) + b4.w;
        uint2 packed;
        *(__half2*)&packed.x = __floats2half2_rn(acc.x, acc.y);
        *(__half2*)&packed.y = __floats2half2_rn(acc.z, acc.w);
        ((uint2*)outh)[row * 32 + lane] = packed;
        ls0 += acc.x; ls1 += acc.y; ls2 += acc.z; ls3 += acc.w;
        lq0 += acc.x * acc.x; lq1 += acc.y * acc.y;
        lq2 += acc.z * acc.z; lq3 += acc.w * acc.w;
    }

    atomicAdd(&bsum[lane * 4 + 0], ls0); atomicAdd(&bsum[lane * 4 + 1], ls1);
    atomicAdd(&bsum[lane * 4 + 2], ls2); atomicAdd(&bsum[lane * 4 + 3], ls3);
    atomicAdd(&bsq[lane * 4 + 0], lq0);  atomicAdd(&bsq[lane * 4 + 1], lq1);
    atomicAdd(&bsq[lane * 4 + 2], lq2);  atomicAdd(&bsq[lane * 4 + 3], lq3);
    __syncthreads();
    if (tid < D) {
        int slot = (blockIdx.x & (NSLOT - 1)) * D + tid;
        atomicAdd(&g_psum[slot], bsum[tid]);
        atomicAdd(&g_psq[slot],  bsq[tid]);
    }
}

// reduce slots -> affine coeffs, then self-zero slots for the next layer
__global__ void k_stats(const float* __restrict__ gamma, const float* __restrict__ beta) {
    int f = threadIdx.x;
    if (f >= D) return;
    float s = 0.f, q = 0.f;
#pragma unroll
    for (int k = 0; k < NSLOT; k++) {
        s += g_psum[k * D + f];
        q += g_psq[k * D + f];
        g_psum[k * D + f] = 0.f;
        g_psq[k * D + f]  = 0.f;
    }
    float mu  = s / (float)NN;
    float var = q / (float)NN - mu * mu;
    float rstd = rsqrtf(var + EPSV);
    float sc = rstd * gamma[f];
    g_scale[f] = sc;
    g_shift[f] = beta[f] - mu * sc;
}

// ---------------- pooling (fused BN+ReLU of last layer) + MLP head ----------------
__global__ void k_pool(const __half* __restrict__ h) {
    int g = blockIdx.x, f = threadIdx.x;
    int a = g_start[g], b = g_end[g];
    float sc = g_scale[f], sh = g_shift[f];
    float s0 = 0.f, s1 = 0.f, s2 = 0.f, s3 = 0.f;
    int i = a;
    for (; i + 4 <= b; i += 4) {
        s0 += fmaxf(fmaf(__half2float(h[(i + 0) * D + f]), sc, sh), 0.f);
        s1 += fmaxf(fmaf(__half2float(h[(i + 1) * D + f]), sc, sh), 0.f);
        s2 += fmaxf(fmaf(__half2float(h[(i + 2) * D + f]), sc, sh), 0.f);
        s3 += fmaxf(fmaf(__half2float(h[(i + 3) * D + f]), sc, sh), 0.f);
    }
    for (; i < b; i++) s0 += fmaxf(fmaf(__half2float(h[i * D + f]), sc, sh), 0.f);
    int c = b - a;
    g_Z[g * D + f] = ((s0 + s1) + (s2 + s3)) / (float)(c > 0 ? c : 1);
}

__global__ void k_head(const float* __restrict__ W1, const float* __restrict__ b1,
                       const float* __restrict__ W2, const float* __restrict__ b2,
                       float* __restrict__ out) {
    __shared__ float zs[D];
    __shared__ float red[4];
    int g = blockIdx.x, j = threadIdx.x;
    zs[j] = g_Z[g * D + j];
    __syncthreads();
    float acc = b1[j];
#pragma unroll 8
    for (int k = 0; k < D; k++) acc = fmaf(zs[k], W1[k * D + j], acc);
    float hz = fmaxf(acc, 0.f);
    float p = hz * W2[j];
#pragma unroll
    for (int o = 16; o; o >>= 1) p += __shfl_down_sync(0xffffffffu, p, o);
    if ((j & 31) == 0) red[j >> 5] = p;
    __syncthreads();
    if (j == 0) out[g] = red[0] + red[1] + red[2] + red[3] + b2[0];
}

// ---------------- launch ----------------
extern "C" void kernel_launch(void* const* d_in, const int* in_sizes, int n_in,
                              void* d_out, int out_size) {
    const float* x      = (const float*)d_in[0];
    const int*   ei     = (const int*)d_in[1];
    const int*   batch  = (const int*)d_in[2];
    const float* Ws     = (const float*)d_in[3];
    const float* bs     = (const float*)d_in[4];
    const float* gammas = (const float*)d_in[5];
    const float* betas  = (const float*)d_in[6];
    const float* W1     = (const float*)d_in[7];
    const float* b1     = (const float*)d_in[8];
    const float* W2     = (const float*)d_in[9];
    const float* b2     = (const float*)d_in[10];
    float* out = (float*)d_out;

    __half *A, *B, *wh, *wl;
    cudaGetSymbolAddress((void**)&A, g_bufA);
    cudaGetSymbolAddress((void**)&B, g_bufB);
    cudaGetSymbolAddress((void**)&wh, g_Wh16);
    cudaGetSymbolAddress((void**)&wl, g_Wl16);
    cudaFuncSetAttribute(k_gemm16, cudaFuncAttributeMaxDynamicSharedMemorySize, MMASMEM);

    const int NB_N = (NN + 255) / 256;   // 391
    const int NB_E = (NE + 255) / 256;   // 3125

    // ncu captures launch index 3: the new fp16 GEMM (layer 0) goes there.
    k_prepw<<<3 * D * D / 128, 128>>>(Ws);                                 // 0
    k_convx<<<(NN * 32 + 255) / 256, 256>>>(x, A);                         // 1
    k_zero_cnt<<<NB_N, 256>>>();                                           // 2
    k_gemm16<<<NT2, 256, MMASMEM>>>(A, wh, wl, B, 0);                      // 3 <- profiled
    k_count<<<NB_E, 256>>>(ei);                                            // 4
    k_node<<<NB_N, 256>>>();                                               // 5
    k_part<<<SCAN_B, 256>>>();                                             // 6
    k_scanpart<<<1, 512>>>();                                              // 7
    k_offsets<<<SCAN_B, 256>>>();                                          // 8
    k_fill<<<NB_E, 256>>>(ei);                                             // 9
    k_bounds<<<NB_N, 256>>>(batch);                                        // 10

    for (int l = 0; l < 3; l++) {
        if (l > 0)
            k_gemm16<<<NT2, 256, MMASMEM>>>(A, wh + l * D * D, wl + l * D * D, B, 1);
        k_agg<<<2048, 256>>>(B, A, bs + l * D);
        k_stats<<<1, 128>>>(gammas + l * D, betas + l * D);
    }

    k_pool<<<NG, 128>>>(A);
    k_head<<<NG, 128>>>(W1, b1, W2, b2, out);
}

// round 10
// speedup vs baseline: 2.2372x; 1.0970x over previous
#include <cuda_runtime.h>
#include <cuda_fp16.h>
#include <cstdint>

#define NN 100000
#define NE 800000
#define NG 512
#define D  128
#define EPSV 1e-5f
#define NT2 391              // ceil(NN/256)
#define SCAN_B 391           // ceil(NN/256)
#define NSLOT 32

// ---------------- scratch (static device globals; no allocations) ----------------
__device__ __half g_bufA[NN * D];
__device__ __half g_bufB[NN * D];
__device__ float  g_dinv[NN];
__device__ float  g_selfw[NN];
__device__ int    g_cnt[NN];
__device__ int    g_fill[NN];
__device__ int    g_off[NN + 1];
__device__ int2   g_edge[NE];        // (src, __float_as_int(w))
__device__ int    g_part[SCAN_B];
__device__ int    g_pbase[SCAN_B];
__device__ float  g_psum[NSLOT * D];
__device__ float  g_psq[NSLOT * D];
__device__ float  g_scale[D];
__device__ float  g_shift[D];
__device__ float  g_Z[NG * D];
__device__ int    g_start[NG];
__device__ int    g_end[NG];
__device__ __half g_Wh16[3 * D * D];   // W^T per layer, [n][k], fp16

__device__ __forceinline__ int clampN(int v) {
    return v < 0 ? 0 : (v >= NN ? NN - 1 : v);
}

__device__ __forceinline__ uint32_t smem_u32(const void* p) {
    uint32_t a;
    asm("{ .reg .u64 t; cvta.to.shared.u64 t, %1; cvt.u32.u64 %0, t; }" : "=r"(a) : "l"(p));
    return a;
}

// XOR swizzle for 256B rows
__device__ __forceinline__ uint32_t sw(uint32_t off) {
    return off ^ ((off >> 4) & 0x70);
}

__device__ __forceinline__ void ldm_x4(uint32_t* r, uint32_t addr) {
    asm volatile("ldmatrix.sync.aligned.m8n8.x4.shared.b16 {%0,%1,%2,%3}, [%4];"
                 : "=r"(r[0]), "=r"(r[1]), "=r"(r[2]), "=r"(r[3]) : "r"(addr));
}

__device__ __forceinline__ void mma_f16(float* c, const uint32_t* a, uint32_t b0, uint32_t b1) {
    asm volatile(
        "mma.sync.aligned.m16n8k16.row.col.f32.f16.f16.f32 "
        "{%0,%1,%2,%3}, {%4,%5,%6,%7}, {%8,%9}, {%0,%1,%2,%3};"
        : "+f"(c[0]), "+f"(c[1]), "+f"(c[2]), "+f"(c[3])
        : "r"(a[0]), "r"(a[1]), "r"(a[2]), "r"(a[3]), "r"(b0), "r"(b1));
}

// ---------------- graph preprocessing ----------------
__global__ void k_zero_cnt() {
    int i = blockIdx.x * blockDim.x + threadIdx.x;
    if (i < NN) g_cnt[i] = 0;
}

__global__ void k_count(const int* __restrict__ ei) {
    int e = blockIdx.x * blockDim.x + threadIdx.x;
    if (e < NE) atomicAdd(&g_cnt[clampN(ei[NE + e])], 1);
}

__global__ void k_node() {
    int i = blockIdx.x * blockDim.x + threadIdx.x;
    if (i < NN) {
        float deg = (float)g_cnt[i] + 1.0f;
        g_dinv[i]  = rsqrtf(deg);
        g_selfw[i] = 1.0f / deg;
        g_fill[i]  = 0;
    }
    if (i < NG) { g_start[i] = 0; g_end[i] = 0; }
    if (i < NSLOT * D) { g_psum[i] = 0.f; g_psq[i] = 0.f; }
}

__global__ void k_part() {
    __shared__ int s[256];
    int t = threadIdx.x;
    int i = blockIdx.x * 256 + t;
    int v = (i < NN) ? g_cnt[i] : 0;
    s[t] = v; __syncthreads();
    for (int o = 128; o; o >>= 1) { if (t < o) s[t] += s[t + o]; __syncthreads(); }
    if (t == 0) g_part[blockIdx.x] = s[0];
}

__global__ void k_scanpart() {
    __shared__ int s[512];
    int t = threadIdx.x;
    int v = (t < SCAN_B) ? g_part[t] : 0;
    s[t] = v; __syncthreads();
    for (int d = 1; d < 512; d <<= 1) {
        int x = (t >= d) ? s[t - d] : 0;
        __syncthreads();
        s[t] += x;
        __syncthreads();
    }
    if (t < SCAN_B) g_pbase[t] = s[t] - v;
    if (t == SCAN_B - 1) g_off[NN] = s[t];
}

__global__ void k_offsets() {
    __shared__ int s[256];
    int t = threadIdx.x;
    int i = blockIdx.x * 256 + t;
    int v = (i < NN) ? g_cnt[i] : 0;
    s[t] = v; __syncthreads();
    for (int d = 1; d < 256; d <<= 1) {
        int x = (t >= d) ? s[t - d] : 0;
        __syncthreads();
        s[t] += x;
        __syncthreads();
    }
    if (i < NN) g_off[i] = g_pbase[blockIdx.x] + s[t] - v;
}

__global__ void k_fill(const int* __restrict__ ei) {
    int e = blockIdx.x * blockDim.x + threadIdx.x;
    if (e >= NE) return;
    int s = clampN(ei[e]);
    int d = clampN(ei[NE + e]);
    int p = g_off[d] + atomicAdd(&g_fill[d], 1);
    g_edge[p] = make_int2(s, __float_as_int(g_dinv[s] * g_dinv[d]));
}

__global__ void k_bounds(const int* __restrict__ batch) {
    int i = blockIdx.x * blockDim.x + threadIdx.x;
    if (i >= NN) return;
    int b = batch[i];
    if (b < 0) b = 0; if (b >= NG) b = NG - 1;
    int bp = (i == 0) ? -1 : batch[i - 1];
    int bn = (i == NN - 1) ? -1 : batch[i + 1];
    if (i == 0      || bp != b) g_start[b] = i;
    if (i == NN - 1 || bn != b) g_end[b]   = i + 1;
}

// W^T fp16: g_Wh16[l][n][k] = fp16(W[l][k][n])
__global__ void k_prepw(const float* __restrict__ Ws) {
    int idx = blockIdx.x * 128 + threadIdx.x;       // 3*128*128 total
    int l = idx >> 14, rem = idx & 16383;
    int n = rem >> 7, k = rem & 127;
    g_Wh16[idx] = __float2half_rn(Ws[l * 16384 + k * 128 + n]);
}

// x (fp32) -> fp16 buffer
__global__ void k_convx(const float* __restrict__ x, __half* __restrict__ o) {
    int i = blockIdx.x * blockDim.x + threadIdx.x;   // float4 index
    if (i >= NN * 32) return;
    float4 v = __ldg((const float4*)x + i);
    uint2 p;
    *(__half2*)&p.x = __floats2half2_rn(v.x, v.y);
    *(__half2*)&p.y = __floats2half2_rn(v.z, v.w);
    ((uint2*)o)[i] = p;
}

// ---------------- fp16 HMMA GEMM: out[N,128] = bnrelu(in)[N,128] @ W ----------------
// Tile M=256 (8 warps x 32 rows). smem: W^T only (32KB). Single fp16 W term.
#define MMASMEM 32768

__global__ __launch_bounds__(256) void k_gemm16(const __half* __restrict__ in,
                                                const __half* __restrict__ Wh,
                                                __half* __restrict__ out,
                                                int apply) {
    extern __shared__ char smc[];
    uint32_t sb = smem_u32(smc);
    int tid = threadIdx.x, wid = tid >> 5, lane = tid & 31;
    int row0 = blockIdx.x * 256;

    // ---- stage W^T
    {
        int n = tid >> 1, hf = tid & 1;
        const uint4* src_h = (const uint4*)(Wh) + n * 16 + hf * 8;
        uint32_t base = n * 256 + hf * 128;
#pragma unroll
        for (int c = 0; c < 8; c++) {
            uint32_t o = sw(base + c * 16);
            *(uint4*)(smc + o) = __ldg(&src_h[c]);
        }
    }

    // ---- A fragments: 2 sets of 16 rows, direct fp16 global loads (+BN/ReLU)
    int groupID = lane >> 2, tig = lane & 3;
    int rb = row0 + wid * 32;
    uint32_t af[2][8][4];
    bool okr[2][2];
#pragma unroll
    for (int s = 0; s < 2; s++) {
        int r0 = rb + s * 16 + groupID;
        int r1 = r0 + 8;
        okr[s][0] = r0 < NN; okr[s][1] = r1 < NN;
        const __half2* hp0 = (const __half2*)(in + (size_t)r0 * D);
        const __half2* hp1 = (const __half2*)(in + (size_t)r1 * D);
#pragma unroll
        for (int k = 0; k < 8; k++) {
            __half2 z = __floats2half2_rn(0.f, 0.f);
            __half2 a0 = okr[s][0] ? __ldg(&hp0[tig + k * 8])     : z;
            __half2 a1 = okr[s][1] ? __ldg(&hp1[tig + k * 8])     : z;
            __half2 a2 = okr[s][0] ? __ldg(&hp0[tig + k * 8 + 4]) : z;
            __half2 a3 = okr[s][1] ? __ldg(&hp1[tig + k * 8 + 4]) : z;
            if (apply) {
                float2 s0 = ((const float2*)g_scale)[tig + k * 8];
                float2 h0 = ((const float2*)g_shift)[tig + k * 8];
                float2 s1 = ((const float2*)g_scale)[tig + k * 8 + 4];
                float2 h1 = ((const float2*)g_shift)[tig + k * 8 + 4];
                float2 f0 = __half22float2(a0), f1 = __half22float2(a1);
                float2 f2 = __half22float2(a2), f3 = __half22float2(a3);
                a0 = __floats2half2_rn(fmaxf(fmaf(f0.x, s0.x, h0.x), 0.f),
                                       fmaxf(fmaf(f0.y, s0.y, h0.y), 0.f));
                a1 = __floats2half2_rn(fmaxf(fmaf(f1.x, s0.x, h0.x), 0.f),
                                       fmaxf(fmaf(f1.y, s0.y, h0.y), 0.f));
                a2 = __floats2half2_rn(fmaxf(fmaf(f2.x, s1.x, h1.x), 0.f),
                                       fmaxf(fmaf(f2.y, s1.y, h1.y), 0.f));
                a3 = __floats2half2_rn(fmaxf(fmaf(f3.x, s1.x, h1.x), 0.f),
                                       fmaxf(fmaf(f3.y, s1.y, h1.y), 0.f));
            }
            af[s][k][0] = *(uint32_t*)&a0;
            af[s][k][1] = *(uint32_t*)&a1;
            af[s][k][2] = *(uint32_t*)&a2;
            af[s][k][3] = *(uint32_t*)&a3;
        }
    }
    __syncthreads();   // W staged

    uint32_t b_base = ((lane & 7) + ((lane >> 4) << 3)) * 256 + (((lane >> 3) & 1) * 8) * 2;
    int col_t = tig * 2;

#pragma unroll 2
    for (int np = 0; np < 8; np++) {
        float e0[4] = {0,0,0,0}, o0[4] = {0,0,0,0};
        float e1[4] = {0,0,0,0}, o1[4] = {0,0,0,0};
#pragma unroll
        for (int k = 0; k < 8; k++) {
            uint32_t bh[4];
            uint32_t o = sw(b_base + np * 4096 + k * 32);
            ldm_x4(bh, sb + o);
            mma_f16(e0, af[0][k], bh[0], bh[1]);
            mma_f16(o0, af[0][k], bh[2], bh[3]);
            mma_f16(e1, af[1][k], bh[0], bh[1]);
            mma_f16(o1, af[1][k], bh[2], bh[3]);
        }
        int nb = np * 16;
#pragma unroll
        for (int s = 0; s < 2; s++) {
            float* ee = s ? e1 : e0; float* oo = s ? o1 : o0;
            int r0 = rb + s * 16 + groupID;
            int r1 = r0 + 8;
            if (okr[s][0]) {
                *(__half2*)(out + (size_t)r0 * D + nb + col_t)     = __floats2half2_rn(ee[0], ee[1]);
                *(__half2*)(out + (size_t)r0 * D + nb + 8 + col_t) = __floats2half2_rn(oo[0], oo[1]);
            }
            if (okr[s][1]) {
                *(__half2*)(out + (size_t)r1 * D + nb + col_t)     = __floats2half2_rn(ee[2], ee[3]);
                *(__half2*)(out + (size_t)r1 * D + nb + 8 + col_t) = __floats2half2_rn(oo[2], oo[3]);
            }
        }
    }
}

// ---------------- aggregation (gather, CSR) + bias + fused BN stats ----------------
__device__ __forceinline__ float4 h4_to_f4(uint2 raw) {
    __half2 a = *(__half2*)&raw.x;
    __half2 b = *(__half2*)&raw.y;
    float2 fa = __half22float2(a), fb = __half22float2(b);
    return make_float4(fa.x, fa.y, fb.x, fb.y);
}

__device__ __forceinline__ void acc4(float4& acc, float w, float4 v) {
    acc.x = fmaf(w, v.x, acc.x);
    acc.y = fmaf(w, v.y, acc.y);
    acc.z = fmaf(w, v.z, acc.z);
    acc.w = fmaf(w, v.w, acc.w);
}

__global__ __launch_bounds__(256) void k_agg(const __half* __restrict__ tmp,
                                             __half* __restrict__ outh,
                                             const float* __restrict__ bias) {
    __shared__ float bsum[D];
    __shared__ float bsq[D];
    int tid = threadIdx.x;
    if (tid < D) { bsum[tid] = 0.f; bsq[tid] = 0.f; }
    __syncthreads();

    int lane = tid & 31, wid = tid >> 5;
    const uint2* t2 = (const uint2*)tmp;
    float4 b4 = ((const float4*)bias)[lane];
    float ls0 = 0, ls1 = 0, ls2 = 0, ls3 = 0;
    float lq0 = 0, lq1 = 0, lq2 = 0, lq3 = 0;

    for (int row = blockIdx.x * 8 + wid; row < NN; row += gridDim.x * 8) {
        float4 acc = make_float4(0.f, 0.f, 0.f, 0.f);
        int e0 = g_off[row], e1 = g_off[row + 1];
        int e = e0;
        for (; e + 8 <= e1; e += 8) {
            int2 p0 = __ldg(&g_edge[e]);
            int2 p1 = __ldg(&g_edge[e + 1]);
            int2 p2 = __ldg(&g_edge[e + 2]);
            int2 p3 = __ldg(&g_edge[e + 3]);
            int2 p4 = __ldg(&g_edge[e + 4]);
            int2 p5 = __ldg(&g_edge[e + 5]);
            int2 p6 = __ldg(&g_edge[e + 6]);
            int2 p7 = __ldg(&g_edge[e + 7]);
            float4 v0 = h4_to_f4(__ldg(&t2[p0.x * 32 + lane]));
            float4 v1 = h4_to_f4(__ldg(&t2[p1.x * 32 + lane]));
            float4 v2 = h4_to_f4(__ldg(&t2[p2.x * 32 + lane]));
            float4 v3 = h4_to_f4(__ldg(&t2[p3.x * 32 + lane]));
            float4 v4 = h4_to_f4(__ldg(&t2[p4.x * 32 + lane]));
            float4 v5 = h4_to_f4(__ldg(&t2[p5.x * 32 + lane]));
            float4 v6 = h4_to_f4(__ldg(&t2[p6.x * 32 + lane]));
            float4 v7 = h4_to_f4(__ldg(&t2[p7.x * 32 + lane]));
            acc4(acc, __int_as_float(p0.y), v0);
            acc4(acc, __int_as_float(p1.y), v1);
            acc4(acc, __int_as_float(p2.y), v2);
            acc4(acc, __int_as_float(p3.y), v3);
            acc4(acc, __int_as_float(p4.y), v4);
            acc4(acc, __int_as_float(p5.y), v5);
            acc4(acc, __int_as_float(p6.y), v6);
            acc4(acc, __int_as_float(p7.y), v7);
        }
        for (; e + 4 <= e1; e += 4) {
            int2 p0 = __ldg(&g_edge[e]);
            int2 p1 = __ldg(&g_edge[e + 1]);
            int2 p2 = __ldg(&g_edge[e + 2]);
            int2 p3 = __ldg(&g_edge[e + 3]);
            float4 v0 = h4_to_f4(__ldg(&t2[p0.x * 32 + lane]));
            float4 v1 = h4_to_f4(__ldg(&t2[p1.x * 32 + lane]));
            float4 v2 = h4_to_f4(__ldg(&t2[p2.x * 32 + lane]));
            float4 v3 = h4_to_f4(__ldg(&t2[p3.x * 32 + lane]));
            acc4(acc, __int_as_float(p0.y), v0);
            acc4(acc, __int_as_float(p1.y), v1);
            acc4(acc, __int_as_float(p2.y), v2);
            acc4(acc, __int_as_float(p3.y), v3);
        }
        for (; e < e1; e++) {
            int2 pp = __ldg(&g_edge[e]);
            float4 v = h4_to_f4(__ldg(&t2[pp.x * 32 + lane]));
            acc4(acc, __int_as_float(pp.y), v);
        }
        float sw_ = g_selfw[row];
        float4 v = h4_to_f4(__ldg(&t2[row * 32 + lane]));
        acc.x = fmaf(sw_, v.x, acc.x) + b4.x;
        acc.y = fmaf(sw_, v.y, acc.y) + b4.y;
        acc.z = fmaf(sw_, v.z, acc.z) + b4.z;
        acc.w = fmaf(sw_, v.w, acc.w) + b4.w;
        uint2 packed;
        *(__half2*)&packed.x = __floats2half2_rn(acc.x, acc.y);
        *(__half2*)&packed.y = __floats2half2_rn(acc.z, acc.w);
        ((uint2*)outh)[row * 32 + lane] = packed;
        ls0 += acc.x; ls1 += acc.y; ls2 += acc.z; ls3 += acc.w;
        lq0 += acc.x * acc.x; lq1 += acc.y * acc.y;
        lq2 += acc.z * acc.z; lq3 += acc.w * acc.w;
    }

    atomicAdd(&bsum[lane * 4 + 0], ls0); atomicAdd(&bsum[lane * 4 + 1], ls1);
    atomicAdd(&bsum[lane * 4 + 2], ls2); atomicAdd(&bsum[lane * 4 + 3], ls3);
    atomicAdd(&bsq[lane * 4 + 0], lq0);  atomicAdd(&bsq[lane * 4 + 1], lq1);
    atomicAdd(&bsq[lane * 4 + 2], lq2);  atomicAdd(&bsq[lane * 4 + 3], lq3);
    __syncthreads();
    if (tid < D) {
        int slot = (blockIdx.x & (NSLOT - 1)) * D + tid;
        atomicAdd(&g_psum[slot], bsum[tid]);
        atomicAdd(&g_psq[slot],  bsq[tid]);
    }
}

// reduce slots -> affine coeffs, then self-zero slots for the next layer
__global__ void k_stats(const float* __restrict__ gamma, const float* __restrict__ beta) {
    int f = threadIdx.x;
    if (f >= D) return;
    float s = 0.f, q = 0.f;
#pragma unroll
    for (int k = 0; k < NSLOT; k++) {
        s += g_psum[k * D + f];
        q += g_psq[k * D + f];
        g_psum[k * D + f] = 0.f;
        g_psq[k * D + f]  = 0.f;
    }
    float mu  = s / (float)NN;
    float var = q / (float)NN - mu * mu;
    float rstd = rsqrtf(var + EPSV);
    float sc = rstd * gamma[f];
    g_scale[f] = sc;
    g_shift[f] = beta[f] - mu * sc;
}

// ---------------- pooling (fused BN+ReLU of last layer) + MLP head ----------------
__global__ void k_pool(const __half* __restrict__ h) {
    int g = blockIdx.x, f = threadIdx.x;
    int a = g_start[g], b = g_end[g];
    float sc = g_scale[f], sh = g_shift[f];
    float s0 = 0.f, s1 = 0.f, s2 = 0.f, s3 = 0.f;
    int i = a;
    for (; i + 4 <= b; i += 4) {
        s0 += fmaxf(fmaf(__half2float(h[(i + 0) * D + f]), sc, sh), 0.f);
        s1 += fmaxf(fmaf(__half2float(h[(i + 1) * D + f]), sc, sh), 0.f);
        s2 += fmaxf(fmaf(__half2float(h[(i + 2) * D + f]), sc, sh), 0.f);
        s3 += fmaxf(fmaf(__half2float(h[(i + 3) * D + f]), sc, sh), 0.f);
    }
    for (; i < b; i++) s0 += fmaxf(fmaf(__half2float(h[i * D + f]), sc, sh), 0.f);
    int c = b - a;
    g_Z[g * D + f] = ((s0 + s1) + (s2 + s3)) / (float)(c > 0 ? c : 1);
}

__global__ void k_head(const float* __restrict__ W1, const float* __restrict__ b1,
                       const float* __restrict__ W2, const float* __restrict__ b2,
                       float* __restrict__ out) {
    __shared__ float zs[D];
    __shared__ float red[4];
    int g = blockIdx.x, j = threadIdx.x;
    zs[j] = g_Z[g * D + j];
    __syncthreads();
    float acc = b1[j];
#pragma unroll 8
    for (int k = 0; k < D; k++) acc = fmaf(zs[k], W1[k * D + j], acc);
    float hz = fmaxf(acc, 0.f);
    float p = hz * W2[j];
#pragma unroll
    for (int o = 16; o; o >>= 1) p += __shfl_down_sync(0xffffffffu, p, o);
    if ((j & 31) == 0) red[j >> 5] = p;
    __syncthreads();
    if (j == 0) out[g] = red[0] + red[1] + red[2] + red[3] + b2[0];
}

// ---------------- launch ----------------
extern "C" void kernel_launch(void* const* d_in, const int* in_sizes, int n_in,
                              void* d_out, int out_size) {
    const float* x      = (const float*)d_in[0];
    const int*   ei     = (const int*)d_in[1];
    const int*   batch  = (const int*)d_in[2];
    const float* Ws     = (const float*)d_in[3];
    const float* bs     = (const float*)d_in[4];
    const float* gammas = (const float*)d_in[5];
    const float* betas  = (const float*)d_in[6];
    const float* W1     = (const float*)d_in[7];
    const float* b1     = (const float*)d_in[8];
    const float* W2     = (const float*)d_in[9];
    const float* b2     = (const float*)d_in[10];
    float* out = (float*)d_out;

    __half *A, *B, *wh;
    cudaGetSymbolAddress((void**)&A, g_bufA);
    cudaGetSymbolAddress((void**)&B, g_bufB);
    cudaGetSymbolAddress((void**)&wh, g_Wh16);
    cudaFuncSetAttribute(k_gemm16, cudaFuncAttributeMaxDynamicSharedMemorySize, MMASMEM);

    const int NB_N = (NN + 255) / 256;   // 391
    const int NB_E = (NE + 255) / 256;   // 3125

    // ncu captures launch index 3: layer-0 GEMM there.
    k_prepw<<<3 * D * D / 128, 128>>>(Ws);                                 // 0
    k_convx<<<(NN * 32 + 255) / 256, 256>>>(x, A);                         // 1
    k_zero_cnt<<<NB_N, 256>>>();                                           // 2
    k_gemm16<<<NT2, 256, MMASMEM>>>(A, wh, B, 0);                          // 3 <- profiled
    k_count<<<NB_E, 256>>>(ei);                                            // 4
    k_node<<<NB_N, 256>>>();                                               // 5
    k_part<<<SCAN_B, 256>>>();                                             // 6
    k_scanpart<<<1, 512>>>();                                              // 7
    k_offsets<<<SCAN_B, 256>>>();                                          // 8
    k_fill<<<NB_E, 256>>>(ei);                                             // 9
    k_bounds<<<NB_N, 256>>>(batch);                                        // 10

    for (int l = 0; l < 3; l++) {
        if (l > 0)
            k_gemm16<<<NT2, 256, MMASMEM>>>(A, wh + l * D * D, B, 1);
        k_agg<<<2048, 256>>>(B, A, bs + l * D);
        k_stats<<<1, 128>>>(gammas + l * D, betas + l * D);
    }

    k_pool<<<NG, 128>>>(A);
    k_head<<<NG, 128>>>(W1, b1, W2, b2, out);
}

// round 11
// speedup vs baseline: 2.4072x; 1.0760x over previous
#include <cuda_runtime.h>
#include <cuda_fp16.h>
#include <cstdint>

#define NN 100000
#define NE 800000
#define NG 512
#define D  128
#define EPSV 1e-5f
#define NT2 391              // ceil(NN/256)
#define SCAN_B 391           // ceil(NN/256)
#define NSLOT 32

// ---------------- scratch (static device globals; no allocations) ----------------
__device__ __half g_bufA[NN * D];
__device__ __half g_bufB[NN * D];
__device__ float  g_dinv[NN];
__device__ float  g_selfw[NN];
__device__ int    g_cnt[NN];         // ZERO at module load; re-zeroed by k_fill each call
__device__ int    g_fill[NN];
__device__ int    g_off[NN + 1];
__device__ int2   g_edge[NE];        // (src, __float_as_int(w))
__device__ int    g_part[SCAN_B];
__device__ int    g_pbase[SCAN_B];
__device__ float  g_psum[NSLOT * D];
__device__ float  g_psq[NSLOT * D];
__device__ float  g_scale[D];
__device__ float  g_shift[D];
__device__ float  g_Z[NG * D];
__device__ int    g_start[NG];
__device__ int    g_end[NG];
__device__ __half g_Wh16[3 * D * D];   // W^T per layer, [n][k], fp16

__device__ __forceinline__ int clampN(int v) {
    return v < 0 ? 0 : (v >= NN ? NN - 1 : v);
}

__device__ __forceinline__ uint32_t smem_u32(const void* p) {
    uint32_t a;
    asm("{ .reg .u64 t; cvta.to.shared.u64 t, %1; cvt.u32.u64 %0, t; }" : "=r"(a) : "l"(p));
    return a;
}

// XOR swizzle for 256B rows
__device__ __forceinline__ uint32_t sw(uint32_t off) {
    return off ^ ((off >> 4) & 0x70);
}

__device__ __forceinline__ void ldm_x4(uint32_t* r, uint32_t addr) {
    asm volatile("ldmatrix.sync.aligned.m8n8.x4.shared.b16 {%0,%1,%2,%3}, [%4];"
                 : "=r"(r[0]), "=r"(r[1]), "=r"(r[2]), "=r"(r[3]) : "r"(addr));
}

__device__ __forceinline__ void mma_f16(float* c, const uint32_t* a, uint32_t b0, uint32_t b1) {
    asm volatile(
        "mma.sync.aligned.m16n8k16.row.col.f32.f16.f16.f32 "
        "{%0,%1,%2,%3}, {%4,%5,%6,%7}, {%8,%9}, {%0,%1,%2,%3};"
        : "+f"(c[0]), "+f"(c[1]), "+f"(c[2]), "+f"(c[3])
        : "r"(a[0]), "r"(a[1]), "r"(a[2]), "r"(a[3]), "r"(b0), "r"(b1));
}

// ---------------- graph preprocessing ----------------
__global__ void k_count(const int* __restrict__ ei) {
    int e = blockIdx.x * blockDim.x + threadIdx.x;
    if (e < NE) atomicAdd(&g_cnt[clampN(ei[NE + e])], 1);
}

// node-wise derived values + per-256-chunk partial sums (merged k_node + k_part)
__global__ void k_nodepart() {
    __shared__ int s[256];
    int t = threadIdx.x;
    int i = blockIdx.x * 256 + t;
    int c = (i < NN) ? g_cnt[i] : 0;
    if (i < NN) {
        float deg = (float)c + 1.0f;
        g_dinv[i]  = rsqrtf(deg);
        g_selfw[i] = 1.0f / deg;
        g_fill[i]  = 0;
    }
    if (i < NG) { g_start[i] = 0; g_end[i] = 0; }
    if (i < NSLOT * D) { g_psum[i] = 0.f; g_psq[i] = 0.f; }
    s[t] = c;
    __syncthreads();
    for (int o = 128; o; o >>= 1) { if (t < o) s[t] += s[t + o]; __syncthreads(); }
    if (t == 0) g_part[blockIdx.x] = s[0];
}

__global__ void k_scanpart() {
    __shared__ int s[512];
    int t = threadIdx.x;
    int v = (t < SCAN_B) ? g_part[t] : 0;
    s[t] = v; __syncthreads();
    for (int d = 1; d < 512; d <<= 1) {
        int x = (t >= d) ? s[t - d] : 0;
        __syncthreads();
        s[t] += x;
        __syncthreads();
    }
    if (t < SCAN_B) g_pbase[t] = s[t] - v;
    if (t == SCAN_B - 1) g_off[NN] = s[t];
}

__global__ void k_offsets() {
    __shared__ int s[256];
    int t = threadIdx.x;
    int i = blockIdx.x * 256 + t;
    int v = (i < NN) ? g_cnt[i] : 0;
    s[t] = v; __syncthreads();
    for (int d = 1; d < 256; d <<= 1) {
        int x = (t >= d) ? s[t - d] : 0;
        __syncthreads();
        s[t] += x;
        __syncthreads();
    }
    if (i < NN) g_off[i] = g_pbase[blockIdx.x] + s[t] - v;
}

__global__ void k_fill(const int* __restrict__ ei) {
    int e = blockIdx.x * blockDim.x + threadIdx.x;
    if (e < NN) g_cnt[e] = 0;          // reset for the NEXT call (cnt consumed by k_offsets)
    if (e >= NE) return;
    int s = clampN(ei[e]);
    int d = clampN(ei[NE + e]);
    int p = g_off[d] + atomicAdd(&g_fill[d], 1);
    g_edge[p] = make_int2(s, __float_as_int(g_dinv[s] * g_dinv[d]));
}

__global__ void k_bounds(const int* __restrict__ batch) {
    int i = blockIdx.x * blockDim.x + threadIdx.x;
    if (i >= NN) return;
    int b = batch[i];
    if (b < 0) b = 0; if (b >= NG) b = NG - 1;
    int bp = (i == 0) ? -1 : batch[i - 1];
    int bn = (i == NN - 1) ? -1 : batch[i + 1];
    if (i == 0      || bp != b) g_start[b] = i;
    if (i == NN - 1 || bn != b) g_end[b]   = i + 1;
}

// W^T fp16: g_Wh16[l][n][k] = fp16(W[l][k][n])
__global__ void k_prepw(const float* __restrict__ Ws) {
    int idx = blockIdx.x * 128 + threadIdx.x;       // 3*128*128 total
    int l = idx >> 14, rem = idx & 16383;
    int n = rem >> 7, k = rem & 127;
    g_Wh16[idx] = __float2half_rn(Ws[l * 16384 + k * 128 + n]);
}

// x (fp32) -> fp16 buffer
__global__ void k_convx(const float* __restrict__ x, __half* __restrict__ o) {
    int i = blockIdx.x * blockDim.x + threadIdx.x;   // float4 index
    if (i >= NN * 32) return;
    float4 v = __ldg((const float4*)x + i);
    uint2 p;
    *(__half2*)&p.x = __floats2half2_rn(v.x, v.y);
    *(__half2*)&p.y = __floats2half2_rn(v.z, v.w);
    ((uint2*)o)[i] = p;
}

// ---------------- fp16 HMMA GEMM: out[N,128] = bnrelu(in)[N,128] @ W ----------------
// Tile M=256 (8 warps x 32 rows). smem: W^T only (32KB).
#define MMASMEM 32768

__global__ __launch_bounds__(256) void k_gemm16(const __half* __restrict__ in,
                                                const __half* __restrict__ Wh,
                                                __half* __restrict__ out,
                                                int apply) {
    extern __shared__ char smc[];
    uint32_t sb = smem_u32(smc);
    int tid = threadIdx.x, wid = tid >> 5, lane = tid & 31;
    int row0 = blockIdx.x * 256;

    // ---- stage W^T
    {
        int n = tid >> 1, hf = tid & 1;
        const uint4* src_h = (const uint4*)(Wh) + n * 16 + hf * 8;
        uint32_t base = n * 256 + hf * 128;
#pragma unroll
        for (int c = 0; c < 8; c++) {
            uint32_t o = sw(base + c * 16);
            *(uint4*)(smc + o) = __ldg(&src_h[c]);
        }
    }

    // ---- A fragments: 2 sets of 16 rows, direct fp16 global loads (+BN/ReLU)
    int groupID = lane >> 2, tig = lane & 3;
    int rb = row0 + wid * 32;
    uint32_t af[2][8][4];
    bool okr[2][2];
#pragma unroll
    for (int s = 0; s < 2; s++) {
        int r0 = rb + s * 16 + groupID;
        int r1 = r0 + 8;
        okr[s][0] = r0 < NN; okr[s][1] = r1 < NN;
        const __half2* hp0 = (const __half2*)(in + (size_t)r0 * D);
        const __half2* hp1 = (const __half2*)(in + (size_t)r1 * D);
#pragma unroll
        for (int k = 0; k < 8; k++) {
            __half2 z = __floats2half2_rn(0.f, 0.f);
            __half2 a0 = okr[s][0] ? __ldg(&hp0[tig + k * 8])     : z;
            __half2 a1 = okr[s][1] ? __ldg(&hp1[tig + k * 8])     : z;
            __half2 a2 = okr[s][0] ? __ldg(&hp0[tig + k * 8 + 4]) : z;
            __half2 a3 = okr[s][1] ? __ldg(&hp1[tig + k * 8 + 4]) : z;
            if (apply) {
                float2 s0 = ((const float2*)g_scale)[tig + k * 8];
                float2 h0 = ((const float2*)g_shift)[tig + k * 8];
                float2 s1 = ((const float2*)g_scale)[tig + k * 8 + 4];
                float2 h1 = ((const float2*)g_shift)[tig + k * 8 + 4];
                float2 f0 = __half22float2(a0), f1 = __half22float2(a1);
                float2 f2 = __half22float2(a2), f3 = __half22float2(a3);
                a0 = __floats2half2_rn(fmaxf(fmaf(f0.x, s0.x, h0.x), 0.f),
                                       fmaxf(fmaf(f0.y, s0.y, h0.y), 0.f));
                a1 = __floats2half2_rn(fmaxf(fmaf(f1.x, s0.x, h0.x), 0.f),
                                       fmaxf(fmaf(f1.y, s0.y, h0.y), 0.f));
                a2 = __floats2half2_rn(fmaxf(fmaf(f2.x, s1.x, h1.x), 0.f),
                                       fmaxf(fmaf(f2.y, s1.y, h1.y), 0.f));
                a3 = __floats2half2_rn(fmaxf(fmaf(f3.x, s1.x, h1.x), 0.f),
                                       fmaxf(fmaf(f3.y, s1.y, h1.y), 0.f));
            }
            af[s][k][0] = *(uint32_t*)&a0;
            af[s][k][1] = *(uint32_t*)&a1;
            af[s][k][2] = *(uint32_t*)&a2;
            af[s][k][3] = *(uint32_t*)&a3;
        }
    }
    __syncthreads();   // W staged

    uint32_t b_base = ((lane & 7) + ((lane >> 4) << 3)) * 256 + (((lane >> 3) & 1) * 8) * 2;
    int col_t = tig * 2;

#pragma unroll 2
    for (int np = 0; np < 8; np++) {
        float e0[4] = {0,0,0,0}, o0[4] = {0,0,0,0};
        float e1[4] = {0,0,0,0}, o1[4] = {0,0,0,0};
#pragma unroll
        for (int k = 0; k < 8; k++) {
            uint32_t bh[4];
            uint32_t o = sw(b_base + np * 4096 + k * 32);
            ldm_x4(bh, sb + o);
            mma_f16(e0, af[0][k], bh[0], bh[1]);
            mma_f16(o0, af[0][k], bh[2], bh[3]);
            mma_f16(e1, af[1][k], bh[0], bh[1]);
            mma_f16(o1, af[1][k], bh[2], bh[3]);
        }
        int nb = np * 16;
#pragma unroll
        for (int s = 0; s < 2; s++) {
            float* ee = s ? e1 : e0; float* oo = s ? o1 : o0;
            int r0 = rb + s * 16 + groupID;
            int r1 = r0 + 8;
            if (okr[s][0]) {
                *(__half2*)(out + (size_t)r0 * D + nb + col_t)     = __floats2half2_rn(ee[0], ee[1]);
                *(__half2*)(out + (size_t)r0 * D + nb + 8 + col_t) = __floats2half2_rn(oo[0], oo[1]);
            }
            if (okr[s][1]) {
                *(__half2*)(out + (size_t)r1 * D + nb + col_t)     = __floats2half2_rn(ee[2], ee[3]);
                *(__half2*)(out + (size_t)r1 * D + nb + 8 + col_t) = __floats2half2_rn(oo[2], oo[3]);
            }
        }
    }
}

// ---------------- aggregation (gather, CSR) + bias + fused BN stats ----------------
__device__ __forceinline__ float4 h4_to_f4(uint2 raw) {
    __half2 a = *(__half2*)&raw.x;
    __half2 b = *(__half2*)&raw.y;
    float2 fa = __half22float2(a), fb = __half22float2(b);
    return make_float4(fa.x, fa.y, fb.x, fb.y);
}

__device__ __forceinline__ void acc4(float4& acc, float w, float4 v) {
    acc.x = fmaf(w, v.x, acc.x);
    acc.y = fmaf(w, v.y, acc.y);
    acc.z = fmaf(w, v.z, acc.z);
    acc.w = fmaf(w, v.w, acc.w);
}

__global__ __launch_bounds__(256) void k_agg(const __half* __restrict__ tmp,
                                             __half* __restrict__ outh,
                                             const float* __restrict__ bias) {
    __shared__ float bsum[D];
    __shared__ float bsq[D];
    int tid = threadIdx.x;
    if (tid < D) { bsum[tid] = 0.f; bsq[tid] = 0.f; }
    __syncthreads();

    int lane = tid & 31, wid = tid >> 5;
    const uint2* t2 = (const uint2*)tmp;
    float4 b4 = ((const float4*)bias)[lane];
    float ls0 = 0, ls1 = 0, ls2 = 0, ls3 = 0;
    float lq0 = 0, lq1 = 0, lq2 = 0, lq3 = 0;

    for (int row = blockIdx.x * 8 + wid; row < NN; row += gridDim.x * 8) {
        float4 acc = make_float4(0.f, 0.f, 0.f, 0.f);
        int e0 = g_off[row], e1 = g_off[row + 1];
        int e = e0;
        for (; e + 8 <= e1; e += 8) {
            int2 p0 = __ldg(&g_edge[e]);
            int2 p1 = __ldg(&g_edge[e + 1]);
            int2 p2 = __ldg(&g_edge[e + 2]);
            int2 p3 = __ldg(&g_edge[e + 3]);
            int2 p4 = __ldg(&g_edge[e + 4]);
            int2 p5 = __ldg(&g_edge[e + 5]);
            int2 p6 = __ldg(&g_edge[e + 6]);
            int2 p7 = __ldg(&g_edge[e + 7]);
            float4 v0 = h4_to_f4(__ldg(&t2[p0.x * 32 + lane]));
            float4 v1 = h4_to_f4(__ldg(&t2[p1.x * 32 + lane]));
            float4 v2 = h4_to_f4(__ldg(&t2[p2.x * 32 + lane]));
            float4 v3 = h4_to_f4(__ldg(&t2[p3.x * 32 + lane]));
            float4 v4 = h4_to_f4(__ldg(&t2[p4.x * 32 + lane]));
            float4 v5 = h4_to_f4(__ldg(&t2[p5.x * 32 + lane]));
            float4 v6 = h4_to_f4(__ldg(&t2[p6.x * 32 + lane]));
            float4 v7 = h4_to_f4(__ldg(&t2[p7.x * 32 + lane]));
            acc4(acc, __int_as_float(p0.y), v0);
            acc4(acc, __int_as_float(p1.y), v1);
            acc4(acc, __int_as_float(p2.y), v2);
            acc4(acc, __int_as_float(p3.y), v3);
            acc4(acc, __int_as_float(p4.y), v4);
            acc4(acc, __int_as_float(p5.y), v5);
            acc4(acc, __int_as_float(p6.y), v6);
            acc4(acc, __int_as_float(p7.y), v7);
        }
        for (; e + 4 <= e1; e += 4) {
            int2 p0 = __ldg(&g_edge[e]);
            int2 p1 = __ldg(&g_edge[e + 1]);
            int2 p2 = __ldg(&g_edge[e + 2]);
            int2 p3 = __ldg(&g_edge[e + 3]);
            float4 v0 = h4_to_f4(__ldg(&t2[p0.x * 32 + lane]));
            float4 v1 = h4_to_f4(__ldg(&t2[p1.x * 32 + lane]));
            float4 v2 = h4_to_f4(__ldg(&t2[p2.x * 32 + lane]));
            float4 v3 = h4_to_f4(__ldg(&t2[p3.x * 32 + lane]));
            acc4(acc, __int_as_float(p0.y), v0);
            acc4(acc, __int_as_float(p1.y), v1);
            acc4(acc, __int_as_float(p2.y), v2);
            acc4(acc, __int_as_float(p3.y), v3);
        }
        for (; e < e1; e++) {
            int2 pp = __ldg(&g_edge[e]);
            float4 v = h4_to_f4(__ldg(&t2[pp.x * 32 + lane]));
            acc4(acc, __int_as_float(pp.y), v);
        }
        float sw_ = g_selfw[row];
        float4 v = h4_to_f4(__ldg(&t2[row * 32 + lane]));
        acc.x = fmaf(sw_, v.x, acc.x) + b4.x;
        acc.y = fmaf(sw_, v.y, acc.y) + b4.y;
        acc.z = fmaf(sw_, v.z, acc.z) + b4.z;
        acc.w = fmaf(sw_, v.w, acc.w) + b4.w;
        uint2 packed;
        *(__half2*)&packed.x = __floats2half2_rn(acc.x, acc.y);
        *(__half2*)&packed.y = __floats2half2_rn(acc.z, acc.w);
        ((uint2*)outh)[row * 32 + lane] = packed;
        ls0 += acc.x; ls1 += acc.y; ls2 += acc.z; ls3 += acc.w;
        lq0 += acc.x * acc.x; lq1 += acc.y * acc.y;
        lq2 += acc.z * acc.z; lq3 += acc.w * acc.w;
    }

    atomicAdd(&bsum[lane * 4 + 0], ls0); atomicAdd(&bsum[lane * 4 + 1], ls1);
    atomicAdd(&bsum[lane * 4 + 2], ls2); atomicAdd(&bsum[lane * 4 + 3], ls3);
    atomicAdd(&bsq[lane * 4 + 0], lq0);  atomicAdd(&bsq[lane * 4 + 1], lq1);
    atomicAdd(&bsq[lane * 4 + 2], lq2);  atomicAdd(&bsq[lane * 4 + 3], lq3);
    __syncthreads();
    if (tid < D) {
        int slot = (blockIdx.x & (NSLOT - 1)) * D + tid;
        atomicAdd(&g_psum[slot], bsum[tid]);
        atomicAdd(&g_psq[slot],  bsq[tid]);
    }
}

// reduce slots -> affine coeffs, then self-zero slots for the next layer
__global__ void k_stats(const float* __restrict__ gamma, const float* __restrict__ beta) {
    int f = threadIdx.x;
    if (f >= D) return;
    float s = 0.f, q = 0.f;
#pragma unroll
    for (int k = 0; k < NSLOT; k++) {
        s += g_psum[k * D + f];
        q += g_psq[k * D + f];
        g_psum[k * D + f] = 0.f;
        g_psq[k * D + f]  = 0.f;
    }
    float mu  = s / (float)NN;
    float var = q / (float)NN - mu * mu;
    float rstd = rsqrtf(var + EPSV);
    float sc = rstd * gamma[f];
    g_scale[f] = sc;
    g_shift[f] = beta[f] - mu * sc;
}

// ---------------- pooling (fused BN+ReLU of last layer, split rows) + MLP head ----------------
__global__ __launch_bounds__(256) void k_pool(const __half* __restrict__ h) {
    __shared__ float partial[D];
    int g = blockIdx.x, t = threadIdx.x;
    int f = t & 127, hf = t >> 7;
    int a = g_start[g], b = g_end[g];
    int n = b - a;
    int mid = a + (n >> 1);
    int lo = hf ? mid : a;
    int hi = hf ? b : mid;
    float sc = g_scale[f], sh = g_shift[f];
    float s0 = 0.f, s1 = 0.f;
    int i = lo;
    for (; i + 2 <= hi; i += 2) {
        s0 += fmaxf(fmaf(__half2float(h[(i + 0) * D + f]), sc, sh), 0.f);
        s1 += fmaxf(fmaf(__half2float(h[(i + 1) * D + f]), sc, sh), 0.f);
    }
    for (; i < hi; i++) s0 += fmaxf(fmaf(__half2float(h[i * D + f]), sc, sh), 0.f);
    float s = s0 + s1;
    if (hf) partial[f] = s;
    __syncthreads();
    if (!hf) g_Z[g * D + f] = (s + partial[f]) / (float)(n > 0 ? n : 1);
}

__global__ void k_head(const float* __restrict__ W1, const float* __restrict__ b1,
                       const float* __restrict__ W2, const float* __restrict__ b2,
                       float* __restrict__ out) {
    __shared__ float zs[D];
    __shared__ float red[4];
    int g = blockIdx.x, j = threadIdx.x;
    zs[j] = g_Z[g * D + j];
    __syncthreads();
    float acc = b1[j];
#pragma unroll 8
    for (int k = 0; k < D; k++) acc = fmaf(zs[k], W1[k * D + j], acc);
    float hz = fmaxf(acc, 0.f);
    float p = hz * W2[j];
#pragma unroll
    for (int o = 16; o; o >>= 1) p += __shfl_down_sync(0xffffffffu, p, o);
    if ((j & 31) == 0) red[j >> 5] = p;
    __syncthreads();
    if (j == 0) out[g] = red[0] + red[1] + red[2] + red[3] + b2[0];
}

// ---------------- launch ----------------
extern "C" void kernel_launch(void* const* d_in, const int* in_sizes, int n_in,
                              void* d_out, int out_size) {
    const float* x      = (const float*)d_in[0];
    const int*   ei     = (const int*)d_in[1];
    const int*   batch  = (const int*)d_in[2];
    const float* Ws     = (const float*)d_in[3];
    const float* bs     = (const float*)d_in[4];
    const float* gammas = (const float*)d_in[5];
    const float* betas  = (const float*)d_in[6];
    const float* W1     = (const float*)d_in[7];
    const float* b1     = (const float*)d_in[8];
    const float* W2     = (const float*)d_in[9];
    const float* b2     = (const float*)d_in[10];
    float* out = (float*)d_out;

    __half *A, *B, *wh;
    cudaGetSymbolAddress((void**)&A, g_bufA);
    cudaGetSymbolAddress((void**)&B, g_bufB);
    cudaGetSymbolAddress((void**)&wh, g_Wh16);
    cudaFuncSetAttribute(k_gemm16, cudaFuncAttributeMaxDynamicSharedMemorySize, MMASMEM);

    // One-time stream/event creation (outside capture — correctness call runs first).
    static cudaStream_t s2 = [] {
        cudaStream_t s; cudaStreamCreateWithFlags(&s, cudaStreamNonBlocking); return s;
    }();
    static cudaEvent_t evFork = [] {
        cudaEvent_t e; cudaEventCreateWithFlags(&e, cudaEventDisableTiming); return e;
    }();
    static cudaEvent_t evJoin = [] {
        cudaEvent_t e; cudaEventCreateWithFlags(&e, cudaEventDisableTiming); return e;
    }();

    const int NB_E = (NE + 255) / 256;   // 3125

    // ---- fork: branch B (CSR build) on s2, branch A (prep+gemm0) on main stream
    cudaEventRecord(evFork, 0);
    cudaStreamWaitEvent(s2, evFork, 0);

    k_count<<<NB_E, 256, 0, s2>>>(ei);                                     // 0
    k_prepw<<<3 * D * D / 128, 128>>>(Ws);                                 // 1
    k_convx<<<(NN * 32 + 255) / 256, 256>>>(x, A);                         // 2
    k_gemm16<<<NT2, 256, MMASMEM>>>(A, wh, B, 0);                          // 3 <- profiled
    k_nodepart<<<SCAN_B, 256, 0, s2>>>();                                  // 4
    k_scanpart<<<1, 512, 0, s2>>>();                                       // 5
    k_offsets<<<SCAN_B, 256, 0, s2>>>();                                   // 6
    k_fill<<<NB_E, 256, 0, s2>>>(ei);                                      // 7
    k_bounds<<<SCAN_B, 256, 0, s2>>>(batch);                               // 8

    // ---- join
    cudaEventRecord(evJoin, s2);
    cudaStreamWaitEvent(0, evJoin, 0);

    for (int l = 0; l < 3; l++) {
        if (l > 0)
            k_gemm16<<<NT2, 256, MMASMEM>>>(A, wh + l * D * D, B, 1);
        k_agg<<<2048, 256>>>(B, A, bs + l * D);
        k_stats<<<1, 128>>>(gammas + l * D, betas + l * D);
    }

    k_pool<<<NG, 256>>>(A);
    k_head<<<NG, 128>>>(W1, b1, W2, b2, out);
}

// round 12
// speedup vs baseline: 2.5256x; 1.0492x over previous
#include <cuda_runtime.h>
#include <cuda_fp16.h>
#include <cstdint>

#define NN 100000
#define NE 800000
#define NG 512
#define D  128
#define EPSV 1e-5f
#define NT2 391              // ceil(NN/256)
#define SCAN_B 391           // ceil(NN/256)
#define NSLOT 32
#define AGG_GRID 1184        // 148 SMs x 8 CTAs (one full wave @ 256 thr)

// ---------------- scratch (static device globals; no allocations) ----------------
__device__ __half g_bufA[NN * D];
__device__ __half g_bufB[NN * D];
__device__ float  g_dinv[NN];
__device__ float  g_selfw[NN];
__device__ int    g_cnt[NN];         // zero at load; re-zeroed by k_fill each call
__device__ int    g_fill[NN];
__device__ int    g_off[NN + 1];
__device__ int2   g_edge[NE];        // (src, __float_as_int(w))
__device__ int    g_part[SCAN_B];
__device__ int    g_pbase[SCAN_B];
__device__ int    g_ticket[4];       // per-layer work-stealing cursors
__device__ float  g_psum[NSLOT * D];
__device__ float  g_psq[NSLOT * D];
__device__ float  g_scale[D];
__device__ float  g_shift[D];
__device__ float  g_Z[NG * D];
__device__ int    g_start[NG];
__device__ int    g_end[NG];
__device__ __half g_Wh16[3 * D * D];   // W^T per layer, [n][k], fp16

__device__ __forceinline__ int clampN(int v) {
    return v < 0 ? 0 : (v >= NN ? NN - 1 : v);
}

__device__ __forceinline__ uint32_t smem_u32(const void* p) {
    uint32_t a;
    asm("{ .reg .u64 t; cvta.to.shared.u64 t, %1; cvt.u32.u64 %0, t; }" : "=r"(a) : "l"(p));
    return a;
}

// XOR swizzle for 256B rows
__device__ __forceinline__ uint32_t sw(uint32_t off) {
    return off ^ ((off >> 4) & 0x70);
}

__device__ __forceinline__ void ldm_x4(uint32_t* r, uint32_t addr) {
    asm volatile("ldmatrix.sync.aligned.m8n8.x4.shared.b16 {%0,%1,%2,%3}, [%4];"
                 : "=r"(r[0]), "=r"(r[1]), "=r"(r[2]), "=r"(r[3]) : "r"(addr));
}

__device__ __forceinline__ void mma_f16(float* c, const uint32_t* a, uint32_t b0, uint32_t b1) {
    asm volatile(
        "mma.sync.aligned.m16n8k16.row.col.f32.f16.f16.f32 "
        "{%0,%1,%2,%3}, {%4,%5,%6,%7}, {%8,%9}, {%0,%1,%2,%3};"
        : "+f"(c[0]), "+f"(c[1]), "+f"(c[2]), "+f"(c[3])
        : "r"(a[0]), "r"(a[1]), "r"(a[2]), "r"(a[3]), "r"(b0), "r"(b1));
}

// ---------------- graph preprocessing ----------------
__global__ void k_count(const int* __restrict__ ei) {
    int e = blockIdx.x * blockDim.x + threadIdx.x;
    if (e < NE) atomicAdd(&g_cnt[clampN(ei[NE + e])], 1);
}

// node-wise derived values + per-256-chunk partial sums (+ticket reset)
__global__ void k_nodepart() {
    __shared__ int s[256];
    int t = threadIdx.x;
    int i = blockIdx.x * 256 + t;
    int c = (i < NN) ? g_cnt[i] : 0;
    if (i < NN) {
        float deg = (float)c + 1.0f;
        g_dinv[i]  = rsqrtf(deg);
        g_selfw[i] = 1.0f / deg;
        g_fill[i]  = 0;
    }
    if (i < NG) { g_start[i] = 0; g_end[i] = 0; }
    if (i < NSLOT * D) { g_psum[i] = 0.f; g_psq[i] = 0.f; }
    if (i < 4) g_ticket[i] = 0;
    s[t] = c;
    __syncthreads();
    for (int o = 128; o; o >>= 1) { if (t < o) s[t] += s[t + o]; __syncthreads(); }
    if (t == 0) g_part[blockIdx.x] = s[0];
}

__global__ void k_scanpart() {
    __shared__ int s[512];
    int t = threadIdx.x;
    int v = (t < SCAN_B) ? g_part[t] : 0;
    s[t] = v; __syncthreads();
    for (int d = 1; d < 512; d <<= 1) {
        int x = (t >= d) ? s[t - d] : 0;
        __syncthreads();
        s[t] += x;
        __syncthreads();
    }
    if (t < SCAN_B) g_pbase[t] = s[t] - v;
    if (t == SCAN_B - 1) g_off[NN] = s[t];
}

__global__ void k_offsets() {
    __shared__ int s[256];
    int t = threadIdx.x;
    int i = blockIdx.x * 256 + t;
    int v = (i < NN) ? g_cnt[i] : 0;
    s[t] = v; __syncthreads();
    for (int d = 1; d < 256; d <<= 1) {
        int x = (t >= d) ? s[t - d] : 0;
        __syncthreads();
        s[t] += x;
        __syncthreads();
    }
    if (i < NN) g_off[i] = g_pbase[blockIdx.x] + s[t] - v;
}

__global__ void k_fill(const int* __restrict__ ei) {
    int e = blockIdx.x * blockDim.x + threadIdx.x;
    if (e < NN) g_cnt[e] = 0;          // reset for the NEXT call
    if (e >= NE) return;
    int s = clampN(ei[e]);
    int d = clampN(ei[NE + e]);
    int p = g_off[d] + atomicAdd(&g_fill[d], 1);
    g_edge[p] = make_int2(s, __float_as_int(g_dinv[s] * g_dinv[d]));
}

__global__ void k_bounds(const int* __restrict__ batch) {
    int i = blockIdx.x * blockDim.x + threadIdx.x;
    if (i >= NN) return;
    int b = batch[i];
    if (b < 0) b = 0; if (b >= NG) b = NG - 1;
    int bp = (i == 0) ? -1 : batch[i - 1];
    int bn = (i == NN - 1) ? -1 : batch[i + 1];
    if (i == 0      || bp != b) g_start[b] = i;
    if (i == NN - 1 || bn != b) g_end[b]   = i + 1;
}

// W^T fp16
__global__ void k_prepw(const float* __restrict__ Ws) {
    int idx = blockIdx.x * 128 + threadIdx.x;
    int l = idx >> 14, rem = idx & 16383;
    int n = rem >> 7, k = rem & 127;
    g_Wh16[idx] = __float2half_rn(Ws[l * 16384 + k * 128 + n]);
}

// x (fp32) -> fp16 buffer
__global__ void k_convx(const float* __restrict__ x, __half* __restrict__ o) {
    int i = blockIdx.x * blockDim.x + threadIdx.x;
    if (i >= NN * 32) return;
    float4 v = __ldg((const float4*)x + i);
    uint2 p;
    *(__half2*)&p.x = __floats2half2_rn(v.x, v.y);
    *(__half2*)&p.y = __floats2half2_rn(v.z, v.w);
    ((uint2*)o)[i] = p;
}

// ---------------- fp16 HMMA GEMM ----------------
#define MMASMEM 32768

__global__ __launch_bounds__(256) void k_gemm16(const __half* __restrict__ in,
                                                const __half* __restrict__ Wh,
                                                __half* __restrict__ out,
                                                int apply) {
    extern __shared__ char smc[];
    uint32_t sb = smem_u32(smc);
    int tid = threadIdx.x, wid = tid >> 5, lane = tid & 31;
    int row0 = blockIdx.x * 256;

    {
        int n = tid >> 1, hf = tid & 1;
        const uint4* src_h = (const uint4*)(Wh) + n * 16 + hf * 8;
        uint32_t base = n * 256 + hf * 128;
#pragma unroll
        for (int c = 0; c < 8; c++) {
            uint32_t o = sw(base + c * 16);
            *(uint4*)(smc + o) = __ldg(&src_h[c]);
        }
    }

    int groupID = lane >> 2, tig = lane & 3;
    int rb = row0 + wid * 32;
    uint32_t af[2][8][4];
    bool okr[2][2];
#pragma unroll
    for (int s = 0; s < 2; s++) {
        int r0 = rb + s * 16 + groupID;
        int r1 = r0 + 8;
        okr[s][0] = r0 < NN; okr[s][1] = r1 < NN;
        const __half2* hp0 = (const __half2*)(in + (size_t)r0 * D);
        const __half2* hp1 = (const __half2*)(in + (size_t)r1 * D);
#pragma unroll
        for (int k = 0; k < 8; k++) {
            __half2 z = __floats2half2_rn(0.f, 0.f);
            __half2 a0 = okr[s][0] ? __ldg(&hp0[tig + k * 8])     : z;
            __half2 a1 = okr[s][1] ? __ldg(&hp1[tig + k * 8])     : z;
            __half2 a2 = okr[s][0] ? __ldg(&hp0[tig + k * 8 + 4]) : z;
            __half2 a3 = okr[s][1] ? __ldg(&hp1[tig + k * 8 + 4]) : z;
            if (apply) {
                float2 s0 = ((const float2*)g_scale)[tig + k * 8];
                float2 h0 = ((const float2*)g_shift)[tig + k * 8];
                float2 s1 = ((const float2*)g_scale)[tig + k * 8 + 4];
                float2 h1 = ((const float2*)g_shift)[tig + k * 8 + 4];
                float2 f0 = __half22float2(a0), f1 = __half22float2(a1);
                float2 f2 = __half22float2(a2), f3 = __half22float2(a3);
                a0 = __floats2half2_rn(fmaxf(fmaf(f0.x, s0.x, h0.x), 0.f),
                                       fmaxf(fmaf(f0.y, s0.y, h0.y), 0.f));
                a1 = __floats2half2_rn(fmaxf(fmaf(f1.x, s0.x, h0.x), 0.f),
                                       fmaxf(fmaf(f1.y, s0.y, h0.y), 0.f));
                a2 = __floats2half2_rn(fmaxf(fmaf(f2.x, s1.x, h1.x), 0.f),
                                       fmaxf(fmaf(f2.y, s1.y, h1.y), 0.f));
                a3 = __floats2half2_rn(fmaxf(fmaf(f3.x, s1.x, h1.x), 0.f),
                                       fmaxf(fmaf(f3.y, s1.y, h1.y), 0.f));
            }
            af[s][k][0] = *(uint32_t*)&a0;
            af[s][k][1] = *(uint32_t*)&a1;
            af[s][k][2] = *(uint32_t*)&a2;
            af[s][k][3] = *(uint32_t*)&a3;
        }
    }
    __syncthreads();

    uint32_t b_base = ((lane & 7) + ((lane >> 4) << 3)) * 256 + (((lane >> 3) & 1) * 8) * 2;
    int col_t = tig * 2;

#pragma unroll 2
    for (int np = 0; np < 8; np++) {
        float e0[4] = {0,0,0,0}, o0[4] = {0,0,0,0};
        float e1[4] = {0,0,0,0}, o1[4] = {0,0,0,0};
#pragma unroll
        for (int k = 0; k < 8; k++) {
            uint32_t bh[4];
            uint32_t o = sw(b_base + np * 4096 + k * 32);
            ldm_x4(bh, sb + o);
            mma_f16(e0, af[0][k], bh[0], bh[1]);
            mma_f16(o0, af[0][k], bh[2], bh[3]);
            mma_f16(e1, af[1][k], bh[0], bh[1]);
            mma_f16(o1, af[1][k], bh[2], bh[3]);
        }
        int nb = np * 16;
#pragma unroll
        for (int s = 0; s < 2; s++) {
            float* ee = s ? e1 : e0; float* oo = s ? o1 : o0;
            int r0 = rb + s * 16 + groupID;
            int r1 = r0 + 8;
            if (okr[s][0]) {
                *(__half2*)(out + (size_t)r0 * D + nb + col_t)     = __floats2half2_rn(ee[0], ee[1]);
                *(__half2*)(out + (size_t)r0 * D + nb + 8 + col_t) = __floats2half2_rn(oo[0], oo[1]);
            }
            if (okr[s][1]) {
                *(__half2*)(out + (size_t)r1 * D + nb + col_t)     = __floats2half2_rn(ee[2], ee[3]);
                *(__half2*)(out + (size_t)r1 * D + nb + 8 + col_t) = __floats2half2_rn(oo[2], oo[3]);
            }
        }
    }
}

// ---------------- aggregation (gather, CSR, work-stealing) + bias + BN stats ----------------
__device__ __forceinline__ float4 h4_to_f4(uint2 raw) {
    __half2 a = *(__half2*)&raw.x;
    __half2 b = *(__half2*)&raw.y;
    float2 fa = __half22float2(a), fb = __half22float2(b);
    return make_float4(fa.x, fa.y, fb.x, fb.y);
}

__device__ __forceinline__ void acc4(float4& acc, float w, float4 v) {
    acc.x = fmaf(w, v.x, acc.x);
    acc.y = fmaf(w, v.y, acc.y);
    acc.z = fmaf(w, v.z, acc.z);
    acc.w = fmaf(w, v.w, acc.w);
}

__global__ __launch_bounds__(256) void k_agg(const __half* __restrict__ tmp,
                                             __half* __restrict__ outh,
                                             const float* __restrict__ bias,
                                             int layer) {
    __shared__ float bsum[D];
    __shared__ float bsq[D];
    int tid = threadIdx.x;
    if (tid < D) { bsum[tid] = 0.f; bsq[tid] = 0.f; }
    __syncthreads();

    int lane = tid & 31;
    const uint2* t2 = (const uint2*)tmp;
    float4 b4 = ((const float4*)bias)[lane];
    float ls0 = 0, ls1 = 0, ls2 = 0, ls3 = 0;
    float lq0 = 0, lq1 = 0, lq2 = 0, lq3 = 0;

    for (;;) {
        int base;
        if (lane == 0) base = atomicAdd(&g_ticket[layer], 4);
        base = __shfl_sync(0xffffffffu, base, 0);
        if (base >= NN) break;
        int rend = base + 4 < NN ? base + 4 : NN;
        for (int row = base; row < rend; row++) {
            float4 acc = make_float4(0.f, 0.f, 0.f, 0.f);
            int e0 = g_off[row], e1 = g_off[row + 1];
            int e = e0;
            for (; e + 4 <= e1; e += 4) {
                int2 p0 = __ldg(&g_edge[e]);
                int2 p1 = __ldg(&g_edge[e + 1]);
                int2 p2 = __ldg(&g_edge[e + 2]);
                int2 p3 = __ldg(&g_edge[e + 3]);
                float4 v0 = h4_to_f4(__ldg(&t2[p0.x * 32 + lane]));
                float4 v1 = h4_to_f4(__ldg(&t2[p1.x * 32 + lane]));
                float4 v2 = h4_to_f4(__ldg(&t2[p2.x * 32 + lane]));
                float4 v3 = h4_to_f4(__ldg(&t2[p3.x * 32 + lane]));
                acc4(acc, __int_as_float(p0.y), v0);
                acc4(acc, __int_as_float(p1.y), v1);
                acc4(acc, __int_as_float(p2.y), v2);
                acc4(acc, __int_as_float(p3.y), v3);
            }
            for (; e < e1; e++) {
                int2 pp = __ldg(&g_edge[e]);
                float4 v = h4_to_f4(__ldg(&t2[pp.x * 32 + lane]));
                acc4(acc, __int_as_float(pp.y), v);
            }
            float sw_ = g_selfw[row];
            float4 v = h4_to_f4(__ldg(&t2[row * 32 + lane]));
            acc.x = fmaf(sw_, v.x, acc.x) + b4.x;
            acc.y = fmaf(sw_, v.y, acc.y) + b4.y;
            acc.z = fmaf(sw_, v.z, acc.z) + b4.z;
            acc.w = fmaf(sw_, v.w, acc.w) + b4.w;
            uint2 packed;
            *(__half2*)&packed.x = __floats2half2_rn(acc.x, acc.y);
            *(__half2*)&packed.y = __floats2half2_rn(acc.z, acc.w);
            ((uint2*)outh)[row * 32 + lane] = packed;
            ls0 += acc.x; ls1 += acc.y; ls2 += acc.z; ls3 += acc.w;
            lq0 += acc.x * acc.x; lq1 += acc.y * acc.y;
            lq2 += acc.z * acc.z; lq3 += acc.w * acc.w;
        }
    }

    atomicAdd(&bsum[lane * 4 + 0], ls0); atomicAdd(&bsum[lane * 4 + 1], ls1);
    atomicAdd(&bsum[lane * 4 + 2], ls2); atomicAdd(&bsum[lane * 4 + 3], ls3);
    atomicAdd(&bsq[lane * 4 + 0], lq0);  atomicAdd(&bsq[lane * 4 + 1], lq1);
    atomicAdd(&bsq[lane * 4 + 2], lq2);  atomicAdd(&bsq[lane * 4 + 3], lq3);
    __syncthreads();
    if (tid < D) {
        int slot = (blockIdx.x & (NSLOT - 1)) * D + tid;
        atomicAdd(&g_psum[slot], bsum[tid]);
        atomicAdd(&g_psq[slot],  bsq[tid]);
    }
}

__global__ void k_stats(const float* __restrict__ gamma, const float* __restrict__ beta) {
    int f = threadIdx.x;
    if (f >= D) return;
    float s = 0.f, q = 0.f;
#pragma unroll
    for (int k = 0; k < NSLOT; k++) {
        s += g_psum[k * D + f];
        q += g_psq[k * D + f];
        g_psum[k * D + f] = 0.f;
        g_psq[k * D + f]  = 0.f;
    }
    float mu  = s / (float)NN;
    float var = q / (float)NN - mu * mu;
    float rstd = rsqrtf(var + EPSV);
    float sc = rstd * gamma[f];
    g_scale[f] = sc;
    g_shift[f] = beta[f] - mu * sc;
}

// ---------------- pooling + MLP head ----------------
__global__ __launch_bounds__(256) void k_pool(const __half* __restrict__ h) {
    __shared__ float partial[D];
    int g = blockIdx.x, t = threadIdx.x;
    int f = t & 127, hf = t >> 7;
    int a = g_start[g], b = g_end[g];
    int n = b - a;
    int mid = a + (n >> 1);
    int lo = hf ? mid : a;
    int hi = hf ? b : mid;
    float sc = g_scale[f], sh = g_shift[f];
    float s0 = 0.f, s1 = 0.f;
    int i = lo;
    for (; i + 2 <= hi; i += 2) {
        s0 += fmaxf(fmaf(__half2float(h[(i + 0) * D + f]), sc, sh), 0.f);
        s1 += fmaxf(fmaf(__half2float(h[(i + 1) * D + f]), sc, sh), 0.f);
    }
    for (; i < hi; i++) s0 += fmaxf(fmaf(__half2float(h[i * D + f]), sc, sh), 0.f);
    float s = s0 + s1;
    if (hf) partial[f] = s;
    __syncthreads();
    if (!hf) g_Z[g * D + f] = (s + partial[f]) / (float)(n > 0 ? n : 1);
}

__global__ void k_head(const float* __restrict__ W1, const float* __restrict__ b1,
                       const float* __restrict__ W2, const float* __restrict__ b2,
                       float* __restrict__ out) {
    __shared__ float zs[D];
    __shared__ float red[4];
    int g = blockIdx.x, j = threadIdx.x;
    zs[j] = g_Z[g * D + j];
    __syncthreads();
    float acc = b1[j];
#pragma unroll 8
    for (int k = 0; k < D; k++) acc = fmaf(zs[k], W1[k * D + j], acc);
    float hz = fmaxf(acc, 0.f);
    float p = hz * W2[j];
#pragma unroll
    for (int o = 16; o; o >>= 1) p += __shfl_down_sync(0xffffffffu, p, o);
    if ((j & 31) == 0) red[j >> 5] = p;
    __syncthreads();
    if (j == 0) out[g] = red[0] + red[1] + red[2] + red[3] + b2[0];
}

// ---------------- launch ----------------
extern "C" void kernel_launch(void* const* d_in, const int* in_sizes, int n_in,
                              void* d_out, int out_size) {
    const float* x      = (const float*)d_in[0];
    const int*   ei     = (const int*)d_in[1];
    const int*   batch  = (const int*)d_in[2];
    const float* Ws     = (const float*)d_in[3];
    const float* bs     = (const float*)d_in[4];
    const float* gammas = (const float*)d_in[5];
    const float* betas  = (const float*)d_in[6];
    const float* W1     = (const float*)d_in[7];
    const float* b1     = (const float*)d_in[8];
    const float* W2     = (const float*)d_in[9];
    const float* b2     = (const float*)d_in[10];
    float* out = (float*)d_out;

    __half *A, *B, *wh;
    cudaGetSymbolAddress((void**)&A, g_bufA);
    cudaGetSymbolAddress((void**)&B, g_bufB);
    cudaGetSymbolAddress((void**)&wh, g_Wh16);
    cudaFuncSetAttribute(k_gemm16, cudaFuncAttributeMaxDynamicSharedMemorySize, MMASMEM);

    static cudaStream_t s2 = [] {
        cudaStream_t s; cudaStreamCreateWithFlags(&s, cudaStreamNonBlocking); return s;
    }();
    static cudaEvent_t evFork = [] {
        cudaEvent_t e; cudaEventCreateWithFlags(&e, cudaEventDisableTiming); return e;
    }();
    static cudaEvent_t evJoin = [] {
        cudaEvent_t e; cudaEventCreateWithFlags(&e, cudaEventDisableTiming); return e;
    }();

    const int NB_E = (NE + 255) / 256;   // 3125

    cudaEventRecord(evFork, 0);
    cudaStreamWaitEvent(s2, evFork, 0);

    k_count<<<NB_E, 256, 0, s2>>>(ei);
    k_prepw<<<3 * D * D / 128, 128>>>(Ws);
    k_convx<<<(NN * 32 + 255) / 256, 256>>>(x, A);
    k_gemm16<<<NT2, 256, MMASMEM>>>(A, wh, B, 0);       // <- profiled (idx 3)
    k_nodepart<<<SCAN_B, 256, 0, s2>>>();
    k_scanpart<<<1, 512, 0, s2>>>();
    k_offsets<<<SCAN_B, 256, 0, s2>>>();
    k_fill<<<NB_E, 256, 0, s2>>>(ei);
    k_bounds<<<SCAN_B, 256, 0, s2>>>(batch);

    cudaEventRecord(evJoin, s2);
    cudaStreamWaitEvent(0, evJoin, 0);

    for (int l = 0; l < 3; l++) {
        if (l > 0)
            k_gemm16<<<NT2, 256, MMASMEM>>>(A, wh + l * D * D, B, 1);
        k_agg<<<AGG_GRID, 256>>>(B, A, bs + l * D, l);
        k_stats<<<1, 128>>>(gammas + l * D, betas + l * D);
    }

    k_pool<<<NG, 256>>>(A);
    k_head<<<NG, 128>>>(W1, b1, W2, b2, out);
}

// round 13
// speedup vs baseline: 2.7153x; 1.0751x over previous
#include <cuda_runtime.h>
#include <cuda_fp16.h>
#include <cstdint>

#define NN 100000
#define NE 800000
#define NG 512
#define D  128
#define EPSV 1e-5f
#define NT2 391              // ceil(NN/256)
#define SCAN_B 391           // ceil(NN/256)
#define NSLOT 32
#define AGG_GRID 1184        // 148 SMs x 8 CTAs (one full wave @ 256 thr)

// ---------------- scratch (static device globals; no allocations) ----------------
__device__ __half g_bufA[NN * D];
__device__ __half g_bufB[NN * D];
__device__ float  g_dinv[NN];
__device__ float  g_selfw[NN];
__device__ int    g_cnt[NN];         // zero at load; re-zeroed by k_fill each call
__device__ int    g_fill[NN];
__device__ int    g_off[NN + 1];
__device__ int2   g_edge[NE];        // (src, __float_as_int(w))
__device__ int    g_part[SCAN_B];
__device__ int    g_pbase[SCAN_B];
__device__ int    g_ticket[4];       // per-layer work-stealing cursors
__device__ float  g_psum3[3 * NSLOT * D];   // per-layer BN partial sums
__device__ float  g_psq3[3 * NSLOT * D];
__device__ float  g_Z[NG * D];
__device__ int    g_start[NG];
__device__ int    g_end[NG];
__device__ __half g_Wh16[3 * D * D];   // W^T per layer, [n][k], fp16

__device__ __forceinline__ int clampN(int v) {
    return v < 0 ? 0 : (v >= NN ? NN - 1 : v);
}

__device__ __forceinline__ uint32_t smem_u32(const void* p) {
    uint32_t a;
    asm("{ .reg .u64 t; cvta.to.shared.u64 t, %1; cvt.u32.u64 %0, t; }" : "=r"(a) : "l"(p));
    return a;
}

// XOR swizzle for 256B rows
__device__ __forceinline__ uint32_t sw(uint32_t off) {
    return off ^ ((off >> 4) & 0x70);
}

__device__ __forceinline__ void ldm_x4(uint32_t* r, uint32_t addr) {
    asm volatile("ldmatrix.sync.aligned.m8n8.x4.shared.b16 {%0,%1,%2,%3}, [%4];"
                 : "=r"(r[0]), "=r"(r[1]), "=r"(r[2]), "=r"(r[3]) : "r"(addr));
}

__device__ __forceinline__ void mma_f16(float* c, const uint32_t* a, uint32_t b0, uint32_t b1) {
    asm volatile(
        "mma.sync.aligned.m16n8k16.row.col.f32.f16.f16.f32 "
        "{%0,%1,%2,%3}, {%4,%5,%6,%7}, {%8,%9}, {%0,%1,%2,%3};"
        : "+f"(c[0]), "+f"(c[1]), "+f"(c[2]), "+f"(c[3])
        : "r"(a[0]), "r"(a[1]), "r"(a[2]), "r"(a[3]), "r"(b0), "r"(b1));
}

// typed pair loader -> fp32
__device__ __forceinline__ float2 load_pair_f(const float* base, int idx) {
    return __ldg((const float2*)base + idx);
}
__device__ __forceinline__ float2 load_pair_f(const __half* base, int idx) {
    return __half22float2(__ldg((const __half2*)base + idx));
}

// ---------------- graph preprocessing ----------------
__global__ void k_count(const int* __restrict__ ei) {
    int e = blockIdx.x * blockDim.x + threadIdx.x;
    if (e < NE) atomicAdd(&g_cnt[clampN(ei[NE + e])], 1);
}

// node-wise derived values + per-256-chunk partial sums (+ticket/psum reset)
__global__ void k_nodepart() {
    __shared__ int s[256];
    int t = threadIdx.x;
    int i = blockIdx.x * 256 + t;
    int c = (i < NN) ? g_cnt[i] : 0;
    if (i < NN) {
        float deg = (float)c + 1.0f;
        g_dinv[i]  = rsqrtf(deg);
        g_selfw[i] = 1.0f / deg;
        g_fill[i]  = 0;
    }
    if (i < NG) { g_start[i] = 0; g_end[i] = 0; }
    if (i < 3 * NSLOT * D) { g_psum3[i] = 0.f; g_psq3[i] = 0.f; }
    if (i < 4) g_ticket[i] = 0;
    s[t] = c;
    __syncthreads();
    for (int o = 128; o; o >>= 1) { if (t < o) s[t] += s[t + o]; __syncthreads(); }
    if (t == 0) g_part[blockIdx.x] = s[0];
}

__global__ void k_scanpart() {
    __shared__ int s[512];
    int t = threadIdx.x;
    int v = (t < SCAN_B) ? g_part[t] : 0;
    s[t] = v; __syncthreads();
    for (int d = 1; d < 512; d <<= 1) {
        int x = (t >= d) ? s[t - d] : 0;
        __syncthreads();
        s[t] += x;
        __syncthreads();
    }
    if (t < SCAN_B) g_pbase[t] = s[t] - v;
    if (t == SCAN_B - 1) g_off[NN] = s[t];
}

__global__ void k_offsets() {
    __shared__ int s[256];
    int t = threadIdx.x;
    int i = blockIdx.x * 256 + t;
    int v = (i < NN) ? g_cnt[i] : 0;
    s[t] = v; __syncthreads();
    for (int d = 1; d < 256; d <<= 1) {
        int x = (t >= d) ? s[t - d] : 0;
        __syncthreads();
        s[t] += x;
        __syncthreads();
    }
    if (i < NN) g_off[i] = g_pbase[blockIdx.x] + s[t] - v;
}

__global__ void k_fill(const int* __restrict__ ei) {
    int e = blockIdx.x * blockDim.x + threadIdx.x;
    if (e < NN) g_cnt[e] = 0;          // reset for the NEXT call
    if (e >= NE) return;
    int s = clampN(ei[e]);
    int d = clampN(ei[NE + e]);
    int p = g_off[d] + atomicAdd(&g_fill[d], 1);
    g_edge[p] = make_int2(s, __float_as_int(g_dinv[s] * g_dinv[d]));
}

__global__ void k_bounds(const int* __restrict__ batch) {
    int i = blockIdx.x * blockDim.x + threadIdx.x;
    if (i >= NN) return;
    int b = batch[i];
    if (b < 0) b = 0; if (b >= NG) b = NG - 1;
    int bp = (i == 0) ? -1 : batch[i - 1];
    int bn = (i == NN - 1) ? -1 : batch[i + 1];
    if (i == 0      || bp != b) g_start[b] = i;
    if (i == NN - 1 || bn != b) g_end[b]   = i + 1;
}

// W^T fp16
__global__ void k_prepw(const float* __restrict__ Ws) {
    int idx = blockIdx.x * 128 + threadIdx.x;
    int l = idx >> 14, rem = idx & 16383;
    int n = rem >> 7, k = rem & 127;
    g_Wh16[idx] = __float2half_rn(Ws[l * 16384 + k * 128 + n]);
}

// compute BN affine for layer l from slotted partials (thread f < 128)
__device__ __forceinline__ void bn_affine(int layer, int f,
                                          const float* __restrict__ gamma,
                                          const float* __restrict__ beta,
                                          float& sc_out, float& sh_out) {
    const float* ps = g_psum3 + layer * NSLOT * D;
    const float* pq = g_psq3  + layer * NSLOT * D;
    float s = 0.f, q = 0.f;
#pragma unroll
    for (int k = 0; k < NSLOT; k++) {
        s += ps[k * D + f];
        q += pq[k * D + f];
    }
    float mu  = s / (float)NN;
    float var = q / (float)NN - mu * mu;
    float rstd = rsqrtf(var + EPSV);
    float sc = rstd * gamma[f];
    sc_out = sc;
    sh_out = beta[f] - mu * sc;
}

// ---------------- fp16 HMMA GEMM (in-kernel BN affine for apply path) ----------------
#define S_SC 32768
#define S_SH (32768 + 512)
#define MMASMEM (32768 + 1024)

template <typename T>
__global__ __launch_bounds__(256) void k_gemm16(const T* __restrict__ in,
                                                const __half* __restrict__ Wh,
                                                __half* __restrict__ out,
                                                int apply, int prev_layer,
                                                const float* __restrict__ gamma,
                                                const float* __restrict__ beta) {
    extern __shared__ char smc[];
    uint32_t sb = smem_u32(smc);
    float* smsc = (float*)(smc + S_SC);
    float* smsh = (float*)(smc + S_SH);
    int tid = threadIdx.x, wid = tid >> 5, lane = tid & 31;
    int row0 = blockIdx.x * 256;

    // ---- in-kernel BN affine (layer prev_layer) into smem
    if (apply && tid < D) {
        float sc, sh;
        bn_affine(prev_layer, tid, gamma, beta, sc, sh);
        smsc[tid] = sc;
        smsh[tid] = sh;
    }

    // ---- stage W^T
    {
        int n = tid >> 1, hf = tid & 1;
        const uint4* src_h = (const uint4*)(Wh) + n * 16 + hf * 8;
        uint32_t base = n * 256 + hf * 128;
#pragma unroll
        for (int c = 0; c < 8; c++) {
            uint32_t o = sw(base + c * 16);
            *(uint4*)(smc + o) = __ldg(&src_h[c]);
        }
    }
    __syncthreads();   // W + affine staged

    // ---- A fragments: 2 sets of 16 rows, direct global loads (+BN/ReLU)
    int groupID = lane >> 2, tig = lane & 3;
    int rb = row0 + wid * 32;
    uint32_t af[2][8][4];
    bool okr[2][2];
#pragma unroll
    for (int s = 0; s < 2; s++) {
        int r0 = rb + s * 16 + groupID;
        int r1 = r0 + 8;
        okr[s][0] = r0 < NN; okr[s][1] = r1 < NN;
        const T* bp0 = in + (size_t)r0 * D;
        const T* bp1 = in + (size_t)r1 * D;
#pragma unroll
        for (int k = 0; k < 8; k++) {
            float2 f0 = okr[s][0] ? load_pair_f(bp0, tig + k * 8)     : make_float2(0.f, 0.f);
            float2 f1 = okr[s][1] ? load_pair_f(bp1, tig + k * 8)     : make_float2(0.f, 0.f);
            float2 f2 = okr[s][0] ? load_pair_f(bp0, tig + k * 8 + 4) : make_float2(0.f, 0.f);
            float2 f3 = okr[s][1] ? load_pair_f(bp1, tig + k * 8 + 4) : make_float2(0.f, 0.f);
            if (apply) {
                float2 s0 = ((const float2*)smsc)[tig + k * 8];
                float2 h0 = ((const float2*)smsh)[tig + k * 8];
                float2 s1 = ((const float2*)smsc)[tig + k * 8 + 4];
                float2 h1 = ((const float2*)smsh)[tig + k * 8 + 4];
                f0.x = fmaxf(fmaf(f0.x, s0.x, h0.x), 0.f);
                f0.y = fmaxf(fmaf(f0.y, s0.y, h0.y), 0.f);
                f1.x = fmaxf(fmaf(f1.x, s0.x, h0.x), 0.f);
                f1.y = fmaxf(fmaf(f1.y, s0.y, h0.y), 0.f);
                f2.x = fmaxf(fmaf(f2.x, s1.x, h1.x), 0.f);
                f2.y = fmaxf(fmaf(f2.y, s1.y, h1.y), 0.f);
                f3.x = fmaxf(fmaf(f3.x, s1.x, h1.x), 0.f);
                f3.y = fmaxf(fmaf(f3.y, s1.y, h1.y), 0.f);
            }
            __half2 a0 = __floats2half2_rn(f0.x, f0.y);
            __half2 a1 = __floats2half2_rn(f1.x, f1.y);
            __half2 a2 = __floats2half2_rn(f2.x, f2.y);
            __half2 a3 = __floats2half2_rn(f3.x, f3.y);
            af[s][k][0] = *(uint32_t*)&a0;
            af[s][k][1] = *(uint32_t*)&a1;
            af[s][k][2] = *(uint32_t*)&a2;
            af[s][k][3] = *(uint32_t*)&a3;
        }
    }

    uint32_t b_base = ((lane & 7) + ((lane >> 4) << 3)) * 256 + (((lane >> 3) & 1) * 8) * 2;
    int col_t = tig * 2;

#pragma unroll 2
    for (int np = 0; np < 8; np++) {
        float e0[4] = {0,0,0,0}, o0[4] = {0,0,0,0};
        float e1[4] = {0,0,0,0}, o1[4] = {0,0,0,0};
#pragma unroll
        for (int k = 0; k < 8; k++) {
            uint32_t bh[4];
            uint32_t o = sw(b_base + np * 4096 + k * 32);
            ldm_x4(bh, sb + o);
            mma_f16(e0, af[0][k], bh[0], bh[1]);
            mma_f16(o0, af[0][k], bh[2], bh[3]);
            mma_f16(e1, af[1][k], bh[0], bh[1]);
            mma_f16(o1, af[1][k], bh[2], bh[3]);
        }
        int nb = np * 16;
#pragma unroll
        for (int s = 0; s < 2; s++) {
            float* ee = s ? e1 : e0; float* oo = s ? o1 : o0;
            int r0 = rb + s * 16 + groupID;
            int r1 = r0 + 8;
            if (okr[s][0]) {
                *(__half2*)(out + (size_t)r0 * D + nb + col_t)     = __floats2half2_rn(ee[0], ee[1]);
                *(__half2*)(out + (size_t)r0 * D + nb + 8 + col_t) = __floats2half2_rn(oo[0], oo[1]);
            }
            if (okr[s][1]) {
                *(__half2*)(out + (size_t)r1 * D + nb + col_t)     = __floats2half2_rn(ee[2], ee[3]);
                *(__half2*)(out + (size_t)r1 * D + nb + 8 + col_t) = __floats2half2_rn(oo[2], oo[3]);
            }
        }
    }
}

// ---------------- aggregation (gather, CSR, work-stealing) + bias + BN stats ----------------
__device__ __forceinline__ float4 h4_to_f4(uint2 raw) {
    __half2 a = *(__half2*)&raw.x;
    __half2 b = *(__half2*)&raw.y;
    float2 fa = __half22float2(a), fb = __half22float2(b);
    return make_float4(fa.x, fa.y, fb.x, fb.y);
}

__device__ __forceinline__ void acc4(float4& acc, float w, float4 v) {
    acc.x = fmaf(w, v.x, acc.x);
    acc.y = fmaf(w, v.y, acc.y);
    acc.z = fmaf(w, v.z, acc.z);
    acc.w = fmaf(w, v.w, acc.w);
}

__global__ __launch_bounds__(256) void k_agg(const __half* __restrict__ tmp,
                                             __half* __restrict__ outh,
                                             const float* __restrict__ bias,
                                             int layer) {
    __shared__ float bsum[D];
    __shared__ float bsq[D];
    int tid = threadIdx.x;
    if (tid < D) { bsum[tid] = 0.f; bsq[tid] = 0.f; }
    __syncthreads();

    int lane = tid & 31;
    const uint2* t2 = (const uint2*)tmp;
    float4 b4 = ((const float4*)bias)[lane];
    float ls0 = 0, ls1 = 0, ls2 = 0, ls3 = 0;
    float lq0 = 0, lq1 = 0, lq2 = 0, lq3 = 0;

    for (;;) {
        int base;
        if (lane == 0) base = atomicAdd(&g_ticket[layer], 4);
        base = __shfl_sync(0xffffffffu, base, 0);
        if (base >= NN) break;
        int rend = base + 4 < NN ? base + 4 : NN;
        for (int row = base; row < rend; row++) {
            float4 acc = make_float4(0.f, 0.f, 0.f, 0.f);
            int e0 = g_off[row], e1 = g_off[row + 1];
            int e = e0;
            for (; e + 4 <= e1; e += 4) {
                int2 p0 = __ldg(&g_edge[e]);
                int2 p1 = __ldg(&g_edge[e + 1]);
                int2 p2 = __ldg(&g_edge[e + 2]);
                int2 p3 = __ldg(&g_edge[e + 3]);
                float4 v0 = h4_to_f4(__ldg(&t2[p0.x * 32 + lane]));
                float4 v1 = h4_to_f4(__ldg(&t2[p1.x * 32 + lane]));
                float4 v2 = h4_to_f4(__ldg(&t2[p2.x * 32 + lane]));
                float4 v3 = h4_to_f4(__ldg(&t2[p3.x * 32 + lane]));
                acc4(acc, __int_as_float(p0.y), v0);
                acc4(acc, __int_as_float(p1.y), v1);
                acc4(acc, __int_as_float(p2.y), v2);
                acc4(acc, __int_as_float(p3.y), v3);
            }
            for (; e < e1; e++) {
                int2 pp = __ldg(&g_edge[e]);
                float4 v = h4_to_f4(__ldg(&t2[pp.x * 32 + lane]));
                acc4(acc, __int_as_float(pp.y), v);
            }
            float sw_ = g_selfw[row];
            float4 v = h4_to_f4(__ldg(&t2[row * 32 + lane]));
            acc.x = fmaf(sw_, v.x, acc.x) + b4.x;
            acc.y = fmaf(sw_, v.y, acc.y) + b4.y;
            acc.z = fmaf(sw_, v.z, acc.z) + b4.z;
            acc.w = fmaf(sw_, v.w, acc.w) + b4.w;
            uint2 packed;
            *(__half2*)&packed.x = __floats2half2_rn(acc.x, acc.y);
            *(__half2*)&packed.y = __floats2half2_rn(acc.z, acc.w);
            ((uint2*)outh)[row * 32 + lane] = packed;
            ls0 += acc.x; ls1 += acc.y; ls2 += acc.z; ls3 += acc.w;
            lq0 += acc.x * acc.x; lq1 += acc.y * acc.y;
            lq2 += acc.z * acc.z; lq3 += acc.w * acc.w;
        }
    }

    atomicAdd(&bsum[lane * 4 + 0], ls0); atomicAdd(&bsum[lane * 4 + 1], ls1);
    atomicAdd(&bsum[lane * 4 + 2], ls2); atomicAdd(&bsum[lane * 4 + 3], ls3);
    atomicAdd(&bsq[lane * 4 + 0], lq0);  atomicAdd(&bsq[lane * 4 + 1], lq1);
    atomicAdd(&bsq[lane * 4 + 2], lq2);  atomicAdd(&bsq[lane * 4 + 3], lq3);
    __syncthreads();
    if (tid < D) {
        int slot = (layer * NSLOT + (blockIdx.x & (NSLOT - 1))) * D + tid;
        atomicAdd(&g_psum3[slot], bsum[tid]);
        atomicAdd(&g_psq3[slot],  bsq[tid]);
    }
}

// ---------------- pooling (in-kernel BN affine of layer 2) + MLP head ----------------
__global__ __launch_bounds__(256) void k_pool(const __half* __restrict__ h,
                                              const float* __restrict__ gamma,
                                              const float* __restrict__ beta) {
    __shared__ float partial[D];
    __shared__ float smsc[D];
    __shared__ float smsh[D];
    int g = blockIdx.x, t = threadIdx.x;
    int f = t & 127, hf = t >> 7;
    if (t < D) {
        float sc, sh;
        bn_affine(2, t, gamma, beta, sc, sh);
        smsc[t] = sc;
        smsh[t] = sh;
    }
    __syncthreads();
    int a = g_start[g], b = g_end[g];
    int n = b - a;
    int mid = a + (n >> 1);
    int lo = hf ? mid : a;
    int hi = hf ? b : mid;
    float sc = smsc[f], sh = smsh[f];
    float s0 = 0.f, s1 = 0.f;
    int i = lo;
    for (; i + 2 <= hi; i += 2) {
        s0 += fmaxf(fmaf(__half2float(h[(i + 0) * D + f]), sc, sh), 0.f);
        s1 += fmaxf(fmaf(__half2float(h[(i + 1) * D + f]), sc, sh), 0.f);
    }
    for (; i < hi; i++) s0 += fmaxf(fmaf(__half2float(h[i * D + f]), sc, sh), 0.f);
    float s = s0 + s1;
    if (hf) partial[f] = s;
    __syncthreads();
    if (!hf) g_Z[g * D + f] = (s + partial[f]) / (float)(n > 0 ? n : 1);
}

__global__ void k_head(const float* __restrict__ W1, const float* __restrict__ b1,
                       const float* __restrict__ W2, const float* __restrict__ b2,
                       float* __restrict__ out) {
    __shared__ float zs[D];
    __shared__ float red[4];
    int g = blockIdx.x, j = threadIdx.x;
    zs[j] = g_Z[g * D + j];
    __syncthreads();
    float acc = b1[j];
#pragma unroll 8
    for (int k = 0; k < D; k++) acc = fmaf(zs[k], W1[k * D + j], acc);
    float hz = fmaxf(acc, 0.f);
    float p = hz * W2[j];
#pragma unroll
    for (int o = 16; o; o >>= 1) p += __shfl_down_sync(0xffffffffu, p, o);
    if ((j & 31) == 0) red[j >> 5] = p;
    __syncthreads();
    if (j == 0) out[g] = red[0] + red[1] + red[2] + red[3] + b2[0];
}

// ---------------- launch ----------------
extern "C" void kernel_launch(void* const* d_in, const int* in_sizes, int n_in,
                              void* d_out, int out_size) {
    const float* x      = (const float*)d_in[0];
    const int*   ei     = (const int*)d_in[1];
    const int*   batch  = (const int*)d_in[2];
    const float* Ws     = (const float*)d_in[3];
    const float* bs     = (const float*)d_in[4];
    const float* gammas = (const float*)d_in[5];
    const float* betas  = (const float*)d_in[6];
    const float* W1     = (const float*)d_in[7];
    const float* b1     = (const float*)d_in[8];
    const float* W2     = (const float*)d_in[9];
    const float* b2     = (const float*)d_in[10];
    float* out = (float*)d_out;

    __half *A, *B, *wh;
    cudaGetSymbolAddress((void**)&A, g_bufA);
    cudaGetSymbolAddress((void**)&B, g_bufB);
    cudaGetSymbolAddress((void**)&wh, g_Wh16);
    cudaFuncSetAttribute(k_gemm16<float>,  cudaFuncAttributeMaxDynamicSharedMemorySize, MMASMEM);
    cudaFuncSetAttribute(k_gemm16<__half>, cudaFuncAttributeMaxDynamicSharedMemorySize, MMASMEM);

    static cudaStream_t s2 = [] {
        cudaStream_t s; cudaStreamCreateWithFlags(&s, cudaStreamNonBlocking); return s;
    }();
    static cudaEvent_t evFork = [] {
        cudaEvent_t e; cudaEventCreateWithFlags(&e, cudaEventDisableTiming); return e;
    }();
    static cudaEvent_t evJoin = [] {
        cudaEvent_t e; cudaEventCreateWithFlags(&e, cudaEventDisableTiming); return e;
    }();

    const int NB_E = (NE + 255) / 256;   // 3125

    cudaEventRecord(evFork, 0);
    cudaStreamWaitEvent(s2, evFork, 0);

    k_count<<<NB_E, 256, 0, s2>>>(ei);                                     // 0
    k_prepw<<<3 * D * D / 128, 128>>>(Ws);                                 // 1
    k_nodepart<<<SCAN_B, 256, 0, s2>>>();                                  // 2
    k_gemm16<float><<<NT2, 256, MMASMEM>>>(x, wh, B, 0, 0,
                                           gammas, betas);                 // 3 <- profiled
    k_scanpart<<<1, 512, 0, s2>>>();                                       // 4
    k_offsets<<<SCAN_B, 256, 0, s2>>>();                                   // 5
    k_fill<<<NB_E, 256, 0, s2>>>(ei);                                      // 6
    k_bounds<<<SCAN_B, 256, 0, s2>>>(batch);                               // 7

    cudaEventRecord(evJoin, s2);
    cudaStreamWaitEvent(0, evJoin, 0);

    for (int l = 0; l < 3; l++) {
        if (l > 0)
            k_gemm16<__half><<<NT2, 256, MMASMEM>>>(A, wh + l * D * D, B, 1, l - 1,
                                                    gammas + (l - 1) * D,
                                                    betas + (l - 1) * D);
        k_agg<<<AGG_GRID, 256>>>(B, A, bs + l * D, l);
    }

    k_pool<<<NG, 256>>>(A, gammas + 2 * D, betas + 2 * D);
    k_head<<<NG, 128>>>(W1, b1, W2, b2, out);
}